// round 11
// baseline (speedup 1.0000x reference)
#include <cuda_runtime.h>
#include <cuda_bf16.h>
#include <cstdint>

// ---------------------------------------------------------------------------
// Problem constants (B=2, S=2048, H=1024, NH=16, NKV=8, D=128)
// ---------------------------------------------------------------------------
constexpr int B_   = 2;
constexpr int S_   = 2048;
constexpr int H_   = 1024;
constexpr int NH_  = 16;
constexpr int NKV_ = 8;
constexpr int D_   = 128;
constexpr int TOK  = B_ * S_;            // 4096 tokens

// Scratch (device globals; no allocation allowed)
__device__ float g_q [TOK * NH_  * D_];
__device__ float g_k [TOK * NKV_ * D_];
__device__ float g_v [TOK * NKV_ * D_];
__device__ float g_ao[TOK * NH_  * D_];
// bf16 hi/lo split attention operands
__device__ __nv_bfloat16 g_qh[TOK * NH_  * D_], g_ql[TOK * NH_  * D_];
__device__ __nv_bfloat16 g_kh[TOK * NKV_ * D_], g_kl[TOK * NKV_ * D_];
__device__ __nv_bfloat16 g_vh[TOK * NKV_ * D_], g_vl[TOK * NKV_ * D_];
// per-row quantization scales {inv = 127/rowmax, s = rowmax/127}
__device__ float2 g_sc_h [TOK];          // hidden rows
__device__ float2 g_sc_wq[NH_  * D_];
__device__ float2 g_sc_wk[NKV_ * D_];
__device__ float2 g_sc_wv[NKV_ * D_];
__device__ float2 g_sc_wo[H_];
__device__ float2 g_sc_ao[TOK];

#define DEV_INLINE __device__ __forceinline__

// ---------------------------------------------------------------------------
// helpers
// ---------------------------------------------------------------------------
DEV_INLINE uint32_t cvt_bf16x2(float hi_elem, float lo_elem) {
    uint32_t r;
    asm("cvt.rn.bf16x2.f32 %0, %1, %2;" : "=r"(r) : "f"(hi_elem), "f"(lo_elem));
    return r;
}
DEV_INLINE void split_pair(float f0, float f1, uint32_t& hiw, uint32_t& low) {
    hiw = cvt_bf16x2(f1, f0);
    float h0 = __uint_as_float(hiw << 16);
    float h1 = __uint_as_float(hiw & 0xFFFF0000u);
    low = cvt_bf16x2(f1 - h1, f0 - h0);
}
DEV_INLINE void ldsm_x4(uint32_t* r, uint32_t addr) {
    asm volatile("ldmatrix.sync.aligned.m8n8.x4.shared.b16 {%0,%1,%2,%3}, [%4];"
                 : "=r"(r[0]), "=r"(r[1]), "=r"(r[2]), "=r"(r[3]) : "r"(addr));
}
DEV_INLINE void ldsm_x4_trans(uint32_t* r, uint32_t addr) {
    asm volatile("ldmatrix.sync.aligned.m8n8.x4.trans.shared.b16 {%0,%1,%2,%3}, [%4];"
                 : "=r"(r[0]), "=r"(r[1]), "=r"(r[2]), "=r"(r[3]) : "r"(addr));
}
DEV_INLINE void mma_bf16(float* c, const uint32_t* a, const uint32_t* b) {
    asm volatile(
        "mma.sync.aligned.m16n8k16.row.col.f32.bf16.bf16.f32 "
        "{%0,%1,%2,%3}, {%4,%5,%6,%7}, {%8,%9}, {%0,%1,%2,%3};"
        : "+f"(c[0]), "+f"(c[1]), "+f"(c[2]), "+f"(c[3])
        : "r"(a[0]), "r"(a[1]), "r"(a[2]), "r"(a[3]), "r"(b[0]), "r"(b[1]));
}
// int8 tensor-core mma, k=32 (2x MAC rate vs bf16 k16)
DEV_INLINE void mma_s8(int* c, const uint32_t* a, const uint32_t* b) {
    asm volatile(
        "mma.sync.aligned.m16n8k32.row.col.s32.s8.s8.s32 "
        "{%0,%1,%2,%3}, {%4,%5,%6,%7}, {%8,%9}, {%0,%1,%2,%3};"
        : "+r"(c[0]), "+r"(c[1]), "+r"(c[2]), "+r"(c[3])
        : "r"(a[0]), "r"(a[1]), "r"(a[2]), "r"(a[3]), "r"(b[0]), "r"(b[1]));
}
DEV_INLINE uint32_t smem_u32(const void* p) {
    uint32_t a;
    asm("{ .reg .u64 t; cvta.to.shared.u64 t, %1; cvt.u32.u64 %0, t; }"
        : "=r"(a) : "l"(p));
    return a;
}
DEV_INLINE void cp16(uint32_t dst, const void* src) {
    asm volatile("cp.async.cg.shared.global [%0], [%1], 16;"
                 :: "r"(dst), "l"(src) : "memory");
}
DEV_INLINE void cp_commit() { asm volatile("cp.async.commit_group;" ::: "memory"); }
DEV_INLINE void cp_wait1()  { asm volatile("cp.async.wait_group 1;" ::: "memory"); }
DEV_INLINE void cp_wait0()  { asm volatile("cp.async.wait_group 0;" ::: "memory"); }

// ---------------------------------------------------------------------------
// Row-max pre-pass: one warp per row, writes {127/max, max/127}
// ---------------------------------------------------------------------------
__global__ void __launch_bounds__(256)
rowmax_kernel(const float* __restrict__ x, float2* __restrict__ s, int K)
{
    const int row = blockIdx.x * 8 + (threadIdx.x >> 5);
    const int l   = threadIdx.x & 31;
    const float* p = x + (size_t)row * K;
    float m = 0.f;
    for (int i = l * 4; i < K; i += 128) {
        const float4 v = *reinterpret_cast<const float4*>(p + i);
        m = fmaxf(m, fmaxf(fmaxf(fabsf(v.x), fabsf(v.y)),
                           fmaxf(fabsf(v.z), fabsf(v.w))));
    }
#pragma unroll
    for (int off = 16; off >= 1; off >>= 1) m = fmaxf(m, __shfl_xor_sync(0xffffffffu, m, off));
    m = fmaxf(m, 1e-20f);
    if (l == 0) s[row] = make_float2(127.0f / m, m / 127.0f);
}

// ---------------------------------------------------------------------------
// int8 dual-limb quantization helpers
// ---------------------------------------------------------------------------
DEV_INLINE uint32_t pack4(int a, int b, int c, int d) {
    return (uint32_t)(a & 255) | ((uint32_t)(b & 255) << 8) |
           ((uint32_t)(c & 255) << 16) | ((uint32_t)d << 24);
}
DEV_INLINE void q4(float4 v, float inv, uint32_t& hw, uint32_t& lw) {
    const float y0 = v.x * inv, y1 = v.y * inv, y2 = v.z * inv, y3 = v.w * inv;
    const int h0 = __float2int_rn(y0), h1 = __float2int_rn(y1);
    const int h2 = __float2int_rn(y2), h3 = __float2int_rn(y3);
    const int l0 = __float2int_rn((y0 - (float)h0) * 128.f);
    const int l1 = __float2int_rn((y1 - (float)h1) * 128.f);
    const int l2 = __float2int_rn((y2 - (float)h2) * 128.f);
    const int l3 = __float2int_rn((y3 - (float)h3) * 128.f);
    hw = pack4(h0, h1, h2, h3);
    lw = pack4(l0, l1, l2, l3);
}

// ---------------------------------------------------------------------------
// int8 dual-limb tensor-core NT GEMM: C[m,n] = sum_k A[m,k]*B[n,k]
// A = sA_m(h + l/128), B = sB_n(h + l/128); products hh + (hl+lh)/128,
// int32 accumulation over full K (exact; |sum| < 2^27).
// CTA tile 128x128, BK=32 (ONE k32 IMMA step), 256 threads = 8 warps
// (4m x 2n, warp tile 32x64). Single-barrier double-buffered pipeline.
// SMEM tiles: {Ah, Al, Bh, Bl}, 128 rows x 32B data, 48B stride (conflict-
// free ldmatrix: banks 12r mod 32 partition perfectly).
// ---------------------------------------------------------------------------
constexpr int I8MATB = 128 * 48;       // 6144 per limb tile
constexpr int I8BUFB = 4 * I8MATB;     // 24576 per double-buffer slot
constexpr int I8SMEM = 2 * I8BUFB;     // 49152

DEV_INLINE void q_store(char* bp, uint32_t off, const float4* ra, const float4* rb,
                        float invA, float invB)
{
    uint32_t h[4], l[4];
    q4(ra[0], invA, h[0], l[0]); q4(ra[1], invA, h[1], l[1]);
    q4(ra[2], invA, h[2], l[2]); q4(ra[3], invA, h[3], l[3]);
    *reinterpret_cast<uint4*>(bp + off)          = make_uint4(h[0], h[1], h[2], h[3]);
    *reinterpret_cast<uint4*>(bp + I8MATB + off) = make_uint4(l[0], l[1], l[2], l[3]);
    q4(rb[0], invB, h[0], l[0]); q4(rb[1], invB, h[1], l[1]);
    q4(rb[2], invB, h[2], l[2]); q4(rb[3], invB, h[3], l[3]);
    *reinterpret_cast<uint4*>(bp + 2 * I8MATB + off) = make_uint4(h[0], h[1], h[2], h[3]);
    *reinterpret_cast<uint4*>(bp + 3 * I8MATB + off) = make_uint4(l[0], l[1], l[2], l[3]);
}

DEV_INLINE void gemm_i8_body(const float* __restrict__ A, const float* __restrict__ Bm,
                             float* __restrict__ C, int K, int N, int m0, int n0,
                             const float2* __restrict__ sA, const float2* __restrict__ sB,
                             char* smem, uint32_t sb)
{
    const int tid  = threadIdx.x;
    const int lane = tid & 31;
    const int wid  = tid >> 5;          // 0..7
    const int wm   = wid & 3;           // 4 m-warps
    const int wn   = wid >> 2;          // 2 n-warps (warp tile 32x64)

    // producer mapping: row r (0..127), 16-float half of the 32-float chunk row
    const int r    = tid >> 1;
    const int half = tid & 1;
    const uint32_t soff = (uint32_t)r * 48 + (uint32_t)half * 16;
    const float* Arow = A  + (size_t)(m0 + r) * K + half * 16;
    const float* Brow = Bm + (size_t)(n0 + r) * K + half * 16;
    const float invA = sA[m0 + r].x;
    const float invB = sB[n0 + r].x;

    int acc_hh[2][8][4];
    int acc_x [2][8][4];
#pragma unroll
    for (int mi = 0; mi < 2; mi++)
#pragma unroll
        for (int nf = 0; nf < 8; nf++)
#pragma unroll
            for (int e = 0; e < 4; e++) { acc_hh[mi][nf][e] = 0; acc_x[mi][nf][e] = 0; }

    const uint32_t lrow = (uint32_t)(lane & 15);
    const uint32_t lcol = (uint32_t)(lane >> 4) * 16;
    const int NC = K / 32;

    // prologue: quantize chunk 0 into buf0; prefetch chunk 1 into regs
    float4 ra[4], rb[4];
    {
        float4 a0[4], b0[4];
#pragma unroll
        for (int i = 0; i < 4; i++) {
            a0[i] = *reinterpret_cast<const float4*>(Arow + i * 4);
            b0[i] = *reinterpret_cast<const float4*>(Brow + i * 4);
        }
        q_store(smem, soff, a0, b0, invA, invB);
    }
    if (NC > 1) {
#pragma unroll
        for (int i = 0; i < 4; i++) {
            ra[i] = *reinterpret_cast<const float4*>(Arow + 32 + i * 4);
            rb[i] = *reinterpret_cast<const float4*>(Brow + 32 + i * 4);
        }
    }
    __syncthreads();

    for (int c = 0; c < NC; c++) {
        const uint32_t bufs = sb + (c & 1) * I8BUFB;

        // A fragments: both limbs, two 16-row m-frags (k32 s8 == k16 b16 bytes)
        uint32_t af[2][2][4];
#pragma unroll
        for (int sel = 0; sel < 2; sel++)
#pragma unroll
            for (int mi = 0; mi < 2; mi++) {
                const uint32_t addr = bufs + (uint32_t)sel * I8MATB +
                    ((uint32_t)(wm * 32 + mi * 16) + lrow) * 48 + lcol;
                ldsm_x4(af[sel][mi], addr);
            }

        // B streamed per 16-col group; products: AhBh->hh, AlBh->x, AhBl->x
#pragma unroll
        for (int ng = 0; ng < 4; ng++) {
            const uint32_t baddr = bufs + 2 * I8MATB +
                ((uint32_t)(wn * 64 + ng * 16) + lrow) * 48 + lcol;
            uint32_t t4[4], u4[4];
            ldsm_x4(t4, baddr);             // B h limb
            ldsm_x4(u4, baddr + I8MATB);    // B l limb
            uint32_t bh0[2] = {t4[0], t4[2]}, bh1[2] = {t4[1], t4[3]};
            uint32_t bl0[2] = {u4[0], u4[2]}, bl1[2] = {u4[1], u4[3]};
#pragma unroll
            for (int mi = 0; mi < 2; mi++) {
                mma_s8(acc_hh[mi][ng * 2],     af[0][mi], bh0);
                mma_s8(acc_hh[mi][ng * 2 + 1], af[0][mi], bh1);
                mma_s8(acc_x [mi][ng * 2],     af[1][mi], bh0);
                mma_s8(acc_x [mi][ng * 2 + 1], af[1][mi], bh1);
                mma_s8(acc_x [mi][ng * 2],     af[0][mi], bl0);
                mma_s8(acc_x [mi][ng * 2 + 1], af[0][mi], bl1);
            }
        }

        // quantize+store chunk c+1; prefetch c+2
        if (c + 1 < NC) {
            q_store(smem + ((c + 1) & 1) * I8BUFB, soff, ra, rb, invA, invB);
            if (c + 2 < NC) {
                const int k0 = (c + 2) * 32;
#pragma unroll
                for (int i = 0; i < 4; i++) {
                    ra[i] = *reinterpret_cast<const float4*>(Arow + k0 + i * 4);
                    rb[i] = *reinterpret_cast<const float4*>(Brow + k0 + i * 4);
                }
            }
        }
        __syncthreads();
    }

    // epilogue: rescale and store fp32
#pragma unroll
    for (int mi = 0; mi < 2; mi++) {
        const int row = m0 + wm * 32 + mi * 16 + (lane >> 2);
        const float sa0 = sA[row].y;
        const float sa1 = sA[row + 8].y;
#pragma unroll
        for (int nf = 0; nf < 8; nf++) {
            const int col = n0 + wn * 64 + nf * 8 + (lane & 3) * 2;
            const float sb0 = sB[col].y;
            const float sb1 = sB[col + 1].y;
            const float v0 = (float)acc_hh[mi][nf][0] + 0.0078125f * (float)acc_x[mi][nf][0];
            const float v1 = (float)acc_hh[mi][nf][1] + 0.0078125f * (float)acc_x[mi][nf][1];
            const float v2 = (float)acc_hh[mi][nf][2] + 0.0078125f * (float)acc_x[mi][nf][2];
            const float v3 = (float)acc_hh[mi][nf][3] + 0.0078125f * (float)acc_x[mi][nf][3];
            *reinterpret_cast<float2*>(C + (size_t)row * N + col) =
                make_float2(sa0 * sb0 * v0, sa0 * sb1 * v1);
            *reinterpret_cast<float2*>(C + (size_t)(row + 8) * N + col) =
                make_float2(sa1 * sb0 * v2, sa1 * sb1 * v3);
        }
    }
}

// Merged QKV projection: grid (32 n-tiles routed, 32 m-tiles)
__global__ void __launch_bounds__(256, 1)
gemm_qkv_i8(const float* __restrict__ A,
            const float* __restrict__ Wq, const float* __restrict__ Wk,
            const float* __restrict__ Wv,
            float* __restrict__ q, float* __restrict__ k, float* __restrict__ v)
{
    extern __shared__ char smem[];
    const uint32_t sb = smem_u32(smem);
    const int bx = blockIdx.x;
    const int m0 = blockIdx.y * 128;

    const float* Bm; float* C; int N; int n0; const float2* sB;
    if (bx < 16)      { Bm = Wq; C = q; N = NH_ * D_;  n0 = bx * 128;        sB = g_sc_wq; }
    else if (bx < 24) { Bm = Wk; C = k; N = NKV_ * D_; n0 = (bx - 16) * 128; sB = g_sc_wk; }
    else              { Bm = Wv; C = v; N = NKV_ * D_; n0 = (bx - 24) * 128; sB = g_sc_wv; }

    gemm_i8_body(A, Bm, C, H_, N, m0, n0, g_sc_h, sB, smem, sb);
}

// Output projection GEMM (int8)
__global__ void __launch_bounds__(256, 1)
gemm_o_i8(const float* __restrict__ A, const float* __restrict__ Bm,
          float* __restrict__ C, int M, int N, int K)
{
    extern __shared__ char smem[];
    const uint32_t sb = smem_u32(smem);
    gemm_i8_body(A, Bm, C, K, N, blockIdx.y * 128, blockIdx.x * 128,
                 g_sc_ao, g_sc_wo, smem, sb);
}

// ---------------------------------------------------------------------------
// Fused RMSNorm + RoPE + bf16 hi/lo split. Warp-per-row (D=128, 4 els/lane).
// ---------------------------------------------------------------------------
__global__ void __launch_bounds__(256)
rms_rope_split2(const float* __restrict__ qbuf, const float* __restrict__ kbuf,
                const float* __restrict__ vbuf,
                const float* __restrict__ cosb, const float* __restrict__ sinb,
                const float* __restrict__ qw,   const float* __restrict__ kw,
                __nv_bfloat16* __restrict__ qh, __nv_bfloat16* __restrict__ ql,
                __nv_bfloat16* __restrict__ kh, __nv_bfloat16* __restrict__ kl,
                __nv_bfloat16* __restrict__ vh, __nv_bfloat16* __restrict__ vl)
{
    const int rrow = blockIdx.x * 8 + (threadIdx.x >> 5);
    const int l    = threadIdx.x & 31;
    const int t    = rrow >> 5;
    const int hh   = rrow & 31;

    if (hh >= 24) {                      // v: split only
        const size_t base = (size_t)t * (NKV_ * D_) + (hh - 24) * D_ + l * 4;
        const float4 x = *reinterpret_cast<const float4*>(vbuf + base);
        uint32_t h0, l0, h1, l1;
        split_pair(x.x, x.y, h0, l0);
        split_pair(x.z, x.w, h1, l1);
        *reinterpret_cast<uint2*>(vh + base) = make_uint2(h0, h1);
        *reinterpret_cast<uint2*>(vl + base) = make_uint2(l0, l1);
        return;
    }

    const float* src; const float* w;
    __nv_bfloat16 *oh, *ol;
    size_t base;
    if (hh < 16) {
        base = (size_t)t * (NH_ * D_) + hh * D_ + l * 4;
        src = qbuf; w = qw; oh = qh; ol = ql;
    } else {
        base = (size_t)t * (NKV_ * D_) + (hh - 16) * D_ + l * 4;
        src = kbuf; w = kw; oh = kh; ol = kl;
    }

    const float4 x = *reinterpret_cast<const float4*>(src + base);
    float ss = x.x * x.x + x.y * x.y + x.z * x.z + x.w * x.w;
#pragma unroll
    for (int off = 16; off >= 1; off >>= 1) ss += __shfl_xor_sync(0xffffffffu, ss, off);
    const float inv = rsqrtf(ss * (1.0f / 128.0f) + 1e-6f);

    const float4 wv = *reinterpret_cast<const float4*>(w + l * 4);
    const float4 cv = *reinterpret_cast<const float4*>(cosb + (size_t)t * D_ + l * 4);
    const float4 sv = *reinterpret_cast<const float4*>(sinb + (size_t)t * D_ + l * 4);

    const float z0 = x.x * wv.x, z1 = x.y * wv.y, z2 = x.z * wv.z, z3 = x.w * wv.w;
    const float p0 = __shfl_xor_sync(0xffffffffu, z0, 16);
    const float p1 = __shfl_xor_sync(0xffffffffu, z1, 16);
    const float p2 = __shfl_xor_sync(0xffffffffu, z2, 16);
    const float p3 = __shfl_xor_sync(0xffffffffu, z3, 16);
    const float sgn = (l < 16) ? -1.f : 1.f;

    const float y0 = (z0 * cv.x + sgn * p0 * sv.x) * inv;
    const float y1 = (z1 * cv.y + sgn * p1 * sv.y) * inv;
    const float y2 = (z2 * cv.z + sgn * p2 * sv.z) * inv;
    const float y3 = (z3 * cv.w + sgn * p3 * sv.w) * inv;

    uint32_t h0, l0w, h1, l1w;
    split_pair(y0, y1, h0, l0w);
    split_pair(y2, y3, h1, l1w);
    *reinterpret_cast<uint2*>(oh + base) = make_uint2(h0, h1);
    *reinterpret_cast<uint2*>(ol + base) = make_uint2(l0w, l1w);
}

// ---------------------------------------------------------------------------
// Tensor-core flash attention (bf16x3, causal, GQA n_rep=2). Round-4 proven.
// BQ=128, BKV=64, D=128. 256 threads = 8 warps, warp w -> q rows w*16..+15.
// ---------------------------------------------------------------------------
constexpr int AQ_BYTES  = 128 * 272;                 // 34816
constexpr int AKV_BYTES = 64 * 272;                  // 17408
constexpr int ABUF0     = 2 * AQ_BYTES;              // 69632
constexpr int ABUFSZ    = 4 * AKV_BYTES;             // 69632
constexpr int ATTN_SMEM = ABUF0 + 2 * ABUFSZ;        // 208896

__global__ void __launch_bounds__(256, 1)
attn_bf16_kernel(const __nv_bfloat16* __restrict__ qh, const __nv_bfloat16* __restrict__ ql,
                 const __nv_bfloat16* __restrict__ kh, const __nv_bfloat16* __restrict__ kl,
                 const __nv_bfloat16* __restrict__ vh, const __nv_bfloat16* __restrict__ vl,
                 float* __restrict__ ao)
{
    extern __shared__ char smem[];
    const uint32_t sb = smem_u32(smem);

    const int tid  = threadIdx.x;
    const int lane = tid & 31;
    const int w    = tid >> 5;
    const int qi   = gridDim.x - 1 - blockIdx.x;
    const int h    = blockIdx.y;
    const int b    = blockIdx.z;
    const int kvh  = h >> 1;

#pragma unroll
    for (int i = 0; i < 8; i++) {
        const int idx = tid + i * 256;
        const int row = idx >> 4, ch = idx & 15;
        const size_t g = ((size_t)(b * S_) + qi * 128 + row) * (NH_ * D_) + h * D_ + ch * 8;
        cp16(sb + row * 272 + ch * 16,            qh + g);
        cp16(sb + AQ_BYTES + row * 272 + ch * 16, ql + g);
    }
    {
        const uint32_t buf = sb + ABUF0;
#pragma unroll
        for (int i = 0; i < 4; i++) {
            const int idx = tid + i * 256;
            const int row = idx >> 4, ch = idx & 15;
            const size_t g = ((size_t)(b * S_) + row) * (NKV_ * D_) + kvh * D_ + ch * 8;
            const uint32_t so = buf + row * 272 + ch * 16;
            cp16(so,                 kh + g);
            cp16(so + AKV_BYTES,     kl + g);
            cp16(so + 2 * AKV_BYTES, vh + g);
            cp16(so + 3 * AKV_BYTES, vl + g);
        }
    }
    cp_commit();

    float oacc[16][4];
#pragma unroll
    for (int i = 0; i < 16; i++)
#pragma unroll
        for (int e = 0; e < 4; e++) oacc[i][e] = 0.f;
    float m_i[2] = {-1e30f, -1e30f};
    float l_i[2] = {0.f, 0.f};

    const uint32_t lrow16 = (uint32_t)(lane & 15);
    const uint32_t lhalf  = (uint32_t)(lane >> 4) * 16;
    const int jmax = 2 * qi + 1;

    for (int jb = 0; jb <= jmax; jb++) {
        if (jb < jmax) {
            const uint32_t buf = sb + ABUF0 + ((jb + 1) & 1) * ABUFSZ;
#pragma unroll
            for (int i = 0; i < 4; i++) {
                const int idx = tid + i * 256;
                const int row = idx >> 4, ch = idx & 15;
                const size_t g = ((size_t)(b * S_) + (jb + 1) * 64 + row) * (NKV_ * D_) +
                                 kvh * D_ + ch * 8;
                const uint32_t so = buf + row * 272 + ch * 16;
                cp16(so,                 kh + g);
                cp16(so + AKV_BYTES,     kl + g);
                cp16(so + 2 * AKV_BYTES, vh + g);
                cp16(so + 3 * AKV_BYTES, vl + g);
            }
            cp_commit();
            cp_wait1();
        } else {
            cp_wait0();
        }
        __syncthreads();

        const uint32_t kb = sb + ABUF0 + (jb & 1) * ABUFSZ;
        const bool skip = (jb * 64) > (qi * 128 + w * 16 + 15);

        if (!skip) {
            float sacc[8][4];
#pragma unroll
            for (int i = 0; i < 8; i++)
#pragma unroll
                for (int e = 0; e < 4; e++) sacc[i][e] = 0.f;

            const uint32_t qbase = sb + ((uint32_t)(w * 16) + lrow16) * 272 + lhalf;
#pragma unroll
            for (int ks = 0; ks < 8; ks++) {
                uint32_t ahi[4], alo[4];
                ldsm_x4(ahi, qbase + ks * 32);
                ldsm_x4(alo, qbase + AQ_BYTES + ks * 32);
#pragma unroll
                for (int ng = 0; ng < 4; ng++) {
                    uint32_t t[4], u[4];
                    const uint32_t ka = kb + ((uint32_t)(ng * 16) + lrow16) * 272 + ks * 32 + lhalf;
                    ldsm_x4(t, ka);
                    ldsm_x4(u, ka + AKV_BYTES);
                    uint32_t bh0[2] = {t[0], t[2]}, bh1[2] = {t[1], t[3]};
                    uint32_t bl0[2] = {u[0], u[2]}, bl1[2] = {u[1], u[3]};
                    mma_bf16(sacc[ng * 2],     ahi, bh0);
                    mma_bf16(sacc[ng * 2 + 1], ahi, bh1);
                    mma_bf16(sacc[ng * 2],     ahi, bl0);
                    mma_bf16(sacc[ng * 2 + 1], ahi, bl1);
                    mma_bf16(sacc[ng * 2],     alo, bh0);
                    mma_bf16(sacc[ng * 2 + 1], alo, bh1);
                }
            }

            const float sc = 0.088388347648318447f;
            const bool domask = (jb * 64 + 63) > (qi * 128 + w * 16);
#pragma unroll
            for (int nf = 0; nf < 8; nf++)
#pragma unroll
                for (int e = 0; e < 4; e++) {
                    float s = sacc[nf][e] * sc;
                    if (domask) {
                        const int col = jb * 64 + nf * 8 + ((lane & 3) << 1) + (e & 1);
                        const int row = qi * 128 + w * 16 + (lane >> 2) + ((e >> 1) << 3);
                        if (col > row) s = -1e30f;
                    }
                    sacc[nf][e] = s;
                }

#pragma unroll
            for (int r2 = 0; r2 < 2; r2++) {
                float mx = -1e30f;
#pragma unroll
                for (int nf = 0; nf < 8; nf++)
                    mx = fmaxf(mx, fmaxf(sacc[nf][2 * r2], sacc[nf][2 * r2 + 1]));
                mx = fmaxf(mx, __shfl_xor_sync(0xffffffffu, mx, 1));
                mx = fmaxf(mx, __shfl_xor_sync(0xffffffffu, mx, 2));
                const float mn = fmaxf(m_i[r2], mx);
                const float alpha = __expf(m_i[r2] - mn);
                m_i[r2] = mn;
                float rs = 0.f;
#pragma unroll
                for (int nf = 0; nf < 8; nf++) {
                    float p0 = __expf(sacc[nf][2 * r2]     - mn);
                    float p1 = __expf(sacc[nf][2 * r2 + 1] - mn);
                    sacc[nf][2 * r2]     = p0;
                    sacc[nf][2 * r2 + 1] = p1;
                    rs += p0 + p1;
                }
                rs += __shfl_xor_sync(0xffffffffu, rs, 1);
                rs += __shfl_xor_sync(0xffffffffu, rs, 2);
                l_i[r2] = l_i[r2] * alpha + rs;
#pragma unroll
                for (int ndf = 0; ndf < 16; ndf++) {
                    oacc[ndf][2 * r2]     *= alpha;
                    oacc[ndf][2 * r2 + 1] *= alpha;
                }
            }

#pragma unroll
            for (int kk = 0; kk < 4; kk++) {
                uint32_t phi[4], plo[4];
                split_pair(sacc[2 * kk][0],     sacc[2 * kk][1],     phi[0], plo[0]);
                split_pair(sacc[2 * kk][2],     sacc[2 * kk][3],     phi[1], plo[1]);
                split_pair(sacc[2 * kk + 1][0], sacc[2 * kk + 1][1], phi[2], plo[2]);
                split_pair(sacc[2 * kk + 1][2], sacc[2 * kk + 1][3], phi[3], plo[3]);
#pragma unroll
                for (int ndg = 0; ndg < 8; ndg++) {
                    uint32_t t[4], u[4];
                    const uint32_t va = kb + 2 * AKV_BYTES +
                        ((uint32_t)(kk * 16) + lrow16) * 272 + ndg * 32 + lhalf;
                    ldsm_x4_trans(t, va);
                    ldsm_x4_trans(u, va + AKV_BYTES);
                    uint32_t bh0[2] = {t[0], t[1]}, bh1[2] = {t[2], t[3]};
                    uint32_t bl0[2] = {u[0], u[1]}, bl1[2] = {u[2], u[3]};
                    mma_bf16(oacc[ndg * 2],     phi, bh0);
                    mma_bf16(oacc[ndg * 2 + 1], phi, bh1);
                    mma_bf16(oacc[ndg * 2],     phi, bl0);
                    mma_bf16(oacc[ndg * 2 + 1], phi, bl1);
                    mma_bf16(oacc[ndg * 2],     plo, bh0);
                    mma_bf16(oacc[ndg * 2 + 1], plo, bh1);
                }
            }
        }
        __syncthreads();
    }

    const float i0 = 1.0f / l_i[0];
    const float i1 = 1.0f / l_i[1];
    const int row0 = qi * 128 + w * 16 + (lane >> 2);
    const size_t base0 = ((size_t)(b * S_) + row0) * (NH_ * D_) + h * D_ + (lane & 3) * 2;
    const size_t base1 = base0 + (size_t)8 * (NH_ * D_);
#pragma unroll
    for (int ndf = 0; ndf < 16; ndf++) {
        *reinterpret_cast<float2*>(ao + base0 + ndf * 8) =
            make_float2(oacc[ndf][0] * i0, oacc[ndf][1] * i0);
        *reinterpret_cast<float2*>(ao + base1 + ndf * 8) =
            make_float2(oacc[ndf][2] * i1, oacc[ndf][3] * i1);
    }
}

// ---------------------------------------------------------------------------
// Launch
// ---------------------------------------------------------------------------
extern "C" void kernel_launch(void* const* d_in, const int* in_sizes, int n_in,
                              void* d_out, int out_size)
{
    const float* hidden = (const float*)d_in[0];
    const float* cosb   = (const float*)d_in[1];
    const float* sinb   = (const float*)d_in[2];
    const float* Wq     = (const float*)d_in[3];
    const float* Wk     = (const float*)d_in[4];
    const float* Wv     = (const float*)d_in[5];
    const float* Wo     = (const float*)d_in[6];
    const float* qw     = (const float*)d_in[7];
    const float* kw     = (const float*)d_in[8];
    float* out = (float*)d_out;

    float *gq, *gk, *gv, *gao;
    cudaGetSymbolAddress((void**)&gq,  g_q);
    cudaGetSymbolAddress((void**)&gk,  g_k);
    cudaGetSymbolAddress((void**)&gv,  g_v);
    cudaGetSymbolAddress((void**)&gao, g_ao);
    __nv_bfloat16 *qh, *ql, *kh, *kl, *vh, *vl;
    cudaGetSymbolAddress((void**)&qh, g_qh);
    cudaGetSymbolAddress((void**)&ql, g_ql);
    cudaGetSymbolAddress((void**)&kh, g_kh);
    cudaGetSymbolAddress((void**)&kl, g_kl);
    cudaGetSymbolAddress((void**)&vh, g_vh);
    cudaGetSymbolAddress((void**)&vl, g_vl);
    float2 *sc_h, *sc_wq, *sc_wk, *sc_wv, *sc_wo, *sc_ao;
    cudaGetSymbolAddress((void**)&sc_h,  g_sc_h);
    cudaGetSymbolAddress((void**)&sc_wq, g_sc_wq);
    cudaGetSymbolAddress((void**)&sc_wk, g_sc_wk);
    cudaGetSymbolAddress((void**)&sc_wv, g_sc_wv);
    cudaGetSymbolAddress((void**)&sc_wo, g_sc_wo);
    cudaGetSymbolAddress((void**)&sc_ao, g_sc_ao);

    cudaFuncSetAttribute((const void*)gemm_qkv_i8,
                         cudaFuncAttributeMaxDynamicSharedMemorySize, I8SMEM);
    cudaFuncSetAttribute((const void*)gemm_o_i8,
                         cudaFuncAttributeMaxDynamicSharedMemorySize, I8SMEM);
    cudaFuncSetAttribute((const void*)attn_bf16_kernel,
                         cudaFuncAttributeMaxDynamicSharedMemorySize, ATTN_SMEM);

    // row-max pre-passes (scales for int8 quantization)
    rowmax_kernel<<<TOK / 8, 256>>>(hidden, sc_h, H_);
    rowmax_kernel<<<(NH_ * D_) / 8, 256>>>(Wq, sc_wq, H_);
    rowmax_kernel<<<(NKV_ * D_) / 8, 256>>>(Wk, sc_wk, H_);
    rowmax_kernel<<<(NKV_ * D_) / 8, 256>>>(Wv, sc_wv, H_);
    rowmax_kernel<<<H_ / 8, 256>>>(Wo, sc_wo, NH_ * D_);

    // merged QKV projection (int8 dual-limb tensor GEMM)
    gemm_qkv_i8<<<dim3(32, TOK / 128), 256, I8SMEM>>>(hidden, Wq, Wk, Wv, gq, gk, gv);

    // fused RMSNorm + RoPE + split (warp per row)
    rms_rope_split2<<<TOK * 32 / 8, 256>>>(gq, gk, gv, cosb, sinb, qw, kw,
                                           qh, ql, kh, kl, vh, vl);

    // tensor-core causal flash attention (bf16x3)
    attn_bf16_kernel<<<dim3(S_ / 128, NH_, B_), 256, ATTN_SMEM>>>(
        qh, ql, kh, kl, vh, vl, gao);

    // output projection (int8 dual-limb)
    rowmax_kernel<<<TOK / 8, 256>>>(gao, sc_ao, NH_ * D_);
    gemm_o_i8<<<dim3(H_ / 128, TOK / 128), 256, I8SMEM>>>(
        gao, Wo, out, TOK, H_, NH_ * D_);
}

// round 12
// speedup vs baseline: 1.9440x; 1.9440x over previous
#include <cuda_runtime.h>
#include <cuda_bf16.h>
#include <cstdint>

// ---------------------------------------------------------------------------
// Problem constants (B=2, S=2048, H=1024, NH=16, NKV=8, D=128)
// ---------------------------------------------------------------------------
constexpr int B_   = 2;
constexpr int S_   = 2048;
constexpr int H_   = 1024;
constexpr int NH_  = 16;
constexpr int NKV_ = 8;
constexpr int D_   = 128;
constexpr int TOK  = B_ * S_;            // 4096 tokens

// Scratch (device globals; no allocation allowed)
__device__ float g_ao[TOK * NH_ * D_];
// bf16 hi/lo split attention operands
__device__ __nv_bfloat16 g_qh[TOK * NH_  * D_], g_ql[TOK * NH_  * D_];
__device__ __nv_bfloat16 g_kh[TOK * NKV_ * D_], g_kl[TOK * NKV_ * D_];
__device__ __nv_bfloat16 g_vh[TOK * NKV_ * D_], g_vl[TOK * NKV_ * D_];

#define DEV_INLINE __device__ __forceinline__

// ---------------------------------------------------------------------------
// helpers
// ---------------------------------------------------------------------------
DEV_INLINE uint32_t cvt_bf16x2(float hi_elem, float lo_elem) {
    uint32_t r;
    asm("cvt.rn.bf16x2.f32 %0, %1, %2;" : "=r"(r) : "f"(hi_elem), "f"(lo_elem));
    return r;
}
// split two fp32 (f0 -> low lane, f1 -> high lane) into bf16 hi-pair + lo-pair
DEV_INLINE void split_pair(float f0, float f1, uint32_t& hiw, uint32_t& low) {
    hiw = cvt_bf16x2(f1, f0);
    float h0 = __uint_as_float(hiw << 16);
    float h1 = __uint_as_float(hiw & 0xFFFF0000u);
    low = cvt_bf16x2(f1 - h1, f0 - h0);
}
DEV_INLINE void ldsm_x4(uint32_t* r, uint32_t addr) {
    asm volatile("ldmatrix.sync.aligned.m8n8.x4.shared.b16 {%0,%1,%2,%3}, [%4];"
                 : "=r"(r[0]), "=r"(r[1]), "=r"(r[2]), "=r"(r[3]) : "r"(addr));
}
DEV_INLINE void ldsm_x4_trans(uint32_t* r, uint32_t addr) {
    asm volatile("ldmatrix.sync.aligned.m8n8.x4.trans.shared.b16 {%0,%1,%2,%3}, [%4];"
                 : "=r"(r[0]), "=r"(r[1]), "=r"(r[2]), "=r"(r[3]) : "r"(addr));
}
DEV_INLINE void mma_bf16(float* c, const uint32_t* a, const uint32_t* b) {
    asm volatile(
        "mma.sync.aligned.m16n8k16.row.col.f32.bf16.bf16.f32 "
        "{%0,%1,%2,%3}, {%4,%5,%6,%7}, {%8,%9}, {%0,%1,%2,%3};"
        : "+f"(c[0]), "+f"(c[1]), "+f"(c[2]), "+f"(c[3])
        : "r"(a[0]), "r"(a[1]), "r"(a[2]), "r"(a[3]), "r"(b[0]), "r"(b[1]));
}
DEV_INLINE uint32_t smem_u32(const void* p) {
    uint32_t a;
    asm("{ .reg .u64 t; cvta.to.shared.u64 t, %1; cvt.u32.u64 %0, t; }"
        : "=r"(a) : "l"(p));
    return a;
}
DEV_INLINE void cp16(uint32_t dst, const void* src) {
    asm volatile("cp.async.cg.shared.global [%0], [%1], 16;"
                 :: "r"(dst), "l"(src) : "memory");
}
DEV_INLINE void cp_commit() { asm volatile("cp.async.commit_group;" ::: "memory"); }
DEV_INLINE void cp_wait1()  { asm volatile("cp.async.wait_group 1;" ::: "memory"); }
DEV_INLINE void cp_wait0()  { asm volatile("cp.async.wait_group 0;" ::: "memory"); }

// ---------------------------------------------------------------------------
// bf16x3 tensor-core NT GEMM mainloop — round-7 champion configuration.
// 512 threads / 16 warps (4m x 4n, warp tile 32x32), CTA tile 128x128, BK=32,
// in-loop split, double buffered, 2 syncs/chunk.
// 3 products: Ah*Bh + Ah*Bl + Al*Bh. Result left in Cacc[2][4][4].
// ---------------------------------------------------------------------------
constexpr int GMATB = 10240;           // 128 * 80 bytes per split tile
constexpr int GBUFB = 4 * GMATB;       // 40960 per double-buffer slot
constexpr int GSMEM = 2 * GBUFB;       // 81920

DEV_INLINE void gemm_mainloop(const float* __restrict__ A, const float* __restrict__ Bm,
                              int K, int m0, int n0,
                              char* smem, uint32_t sb, float Cacc[2][4][4])
{
    const int tid  = threadIdx.x;
    const int lane = tid & 31;
    const int wid  = tid >> 5;          // 0..15
    const int wm   = wid & 3;           // 4 m-warps
    const int wn   = wid >> 2;          // 4 n-warps

    const int r = tid >> 2;             // 0..127
    const int q = tid & 3;              // quarter (8 f32)
    const float* Arow = A  + (size_t)(m0 + r) * K + q * 8;
    const float* Brow = Bm + (size_t)(n0 + r) * K + q * 8;

#pragma unroll
    for (int mi = 0; mi < 2; mi++)
#pragma unroll
        for (int nf = 0; nf < 4; nf++)
#pragma unroll
            for (int e = 0; e < 4; e++) Cacc[mi][nf][e] = 0.f;

    float4 ra[2], rb[2];
#pragma unroll
    for (int i = 0; i < 2; i++) {
        ra[i] = *reinterpret_cast<const float4*>(Arow + i * 4);
        rb[i] = *reinterpret_cast<const float4*>(Brow + i * 4);
    }

    const uint32_t lrow = (uint32_t)(lane & 15);
    const uint32_t lcol = (uint32_t)(lane >> 4) * 16;

    const int NC = K / 32;
    for (int c = 0; c < NC; c++) {
        char* bp = smem + (c & 1) * GBUFB;
        const uint32_t bufs = sb + (c & 1) * GBUFB;

        {   // split + store this chunk (8 f32 of A, 8 f32 of B per thread)
            const uint32_t off = (uint32_t)r * 80 + (uint32_t)q * 16;
            uint32_t h0, l0, h1, l1, h2, l2, h3, l3;
            split_pair(ra[0].x, ra[0].y, h0, l0);
            split_pair(ra[0].z, ra[0].w, h1, l1);
            split_pair(ra[1].x, ra[1].y, h2, l2);
            split_pair(ra[1].z, ra[1].w, h3, l3);
            *reinterpret_cast<uint4*>(bp + off)         = make_uint4(h0, h1, h2, h3);
            *reinterpret_cast<uint4*>(bp + GMATB + off) = make_uint4(l0, l1, l2, l3);
            split_pair(rb[0].x, rb[0].y, h0, l0);
            split_pair(rb[0].z, rb[0].w, h1, l1);
            split_pair(rb[1].x, rb[1].y, h2, l2);
            split_pair(rb[1].z, rb[1].w, h3, l3);
            *reinterpret_cast<uint4*>(bp + 2 * GMATB + off) = make_uint4(h0, h1, h2, h3);
            *reinterpret_cast<uint4*>(bp + 3 * GMATB + off) = make_uint4(l0, l1, l2, l3);
        }
        __syncthreads();

        if (c + 1 < NC) {               // register prefetch of next chunk
            const int k0 = (c + 1) * 32;
#pragma unroll
            for (int i = 0; i < 2; i++) {
                ra[i] = *reinterpret_cast<const float4*>(Arow + k0 + i * 4);
                rb[i] = *reinterpret_cast<const float4*>(Brow + k0 + i * 4);
            }
        }

#pragma unroll
        for (int ks = 0; ks < 2; ks++) {
            uint32_t afrag[2][2][4];    // [sel][mi][4]
            uint32_t bfr[2][4][2];      // [sel][nf][2]
#pragma unroll
            for (int sel = 0; sel < 2; sel++) {
#pragma unroll
                for (int mi = 0; mi < 2; mi++) {
                    const uint32_t addr = bufs + (uint32_t)sel * GMATB +
                        ((uint32_t)(wm * 32 + mi * 16) + lrow) * 80 +
                        (uint32_t)ks * 32 + lcol;
                    ldsm_x4(afrag[sel][mi], addr);
                }
#pragma unroll
                for (int ng = 0; ng < 2; ng++) {
                    uint32_t t4[4];
                    const uint32_t addr = bufs + 2 * GMATB + (uint32_t)sel * GMATB +
                        ((uint32_t)(wn * 32 + ng * 16) + lrow) * 80 +
                        (uint32_t)ks * 32 + lcol;
                    ldsm_x4(t4, addr);
                    bfr[sel][ng * 2][0]     = t4[0];
                    bfr[sel][ng * 2][1]     = t4[2];
                    bfr[sel][ng * 2 + 1][0] = t4[1];
                    bfr[sel][ng * 2 + 1][1] = t4[3];
                }
            }
#pragma unroll
            for (int mi = 0; mi < 2; mi++)
#pragma unroll
                for (int nf = 0; nf < 4; nf++)
                    mma_bf16(Cacc[mi][nf], afrag[0][mi], bfr[0][nf]);
#pragma unroll
            for (int mi = 0; mi < 2; mi++)
#pragma unroll
                for (int nf = 0; nf < 4; nf++)
                    mma_bf16(Cacc[mi][nf], afrag[0][mi], bfr[1][nf]);
#pragma unroll
            for (int mi = 0; mi < 2; mi++)
#pragma unroll
                for (int nf = 0; nf < 4; nf++)
                    mma_bf16(Cacc[mi][nf], afrag[1][mi], bfr[0][nf]);
        }
        __syncthreads();
    }
}

// ---------------------------------------------------------------------------
// Merged QKV projection + FUSED RMSNorm/RoPE/bf16-split epilogue.
// grid (32 routed n-tiles, 32 m-tiles), 512 threads.
// A CTA's output tile [128 tokens x 128 cols] is exactly one head's full D.
// ---------------------------------------------------------------------------
__global__ void __launch_bounds__(512, 1)
gemm_qkv_fused(const float* __restrict__ A,
               const float* __restrict__ Wq, const float* __restrict__ Wk,
               const float* __restrict__ Wv,
               const float* __restrict__ cosb, const float* __restrict__ sinb,
               const float* __restrict__ qw,   const float* __restrict__ kw,
               __nv_bfloat16* __restrict__ qh, __nv_bfloat16* __restrict__ ql,
               __nv_bfloat16* __restrict__ kh, __nv_bfloat16* __restrict__ kl,
               __nv_bfloat16* __restrict__ vh, __nv_bfloat16* __restrict__ vl)
{
    extern __shared__ char smem[];
    const uint32_t sb = smem_u32(smem);
    const int bx = blockIdx.x;
    const int m0 = blockIdx.y * 128;

    const float* Bm; int n0;
    if (bx < 16)      { Bm = Wq; n0 = bx * 128; }
    else if (bx < 24) { Bm = Wk; n0 = (bx - 16) * 128; }
    else              { Bm = Wv; n0 = (bx - 24) * 128; }

    float Cacc[2][4][4];
    gemm_mainloop(A, Bm, H_, m0, n0, smem, sb, Cacc);

    // ---- stash C tile to smem (post-final-sync; buffers dead) ----
    float* Cs = reinterpret_cast<float*>(smem);      // [128][132]
    {
        const int lane = threadIdx.x & 31;
        const int wid  = threadIdx.x >> 5;
        const int wm   = wid & 3;
        const int wn   = wid >> 2;
#pragma unroll
        for (int mi = 0; mi < 2; mi++) {
            const int row = wm * 32 + mi * 16 + (lane >> 2);
#pragma unroll
            for (int nf = 0; nf < 4; nf++) {
                const int col = wn * 32 + nf * 8 + (lane & 3) * 2;
                *reinterpret_cast<float2*>(&Cs[row * 132 + col]) =
                    make_float2(Cacc[mi][nf][0], Cacc[mi][nf][1]);
                *reinterpret_cast<float2*>(&Cs[(row + 8) * 132 + col]) =
                    make_float2(Cacc[mi][nf][2], Cacc[mi][nf][3]);
            }
        }
    }
    __syncthreads();

    // ---- fused norm phase: warp w handles rows w*8 .. w*8+7 ----
    const int lane = threadIdx.x & 31;
    const int wid  = threadIdx.x >> 5;
    const int l    = lane;

    if (bx >= 24) {                       // V: split only
        const int hv = bx - 24;
#pragma unroll
        for (int rr = 0; rr < 8; rr++) {
            const int row = wid * 8 + rr;
            const int token = m0 + row;
            const float4 x = *reinterpret_cast<const float4*>(&Cs[row * 132 + l * 4]);
            uint32_t h0, l0w, h1, l1w;
            split_pair(x.x, x.y, h0, l0w);
            split_pair(x.z, x.w, h1, l1w);
            const size_t base = (size_t)token * (NKV_ * D_) + hv * D_ + l * 4;
            *reinterpret_cast<uint2*>(vh + base) = make_uint2(h0, h1);
            *reinterpret_cast<uint2*>(vl + base) = make_uint2(l0w, l1w);
        }
        return;
    }

    const bool isq = (bx < 16);
    const float* w = isq ? qw : kw;
    __nv_bfloat16* oh = isq ? qh : kh;
    __nv_bfloat16* ol = isq ? ql : kl;
    const int hd  = isq ? bx : (bx - 16);
    const int hdn = isq ? (NH_ * D_) : (NKV_ * D_);
    const float4 wv = *reinterpret_cast<const float4*>(w + l * 4);
    const float sgn = (l < 16) ? -1.f : 1.f;

#pragma unroll
    for (int rr = 0; rr < 8; rr++) {
        const int row = wid * 8 + rr;
        const int token = m0 + row;
        const float4 x = *reinterpret_cast<const float4*>(&Cs[row * 132 + l * 4]);

        float ss = x.x * x.x + x.y * x.y + x.z * x.z + x.w * x.w;
#pragma unroll
        for (int off = 16; off >= 1; off >>= 1)
            ss += __shfl_xor_sync(0xffffffffu, ss, off);
        const float inv = rsqrtf(ss * (1.0f / 128.0f) + 1e-6f);

        const float4 cv = *reinterpret_cast<const float4*>(cosb + (size_t)token * D_ + l * 4);
        const float4 sv = *reinterpret_cast<const float4*>(sinb + (size_t)token * D_ + l * 4);

        const float z0 = x.x * wv.x, z1 = x.y * wv.y, z2 = x.z * wv.z, z3 = x.w * wv.w;
        const float p0 = __shfl_xor_sync(0xffffffffu, z0, 16);
        const float p1 = __shfl_xor_sync(0xffffffffu, z1, 16);
        const float p2 = __shfl_xor_sync(0xffffffffu, z2, 16);
        const float p3 = __shfl_xor_sync(0xffffffffu, z3, 16);

        const float y0 = (z0 * cv.x + sgn * p0 * sv.x) * inv;
        const float y1 = (z1 * cv.y + sgn * p1 * sv.y) * inv;
        const float y2 = (z2 * cv.z + sgn * p2 * sv.z) * inv;
        const float y3 = (z3 * cv.w + sgn * p3 * sv.w) * inv;

        uint32_t h0, l0w, h1, l1w;
        split_pair(y0, y1, h0, l0w);
        split_pair(y2, y3, h1, l1w);
        const size_t base = (size_t)token * hdn + hd * D_ + l * 4;
        *reinterpret_cast<uint2*>(oh + base) = make_uint2(h0, h1);
        *reinterpret_cast<uint2*>(ol + base) = make_uint2(l0w, l1w);
    }
}

// ---------------------------------------------------------------------------
// Generic GEMM (output projection) — round-7 exact
// ---------------------------------------------------------------------------
__global__ void __launch_bounds__(512, 1)
gemm_nt(const float* __restrict__ A, const float* __restrict__ Bm,
        float* __restrict__ C, int M, int N, int K)
{
    extern __shared__ char smem[];
    const uint32_t sb = smem_u32(smem);
    const int m0 = blockIdx.y * 128;
    const int n0 = blockIdx.x * 128;

    float Cacc[2][4][4];
    gemm_mainloop(A, Bm, K, m0, n0, smem, sb, Cacc);

    const int lane = threadIdx.x & 31;
    const int wid  = threadIdx.x >> 5;
    const int wm   = wid & 3;
    const int wn   = wid >> 2;
#pragma unroll
    for (int mi = 0; mi < 2; mi++) {
        const int row = m0 + wm * 32 + mi * 16 + (lane >> 2);
#pragma unroll
        for (int nf = 0; nf < 4; nf++) {
            const int col = n0 + wn * 32 + nf * 8 + (lane & 3) * 2;
            *reinterpret_cast<float2*>(C + (size_t)row * N + col) =
                make_float2(Cacc[mi][nf][0], Cacc[mi][nf][1]);
            *reinterpret_cast<float2*>(C + (size_t)(row + 8) * N + col) =
                make_float2(Cacc[mi][nf][2], Cacc[mi][nf][3]);
        }
    }
}

// ---------------------------------------------------------------------------
// Tensor-core flash attention (bf16x3, causal, GQA n_rep=2). Round-4 proven.
// BQ=128, BKV=64, D=128. 256 threads = 8 warps, warp w -> q rows w*16..+15.
// ---------------------------------------------------------------------------
constexpr int AQ_BYTES  = 128 * 272;                 // 34816
constexpr int AKV_BYTES = 64 * 272;                  // 17408
constexpr int ABUF0     = 2 * AQ_BYTES;              // 69632
constexpr int ABUFSZ    = 4 * AKV_BYTES;             // 69632
constexpr int ATTN_SMEM = ABUF0 + 2 * ABUFSZ;        // 208896

__global__ void __launch_bounds__(256, 1)
attn_bf16_kernel(const __nv_bfloat16* __restrict__ qh, const __nv_bfloat16* __restrict__ ql,
                 const __nv_bfloat16* __restrict__ kh, const __nv_bfloat16* __restrict__ kl,
                 const __nv_bfloat16* __restrict__ vh, const __nv_bfloat16* __restrict__ vl,
                 float* __restrict__ ao)
{
    extern __shared__ char smem[];
    const uint32_t sb = smem_u32(smem);

    const int tid  = threadIdx.x;
    const int lane = tid & 31;
    const int w    = tid >> 5;
    const int qi   = gridDim.x - 1 - blockIdx.x;
    const int h    = blockIdx.y;
    const int b    = blockIdx.z;
    const int kvh  = h >> 1;

#pragma unroll
    for (int i = 0; i < 8; i++) {
        const int idx = tid + i * 256;
        const int row = idx >> 4, ch = idx & 15;
        const size_t g = ((size_t)(b * S_) + qi * 128 + row) * (NH_ * D_) + h * D_ + ch * 8;
        cp16(sb + row * 272 + ch * 16,            qh + g);
        cp16(sb + AQ_BYTES + row * 272 + ch * 16, ql + g);
    }
    {
        const uint32_t buf = sb + ABUF0;
#pragma unroll
        for (int i = 0; i < 4; i++) {
            const int idx = tid + i * 256;
            const int row = idx >> 4, ch = idx & 15;
            const size_t g = ((size_t)(b * S_) + row) * (NKV_ * D_) + kvh * D_ + ch * 8;
            const uint32_t so = buf + row * 272 + ch * 16;
            cp16(so,                 kh + g);
            cp16(so + AKV_BYTES,     kl + g);
            cp16(so + 2 * AKV_BYTES, vh + g);
            cp16(so + 3 * AKV_BYTES, vl + g);
        }
    }
    cp_commit();

    float oacc[16][4];
#pragma unroll
    for (int i = 0; i < 16; i++)
#pragma unroll
        for (int e = 0; e < 4; e++) oacc[i][e] = 0.f;
    float m_i[2] = {-1e30f, -1e30f};
    float l_i[2] = {0.f, 0.f};

    const uint32_t lrow16 = (uint32_t)(lane & 15);
    const uint32_t lhalf  = (uint32_t)(lane >> 4) * 16;
    const int jmax = 2 * qi + 1;

    for (int jb = 0; jb <= jmax; jb++) {
        if (jb < jmax) {
            const uint32_t buf = sb + ABUF0 + ((jb + 1) & 1) * ABUFSZ;
#pragma unroll
            for (int i = 0; i < 4; i++) {
                const int idx = tid + i * 256;
                const int row = idx >> 4, ch = idx & 15;
                const size_t g = ((size_t)(b * S_) + (jb + 1) * 64 + row) * (NKV_ * D_) +
                                 kvh * D_ + ch * 8;
                const uint32_t so = buf + row * 272 + ch * 16;
                cp16(so,                 kh + g);
                cp16(so + AKV_BYTES,     kl + g);
                cp16(so + 2 * AKV_BYTES, vh + g);
                cp16(so + 3 * AKV_BYTES, vl + g);
            }
            cp_commit();
            cp_wait1();
        } else {
            cp_wait0();
        }
        __syncthreads();

        const uint32_t kb = sb + ABUF0 + (jb & 1) * ABUFSZ;
        const bool skip = (jb * 64) > (qi * 128 + w * 16 + 15);

        if (!skip) {
            float sacc[8][4];
#pragma unroll
            for (int i = 0; i < 8; i++)
#pragma unroll
                for (int e = 0; e < 4; e++) sacc[i][e] = 0.f;

            const uint32_t qbase = sb + ((uint32_t)(w * 16) + lrow16) * 272 + lhalf;
#pragma unroll
            for (int ks = 0; ks < 8; ks++) {
                uint32_t ahi[4], alo[4];
                ldsm_x4(ahi, qbase + ks * 32);
                ldsm_x4(alo, qbase + AQ_BYTES + ks * 32);
#pragma unroll
                for (int ng = 0; ng < 4; ng++) {
                    uint32_t t[4], u[4];
                    const uint32_t ka = kb + ((uint32_t)(ng * 16) + lrow16) * 272 + ks * 32 + lhalf;
                    ldsm_x4(t, ka);
                    ldsm_x4(u, ka + AKV_BYTES);
                    uint32_t bh0[2] = {t[0], t[2]}, bh1[2] = {t[1], t[3]};
                    uint32_t bl0[2] = {u[0], u[2]}, bl1[2] = {u[1], u[3]};
                    mma_bf16(sacc[ng * 2],     ahi, bh0);
                    mma_bf16(sacc[ng * 2 + 1], ahi, bh1);
                    mma_bf16(sacc[ng * 2],     ahi, bl0);
                    mma_bf16(sacc[ng * 2 + 1], ahi, bl1);
                    mma_bf16(sacc[ng * 2],     alo, bh0);
                    mma_bf16(sacc[ng * 2 + 1], alo, bh1);
                }
            }

            const float sc = 0.088388347648318447f;
            const bool domask = (jb * 64 + 63) > (qi * 128 + w * 16);
#pragma unroll
            for (int nf = 0; nf < 8; nf++)
#pragma unroll
                for (int e = 0; e < 4; e++) {
                    float s = sacc[nf][e] * sc;
                    if (domask) {
                        const int col = jb * 64 + nf * 8 + ((lane & 3) << 1) + (e & 1);
                        const int row = qi * 128 + w * 16 + (lane >> 2) + ((e >> 1) << 3);
                        if (col > row) s = -1e30f;
                    }
                    sacc[nf][e] = s;
                }

#pragma unroll
            for (int r2 = 0; r2 < 2; r2++) {
                float mx = -1e30f;
#pragma unroll
                for (int nf = 0; nf < 8; nf++)
                    mx = fmaxf(mx, fmaxf(sacc[nf][2 * r2], sacc[nf][2 * r2 + 1]));
                mx = fmaxf(mx, __shfl_xor_sync(0xffffffffu, mx, 1));
                mx = fmaxf(mx, __shfl_xor_sync(0xffffffffu, mx, 2));
                const float mn = fmaxf(m_i[r2], mx);
                const float alpha = __expf(m_i[r2] - mn);
                m_i[r2] = mn;
                float rs = 0.f;
#pragma unroll
                for (int nf = 0; nf < 8; nf++) {
                    float p0 = __expf(sacc[nf][2 * r2]     - mn);
                    float p1 = __expf(sacc[nf][2 * r2 + 1] - mn);
                    sacc[nf][2 * r2]     = p0;
                    sacc[nf][2 * r2 + 1] = p1;
                    rs += p0 + p1;
                }
                rs += __shfl_xor_sync(0xffffffffu, rs, 1);
                rs += __shfl_xor_sync(0xffffffffu, rs, 2);
                l_i[r2] = l_i[r2] * alpha + rs;
#pragma unroll
                for (int ndf = 0; ndf < 16; ndf++) {
                    oacc[ndf][2 * r2]     *= alpha;
                    oacc[ndf][2 * r2 + 1] *= alpha;
                }
            }

#pragma unroll
            for (int kk = 0; kk < 4; kk++) {
                uint32_t phi[4], plo[4];
                split_pair(sacc[2 * kk][0],     sacc[2 * kk][1],     phi[0], plo[0]);
                split_pair(sacc[2 * kk][2],     sacc[2 * kk][3],     phi[1], plo[1]);
                split_pair(sacc[2 * kk + 1][0], sacc[2 * kk + 1][1], phi[2], plo[2]);
                split_pair(sacc[2 * kk + 1][2], sacc[2 * kk + 1][3], phi[3], plo[3]);
#pragma unroll
                for (int ndg = 0; ndg < 8; ndg++) {
                    uint32_t t[4], u[4];
                    const uint32_t va = kb + 2 * AKV_BYTES +
                        ((uint32_t)(kk * 16) + lrow16) * 272 + ndg * 32 + lhalf;
                    ldsm_x4_trans(t, va);
                    ldsm_x4_trans(u, va + AKV_BYTES);
                    uint32_t bh0[2] = {t[0], t[1]}, bh1[2] = {t[2], t[3]};
                    uint32_t bl0[2] = {u[0], u[1]}, bl1[2] = {u[2], u[3]};
                    mma_bf16(oacc[ndg * 2],     phi, bh0);
                    mma_bf16(oacc[ndg * 2 + 1], phi, bh1);
                    mma_bf16(oacc[ndg * 2],     phi, bl0);
                    mma_bf16(oacc[ndg * 2 + 1], phi, bl1);
                    mma_bf16(oacc[ndg * 2],     plo, bh0);
                    mma_bf16(oacc[ndg * 2 + 1], plo, bh1);
                }
            }
        }
        __syncthreads();
    }

    const float i0 = 1.0f / l_i[0];
    const float i1 = 1.0f / l_i[1];
    const int row0 = qi * 128 + w * 16 + (lane >> 2);
    const size_t base0 = ((size_t)(b * S_) + row0) * (NH_ * D_) + h * D_ + (lane & 3) * 2;
    const size_t base1 = base0 + (size_t)8 * (NH_ * D_);
#pragma unroll
    for (int ndf = 0; ndf < 16; ndf++) {
        *reinterpret_cast<float2*>(ao + base0 + ndf * 8) =
            make_float2(oacc[ndf][0] * i0, oacc[ndf][1] * i0);
        *reinterpret_cast<float2*>(ao + base1 + ndf * 8) =
            make_float2(oacc[ndf][2] * i1, oacc[ndf][3] * i1);
    }
}

// ---------------------------------------------------------------------------
// Launch
// ---------------------------------------------------------------------------
extern "C" void kernel_launch(void* const* d_in, const int* in_sizes, int n_in,
                              void* d_out, int out_size)
{
    const float* hidden = (const float*)d_in[0];
    const float* cosb   = (const float*)d_in[1];
    const float* sinb   = (const float*)d_in[2];
    const float* Wq     = (const float*)d_in[3];
    const float* Wk     = (const float*)d_in[4];
    const float* Wv     = (const float*)d_in[5];
    const float* Wo     = (const float*)d_in[6];
    const float* qw     = (const float*)d_in[7];
    const float* kw     = (const float*)d_in[8];
    float* out = (float*)d_out;

    float* gao;
    cudaGetSymbolAddress((void**)&gao, g_ao);
    __nv_bfloat16 *qh, *ql, *kh, *kl, *vh, *vl;
    cudaGetSymbolAddress((void**)&qh, g_qh);
    cudaGetSymbolAddress((void**)&ql, g_ql);
    cudaGetSymbolAddress((void**)&kh, g_kh);
    cudaGetSymbolAddress((void**)&kl, g_kl);
    cudaGetSymbolAddress((void**)&vh, g_vh);
    cudaGetSymbolAddress((void**)&vl, g_vl);

    cudaFuncSetAttribute((const void*)gemm_qkv_fused,
                         cudaFuncAttributeMaxDynamicSharedMemorySize, GSMEM);
    cudaFuncSetAttribute((const void*)gemm_nt,
                         cudaFuncAttributeMaxDynamicSharedMemorySize, GSMEM);
    cudaFuncSetAttribute((const void*)attn_bf16_kernel,
                         cudaFuncAttributeMaxDynamicSharedMemorySize, ATTN_SMEM);

    // merged QKV projection + fused RMSNorm/RoPE/split epilogue
    gemm_qkv_fused<<<dim3(32, TOK / 128), 512, GSMEM>>>(
        hidden, Wq, Wk, Wv, cosb, sinb, qw, kw, qh, ql, kh, kl, vh, vl);

    // tensor-core causal flash attention
    attn_bf16_kernel<<<dim3(S_ / 128, NH_, B_), 256, ATTN_SMEM>>>(
        qh, ql, kh, kl, vh, vl, gao);

    // output projection
    gemm_nt<<<dim3(H_ / 128, TOK / 128), 512, GSMEM>>>(
        gao, Wo, out, TOK, H_, NH_ * D_);
}

// round 13
// speedup vs baseline: 2.3245x; 1.1958x over previous
#include <cuda_runtime.h>
#include <cuda_bf16.h>
#include <cuda_fp16.h>
#include <cstdint>

// ---------------------------------------------------------------------------
// Problem constants (B=2, S=2048, H=1024, NH=16, NKV=8, D=128)
// ---------------------------------------------------------------------------
constexpr int B_   = 2;
constexpr int S_   = 2048;
constexpr int H_   = 1024;
constexpr int NH_  = 16;
constexpr int NKV_ = 8;
constexpr int D_   = 128;
constexpr int TOK  = B_ * S_;            // 4096 tokens

// Scratch (device globals; no allocation allowed)
__device__ float g_ao[TOK * NH_ * D_];
// bf16 hi/lo split attention operands
__device__ __nv_bfloat16 g_qh[TOK * NH_  * D_], g_ql[TOK * NH_  * D_];
__device__ __nv_bfloat16 g_kh[TOK * NKV_ * D_], g_kl[TOK * NKV_ * D_];
__device__ __nv_bfloat16 g_vh[TOK * NKV_ * D_], g_vl[TOK * NKV_ * D_];

#define DEV_INLINE __device__ __forceinline__

// ---------------------------------------------------------------------------
// helpers
// ---------------------------------------------------------------------------
DEV_INLINE uint32_t cvt_bf16x2(float hi_elem, float lo_elem) {
    uint32_t r;
    asm("cvt.rn.bf16x2.f32 %0, %1, %2;" : "=r"(r) : "f"(hi_elem), "f"(lo_elem));
    return r;
}
// bf16 split (attention path)
DEV_INLINE void split_pair(float f0, float f1, uint32_t& hiw, uint32_t& low) {
    hiw = cvt_bf16x2(f1, f0);
    float h0 = __uint_as_float(hiw << 16);
    float h1 = __uint_as_float(hiw & 0xFFFF0000u);
    low = cvt_bf16x2(f1 - h1, f0 - h0);
}
// fp16 helpers (GEMM path)
DEV_INLINE uint32_t cvt_f16x2(float f0, float f1) {
    __half2 h = __float22half2_rn(make_float2(f0, f1));
    return *reinterpret_cast<uint32_t*>(&h);
}
DEV_INLINE void split_pair_f16(float f0, float f1, uint32_t& hiw, uint32_t& low) {
    __half2 h = __float22half2_rn(make_float2(f0, f1));
    hiw = *reinterpret_cast<uint32_t*>(&h);
    const float r0 = f0 - __half2float(__low2half(h));
    const float r1 = f1 - __half2float(__high2half(h));
    __half2 l = __float22half2_rn(make_float2(r0, r1));
    low = *reinterpret_cast<uint32_t*>(&l);
}
DEV_INLINE void ldsm_x4(uint32_t* r, uint32_t addr) {
    asm volatile("ldmatrix.sync.aligned.m8n8.x4.shared.b16 {%0,%1,%2,%3}, [%4];"
                 : "=r"(r[0]), "=r"(r[1]), "=r"(r[2]), "=r"(r[3]) : "r"(addr));
}
DEV_INLINE void ldsm_x4_trans(uint32_t* r, uint32_t addr) {
    asm volatile("ldmatrix.sync.aligned.m8n8.x4.trans.shared.b16 {%0,%1,%2,%3}, [%4];"
                 : "=r"(r[0]), "=r"(r[1]), "=r"(r[2]), "=r"(r[3]) : "r"(addr));
}
DEV_INLINE void mma_bf16(float* c, const uint32_t* a, const uint32_t* b) {
    asm volatile(
        "mma.sync.aligned.m16n8k16.row.col.f32.bf16.bf16.f32 "
        "{%0,%1,%2,%3}, {%4,%5,%6,%7}, {%8,%9}, {%0,%1,%2,%3};"
        : "+f"(c[0]), "+f"(c[1]), "+f"(c[2]), "+f"(c[3])
        : "r"(a[0]), "r"(a[1]), "r"(a[2]), "r"(a[3]), "r"(b[0]), "r"(b[1]));
}
DEV_INLINE void mma_f16(float* c, const uint32_t* a, const uint32_t* b) {
    asm volatile(
        "mma.sync.aligned.m16n8k16.row.col.f32.f16.f16.f32 "
        "{%0,%1,%2,%3}, {%4,%5,%6,%7}, {%8,%9}, {%0,%1,%2,%3};"
        : "+f"(c[0]), "+f"(c[1]), "+f"(c[2]), "+f"(c[3])
        : "r"(a[0]), "r"(a[1]), "r"(a[2]), "r"(a[3]), "r"(b[0]), "r"(b[1]));
}
DEV_INLINE uint32_t smem_u32(const void* p) {
    uint32_t a;
    asm("{ .reg .u64 t; cvta.to.shared.u64 t, %1; cvt.u32.u64 %0, t; }"
        : "=r"(a) : "l"(p));
    return a;
}
DEV_INLINE void cp16(uint32_t dst, const void* src) {
    asm volatile("cp.async.cg.shared.global [%0], [%1], 16;"
                 :: "r"(dst), "l"(src) : "memory");
}
DEV_INLINE void cp_commit() { asm volatile("cp.async.commit_group;" ::: "memory"); }
DEV_INLINE void cp_wait1()  { asm volatile("cp.async.wait_group 1;" ::: "memory"); }
DEV_INLINE void cp_wait0()  { asm volatile("cp.async.wait_group 0;" ::: "memory"); }

// ---------------------------------------------------------------------------
// fp16 two-product tensor-core NT GEMM mainloop.
// C = (Ah + Al) * B16, A Dekker-split to fp16 (rep err 2^-22), B single fp16
// (quantization 2^-11 -> ~2.8e-4 statistical rel err).
// 512 threads / 16 warps (4m x 4n, warp tile 32x32), CTA tile 128x128, BK=32,
// in-loop convert, double buffered. Result in Cacc[2][4][4].
// ---------------------------------------------------------------------------
constexpr int GMATB = 10240;           // 128 * 80 bytes per tile
constexpr int GBUFB = 3 * GMATB;       // 30720 per buffer: {Ah, Al, B}
constexpr int GSMEM = 2 * GBUFB;       // 61440
constexpr int QKV_SMEM = 128 * 132 * 4; // 67584 (epilogue stash) > GSMEM

DEV_INLINE void gemm_mainloop(const float* __restrict__ A, const float* __restrict__ Bm,
                              int K, int m0, int n0,
                              char* smem, uint32_t sb, float Cacc[2][4][4])
{
    const int tid  = threadIdx.x;
    const int lane = tid & 31;
    const int wid  = tid >> 5;          // 0..15
    const int wm   = wid & 3;           // 4 m-warps
    const int wn   = wid >> 2;          // 4 n-warps

    const int r = tid >> 2;             // 0..127
    const int q = tid & 3;              // quarter (8 f32)
    const float* Arow = A  + (size_t)(m0 + r) * K + q * 8;
    const float* Brow = Bm + (size_t)(n0 + r) * K + q * 8;

#pragma unroll
    for (int mi = 0; mi < 2; mi++)
#pragma unroll
        for (int nf = 0; nf < 4; nf++)
#pragma unroll
            for (int e = 0; e < 4; e++) Cacc[mi][nf][e] = 0.f;

    float4 ra[2], rb[2];
#pragma unroll
    for (int i = 0; i < 2; i++) {
        ra[i] = *reinterpret_cast<const float4*>(Arow + i * 4);
        rb[i] = *reinterpret_cast<const float4*>(Brow + i * 4);
    }

    const uint32_t lrow = (uint32_t)(lane & 15);
    const uint32_t lcol = (uint32_t)(lane >> 4) * 16;

    const int NC = K / 32;
    for (int c = 0; c < NC; c++) {
        char* bp = smem + (c & 1) * GBUFB;
        const uint32_t bufs = sb + (c & 1) * GBUFB;

        {   // convert + store this chunk: A split hi/lo, B single fp16
            const uint32_t off = (uint32_t)r * 80 + (uint32_t)q * 16;
            uint32_t h0, l0, h1, l1, h2, l2, h3, l3;
            split_pair_f16(ra[0].x, ra[0].y, h0, l0);
            split_pair_f16(ra[0].z, ra[0].w, h1, l1);
            split_pair_f16(ra[1].x, ra[1].y, h2, l2);
            split_pair_f16(ra[1].z, ra[1].w, h3, l3);
            *reinterpret_cast<uint4*>(bp + off)         = make_uint4(h0, h1, h2, h3);
            *reinterpret_cast<uint4*>(bp + GMATB + off) = make_uint4(l0, l1, l2, l3);
            const uint32_t b0 = cvt_f16x2(rb[0].x, rb[0].y);
            const uint32_t b1 = cvt_f16x2(rb[0].z, rb[0].w);
            const uint32_t b2 = cvt_f16x2(rb[1].x, rb[1].y);
            const uint32_t b3 = cvt_f16x2(rb[1].z, rb[1].w);
            *reinterpret_cast<uint4*>(bp + 2 * GMATB + off) = make_uint4(b0, b1, b2, b3);
        }
        __syncthreads();

        if (c + 1 < NC) {               // register prefetch of next chunk
            const int k0 = (c + 1) * 32;
#pragma unroll
            for (int i = 0; i < 2; i++) {
                ra[i] = *reinterpret_cast<const float4*>(Arow + k0 + i * 4);
                rb[i] = *reinterpret_cast<const float4*>(Brow + k0 + i * 4);
            }
        }

#pragma unroll
        for (int ks = 0; ks < 2; ks++) {
            uint32_t afrag[2][2][4];    // [sel hi/lo][mi][4]
            uint32_t bfr[4][2];         // [nf][2]
#pragma unroll
            for (int sel = 0; sel < 2; sel++)
#pragma unroll
                for (int mi = 0; mi < 2; mi++) {
                    const uint32_t addr = bufs + (uint32_t)sel * GMATB +
                        ((uint32_t)(wm * 32 + mi * 16) + lrow) * 80 +
                        (uint32_t)ks * 32 + lcol;
                    ldsm_x4(afrag[sel][mi], addr);
                }
#pragma unroll
            for (int ng = 0; ng < 2; ng++) {
                uint32_t t4[4];
                const uint32_t addr = bufs + 2 * GMATB +
                    ((uint32_t)(wn * 32 + ng * 16) + lrow) * 80 +
                    (uint32_t)ks * 32 + lcol;
                ldsm_x4(t4, addr);
                bfr[ng * 2][0]     = t4[0];
                bfr[ng * 2][1]     = t4[2];
                bfr[ng * 2 + 1][0] = t4[1];
                bfr[ng * 2 + 1][1] = t4[3];
            }
#pragma unroll
            for (int mi = 0; mi < 2; mi++)
#pragma unroll
                for (int nf = 0; nf < 4; nf++)
                    mma_f16(Cacc[mi][nf], afrag[0][mi], bfr[nf]);
#pragma unroll
            for (int mi = 0; mi < 2; mi++)
#pragma unroll
                for (int nf = 0; nf < 4; nf++)
                    mma_f16(Cacc[mi][nf], afrag[1][mi], bfr[nf]);
        }
        __syncthreads();
    }
}

// ---------------------------------------------------------------------------
// Merged QKV projection + FUSED RMSNorm/RoPE/bf16-split epilogue.
// grid (32 routed n-tiles, 32 m-tiles), 512 threads.
// ---------------------------------------------------------------------------
__global__ void __launch_bounds__(512, 1)
gemm_qkv_fused(const float* __restrict__ A,
               const float* __restrict__ Wq, const float* __restrict__ Wk,
               const float* __restrict__ Wv,
               const float* __restrict__ cosb, const float* __restrict__ sinb,
               const float* __restrict__ qw,   const float* __restrict__ kw,
               __nv_bfloat16* __restrict__ qh, __nv_bfloat16* __restrict__ ql,
               __nv_bfloat16* __restrict__ kh, __nv_bfloat16* __restrict__ kl,
               __nv_bfloat16* __restrict__ vh, __nv_bfloat16* __restrict__ vl)
{
    extern __shared__ char smem[];
    const uint32_t sb = smem_u32(smem);
    const int bx = blockIdx.x;
    const int m0 = blockIdx.y * 128;

    const float* Bm; int n0;
    if (bx < 16)      { Bm = Wq; n0 = bx * 128; }
    else if (bx < 24) { Bm = Wk; n0 = (bx - 16) * 128; }
    else              { Bm = Wv; n0 = (bx - 24) * 128; }

    float Cacc[2][4][4];
    gemm_mainloop(A, Bm, H_, m0, n0, smem, sb, Cacc);

    // ---- stash C tile to smem (post-final-sync; buffers dead) ----
    float* Cs = reinterpret_cast<float*>(smem);      // [128][132]
    {
        const int lane = threadIdx.x & 31;
        const int wid  = threadIdx.x >> 5;
        const int wm   = wid & 3;
        const int wn   = wid >> 2;
#pragma unroll
        for (int mi = 0; mi < 2; mi++) {
            const int row = wm * 32 + mi * 16 + (lane >> 2);
#pragma unroll
            for (int nf = 0; nf < 4; nf++) {
                const int col = wn * 32 + nf * 8 + (lane & 3) * 2;
                *reinterpret_cast<float2*>(&Cs[row * 132 + col]) =
                    make_float2(Cacc[mi][nf][0], Cacc[mi][nf][1]);
                *reinterpret_cast<float2*>(&Cs[(row + 8) * 132 + col]) =
                    make_float2(Cacc[mi][nf][2], Cacc[mi][nf][3]);
            }
        }
    }
    __syncthreads();

    // ---- fused norm phase: warp w handles rows w*8 .. w*8+7 ----
    const int lane = threadIdx.x & 31;
    const int wid  = threadIdx.x >> 5;
    const int l    = lane;

    if (bx >= 24) {                       // V: split only
        const int hv = bx - 24;
#pragma unroll
        for (int rr = 0; rr < 8; rr++) {
            const int row = wid * 8 + rr;
            const int token = m0 + row;
            const float4 x = *reinterpret_cast<const float4*>(&Cs[row * 132 + l * 4]);
            uint32_t h0, l0w, h1, l1w;
            split_pair(x.x, x.y, h0, l0w);
            split_pair(x.z, x.w, h1, l1w);
            const size_t base = (size_t)token * (NKV_ * D_) + hv * D_ + l * 4;
            *reinterpret_cast<uint2*>(vh + base) = make_uint2(h0, h1);
            *reinterpret_cast<uint2*>(vl + base) = make_uint2(l0w, l1w);
        }
        return;
    }

    const bool isq = (bx < 16);
    const float* w = isq ? qw : kw;
    __nv_bfloat16* oh = isq ? qh : kh;
    __nv_bfloat16* ol = isq ? ql : kl;
    const int hd  = isq ? bx : (bx - 16);
    const int hdn = isq ? (NH_ * D_) : (NKV_ * D_);
    const float4 wv = *reinterpret_cast<const float4*>(w + l * 4);
    const float sgn = (l < 16) ? -1.f : 1.f;

#pragma unroll
    for (int rr = 0; rr < 8; rr++) {
        const int row = wid * 8 + rr;
        const int token = m0 + row;
        const float4 x = *reinterpret_cast<const float4*>(&Cs[row * 132 + l * 4]);

        float ss = x.x * x.x + x.y * x.y + x.z * x.z + x.w * x.w;
#pragma unroll
        for (int off = 16; off >= 1; off >>= 1)
            ss += __shfl_xor_sync(0xffffffffu, ss, off);
        const float inv = rsqrtf(ss * (1.0f / 128.0f) + 1e-6f);

        const float4 cv = *reinterpret_cast<const float4*>(cosb + (size_t)token * D_ + l * 4);
        const float4 sv = *reinterpret_cast<const float4*>(sinb + (size_t)token * D_ + l * 4);

        const float z0 = x.x * wv.x, z1 = x.y * wv.y, z2 = x.z * wv.z, z3 = x.w * wv.w;
        const float p0 = __shfl_xor_sync(0xffffffffu, z0, 16);
        const float p1 = __shfl_xor_sync(0xffffffffu, z1, 16);
        const float p2 = __shfl_xor_sync(0xffffffffu, z2, 16);
        const float p3 = __shfl_xor_sync(0xffffffffu, z3, 16);

        const float y0 = (z0 * cv.x + sgn * p0 * sv.x) * inv;
        const float y1 = (z1 * cv.y + sgn * p1 * sv.y) * inv;
        const float y2 = (z2 * cv.z + sgn * p2 * sv.z) * inv;
        const float y3 = (z3 * cv.w + sgn * p3 * sv.w) * inv;

        uint32_t h0, l0w, h1, l1w;
        split_pair(y0, y1, h0, l0w);
        split_pair(y2, y3, h1, l1w);
        const size_t base = (size_t)token * hdn + hd * D_ + l * 4;
        *reinterpret_cast<uint2*>(oh + base) = make_uint2(h0, h1);
        *reinterpret_cast<uint2*>(ol + base) = make_uint2(l0w, l1w);
    }
}

// ---------------------------------------------------------------------------
// Generic GEMM (output projection), fp16 two-product
// ---------------------------------------------------------------------------
__global__ void __launch_bounds__(512, 1)
gemm_nt(const float* __restrict__ A, const float* __restrict__ Bm,
        float* __restrict__ C, int M, int N, int K)
{
    extern __shared__ char smem[];
    const uint32_t sb = smem_u32(smem);
    const int m0 = blockIdx.y * 128;
    const int n0 = blockIdx.x * 128;

    float Cacc[2][4][4];
    gemm_mainloop(A, Bm, K, m0, n0, smem, sb, Cacc);

    const int lane = threadIdx.x & 31;
    const int wid  = threadIdx.x >> 5;
    const int wm   = wid & 3;
    const int wn   = wid >> 2;
#pragma unroll
    for (int mi = 0; mi < 2; mi++) {
        const int row = m0 + wm * 32 + mi * 16 + (lane >> 2);
#pragma unroll
        for (int nf = 0; nf < 4; nf++) {
            const int col = n0 + wn * 32 + nf * 8 + (lane & 3) * 2;
            *reinterpret_cast<float2*>(C + (size_t)row * N + col) =
                make_float2(Cacc[mi][nf][0], Cacc[mi][nf][1]);
            *reinterpret_cast<float2*>(C + (size_t)(row + 8) * N + col) =
                make_float2(Cacc[mi][nf][2], Cacc[mi][nf][3]);
        }
    }
}

// ---------------------------------------------------------------------------
// Tensor-core flash attention (bf16x3, causal, GQA n_rep=2). Unchanged.
// BQ=128, BKV=64, D=128. 256 threads = 8 warps, warp w -> q rows w*16..+15.
// ---------------------------------------------------------------------------
constexpr int AQ_BYTES  = 128 * 272;                 // 34816
constexpr int AKV_BYTES = 64 * 272;                  // 17408
constexpr int ABUF0     = 2 * AQ_BYTES;              // 69632
constexpr int ABUFSZ    = 4 * AKV_BYTES;             // 69632
constexpr int ATTN_SMEM = ABUF0 + 2 * ABUFSZ;        // 208896

__global__ void __launch_bounds__(256, 1)
attn_bf16_kernel(const __nv_bfloat16* __restrict__ qh, const __nv_bfloat16* __restrict__ ql,
                 const __nv_bfloat16* __restrict__ kh, const __nv_bfloat16* __restrict__ kl,
                 const __nv_bfloat16* __restrict__ vh, const __nv_bfloat16* __restrict__ vl,
                 float* __restrict__ ao)
{
    extern __shared__ char smem[];
    const uint32_t sb = smem_u32(smem);

    const int tid  = threadIdx.x;
    const int lane = tid & 31;
    const int w    = tid >> 5;
    const int qi   = gridDim.x - 1 - blockIdx.x;
    const int h    = blockIdx.y;
    const int b    = blockIdx.z;
    const int kvh  = h >> 1;

#pragma unroll
    for (int i = 0; i < 8; i++) {
        const int idx = tid + i * 256;
        const int row = idx >> 4, ch = idx & 15;
        const size_t g = ((size_t)(b * S_) + qi * 128 + row) * (NH_ * D_) + h * D_ + ch * 8;
        cp16(sb + row * 272 + ch * 16,            qh + g);
        cp16(sb + AQ_BYTES + row * 272 + ch * 16, ql + g);
    }
    {
        const uint32_t buf = sb + ABUF0;
#pragma unroll
        for (int i = 0; i < 4; i++) {
            const int idx = tid + i * 256;
            const int row = idx >> 4, ch = idx & 15;
            const size_t g = ((size_t)(b * S_) + row) * (NKV_ * D_) + kvh * D_ + ch * 8;
            const uint32_t so = buf + row * 272 + ch * 16;
            cp16(so,                 kh + g);
            cp16(so + AKV_BYTES,     kl + g);
            cp16(so + 2 * AKV_BYTES, vh + g);
            cp16(so + 3 * AKV_BYTES, vl + g);
        }
    }
    cp_commit();

    float oacc[16][4];
#pragma unroll
    for (int i = 0; i < 16; i++)
#pragma unroll
        for (int e = 0; e < 4; e++) oacc[i][e] = 0.f;
    float m_i[2] = {-1e30f, -1e30f};
    float l_i[2] = {0.f, 0.f};

    const uint32_t lrow16 = (uint32_t)(lane & 15);
    const uint32_t lhalf  = (uint32_t)(lane >> 4) * 16;
    const int jmax = 2 * qi + 1;

    for (int jb = 0; jb <= jmax; jb++) {
        if (jb < jmax) {
            const uint32_t buf = sb + ABUF0 + ((jb + 1) & 1) * ABUFSZ;
#pragma unroll
            for (int i = 0; i < 4; i++) {
                const int idx = tid + i * 256;
                const int row = idx >> 4, ch = idx & 15;
                const size_t g = ((size_t)(b * S_) + (jb + 1) * 64 + row) * (NKV_ * D_) +
                                 kvh * D_ + ch * 8;
                const uint32_t so = buf + row * 272 + ch * 16;
                cp16(so,                 kh + g);
                cp16(so + AKV_BYTES,     kl + g);
                cp16(so + 2 * AKV_BYTES, vh + g);
                cp16(so + 3 * AKV_BYTES, vl + g);
            }
            cp_commit();
            cp_wait1();
        } else {
            cp_wait0();
        }
        __syncthreads();

        const uint32_t kb = sb + ABUF0 + (jb & 1) * ABUFSZ;
        const bool skip = (jb * 64) > (qi * 128 + w * 16 + 15);

        if (!skip) {
            float sacc[8][4];
#pragma unroll
            for (int i = 0; i < 8; i++)
#pragma unroll
                for (int e = 0; e < 4; e++) sacc[i][e] = 0.f;

            const uint32_t qbase = sb + ((uint32_t)(w * 16) + lrow16) * 272 + lhalf;
#pragma unroll
            for (int ks = 0; ks < 8; ks++) {
                uint32_t ahi[4], alo[4];
                ldsm_x4(ahi, qbase + ks * 32);
                ldsm_x4(alo, qbase + AQ_BYTES + ks * 32);
#pragma unroll
                for (int ng = 0; ng < 4; ng++) {
                    uint32_t t[4], u[4];
                    const uint32_t ka = kb + ((uint32_t)(ng * 16) + lrow16) * 272 + ks * 32 + lhalf;
                    ldsm_x4(t, ka);
                    ldsm_x4(u, ka + AKV_BYTES);
                    uint32_t bh0[2] = {t[0], t[2]}, bh1[2] = {t[1], t[3]};
                    uint32_t bl0[2] = {u[0], u[2]}, bl1[2] = {u[1], u[3]};
                    mma_bf16(sacc[ng * 2],     ahi, bh0);
                    mma_bf16(sacc[ng * 2 + 1], ahi, bh1);
                    mma_bf16(sacc[ng * 2],     ahi, bl0);
                    mma_bf16(sacc[ng * 2 + 1], ahi, bl1);
                    mma_bf16(sacc[ng * 2],     alo, bh0);
                    mma_bf16(sacc[ng * 2 + 1], alo, bh1);
                }
            }

            const float sc = 0.088388347648318447f;
            const bool domask = (jb * 64 + 63) > (qi * 128 + w * 16);
#pragma unroll
            for (int nf = 0; nf < 8; nf++)
#pragma unroll
                for (int e = 0; e < 4; e++) {
                    float s = sacc[nf][e] * sc;
                    if (domask) {
                        const int col = jb * 64 + nf * 8 + ((lane & 3) << 1) + (e & 1);
                        const int row = qi * 128 + w * 16 + (lane >> 2) + ((e >> 1) << 3);
                        if (col > row) s = -1e30f;
                    }
                    sacc[nf][e] = s;
                }

#pragma unroll
            for (int r2 = 0; r2 < 2; r2++) {
                float mx = -1e30f;
#pragma unroll
                for (int nf = 0; nf < 8; nf++)
                    mx = fmaxf(mx, fmaxf(sacc[nf][2 * r2], sacc[nf][2 * r2 + 1]));
                mx = fmaxf(mx, __shfl_xor_sync(0xffffffffu, mx, 1));
                mx = fmaxf(mx, __shfl_xor_sync(0xffffffffu, mx, 2));
                const float mn = fmaxf(m_i[r2], mx);
                const float alpha = __expf(m_i[r2] - mn);
                m_i[r2] = mn;
                float rs = 0.f;
#pragma unroll
                for (int nf = 0; nf < 8; nf++) {
                    float p0 = __expf(sacc[nf][2 * r2]     - mn);
                    float p1 = __expf(sacc[nf][2 * r2 + 1] - mn);
                    sacc[nf][2 * r2]     = p0;
                    sacc[nf][2 * r2 + 1] = p1;
                    rs += p0 + p1;
                }
                rs += __shfl_xor_sync(0xffffffffu, rs, 1);
                rs += __shfl_xor_sync(0xffffffffu, rs, 2);
                l_i[r2] = l_i[r2] * alpha + rs;
#pragma unroll
                for (int ndf = 0; ndf < 16; ndf++) {
                    oacc[ndf][2 * r2]     *= alpha;
                    oacc[ndf][2 * r2 + 1] *= alpha;
                }
            }

#pragma unroll
            for (int kk = 0; kk < 4; kk++) {
                uint32_t phi[4], plo[4];
                split_pair(sacc[2 * kk][0],     sacc[2 * kk][1],     phi[0], plo[0]);
                split_pair(sacc[2 * kk][2],     sacc[2 * kk][3],     phi[1], plo[1]);
                split_pair(sacc[2 * kk + 1][0], sacc[2 * kk + 1][1], phi[2], plo[2]);
                split_pair(sacc[2 * kk + 1][2], sacc[2 * kk + 1][3], phi[3], plo[3]);
#pragma unroll
                for (int ndg = 0; ndg < 8; ndg++) {
                    uint32_t t[4], u[4];
                    const uint32_t va = kb + 2 * AKV_BYTES +
                        ((uint32_t)(kk * 16) + lrow16) * 272 + ndg * 32 + lhalf;
                    ldsm_x4_trans(t, va);
                    ldsm_x4_trans(u, va + AKV_BYTES);
                    uint32_t bh0[2] = {t[0], t[1]}, bh1[2] = {t[2], t[3]};
                    uint32_t bl0[2] = {u[0], u[1]}, bl1[2] = {u[2], u[3]};
                    mma_bf16(oacc[ndg * 2],     phi, bh0);
                    mma_bf16(oacc[ndg * 2 + 1], phi, bh1);
                    mma_bf16(oacc[ndg * 2],     phi, bl0);
                    mma_bf16(oacc[ndg * 2 + 1], phi, bl1);
                    mma_bf16(oacc[ndg * 2],     plo, bh0);
                    mma_bf16(oacc[ndg * 2 + 1], plo, bh1);
                }
            }
        }
        __syncthreads();
    }

    const float i0 = 1.0f / l_i[0];
    const float i1 = 1.0f / l_i[1];
    const int row0 = qi * 128 + w * 16 + (lane >> 2);
    const size_t base0 = ((size_t)(b * S_) + row0) * (NH_ * D_) + h * D_ + (lane & 3) * 2;
    const size_t base1 = base0 + (size_t)8 * (NH_ * D_);
#pragma unroll
    for (int ndf = 0; ndf < 16; ndf++) {
        *reinterpret_cast<float2*>(ao + base0 + ndf * 8) =
            make_float2(oacc[ndf][0] * i0, oacc[ndf][1] * i0);
        *reinterpret_cast<float2*>(ao + base1 + ndf * 8) =
            make_float2(oacc[ndf][2] * i1, oacc[ndf][3] * i1);
    }
}

// ---------------------------------------------------------------------------
// Launch
// ---------------------------------------------------------------------------
extern "C" void kernel_launch(void* const* d_in, const int* in_sizes, int n_in,
                              void* d_out, int out_size)
{
    const float* hidden = (const float*)d_in[0];
    const float* cosb   = (const float*)d_in[1];
    const float* sinb   = (const float*)d_in[2];
    const float* Wq     = (const float*)d_in[3];
    const float* Wk     = (const float*)d_in[4];
    const float* Wv     = (const float*)d_in[5];
    const float* Wo     = (const float*)d_in[6];
    const float* qw     = (const float*)d_in[7];
    const float* kw     = (const float*)d_in[8];
    float* out = (float*)d_out;

    float* gao;
    cudaGetSymbolAddress((void**)&gao, g_ao);
    __nv_bfloat16 *qh, *ql, *kh, *kl, *vh, *vl;
    cudaGetSymbolAddress((void**)&qh, g_qh);
    cudaGetSymbolAddress((void**)&ql, g_ql);
    cudaGetSymbolAddress((void**)&kh, g_kh);
    cudaGetSymbolAddress((void**)&kl, g_kl);
    cudaGetSymbolAddress((void**)&vh, g_vh);
    cudaGetSymbolAddress((void**)&vl, g_vl);

    cudaFuncSetAttribute((const void*)gemm_qkv_fused,
                         cudaFuncAttributeMaxDynamicSharedMemorySize, QKV_SMEM);
    cudaFuncSetAttribute((const void*)gemm_nt,
                         cudaFuncAttributeMaxDynamicSharedMemorySize, GSMEM);
    cudaFuncSetAttribute((const void*)attn_bf16_kernel,
                         cudaFuncAttributeMaxDynamicSharedMemorySize, ATTN_SMEM);

    // merged QKV projection (fp16 two-product) + fused RMSNorm/RoPE/split
    gemm_qkv_fused<<<dim3(32, TOK / 128), 512, QKV_SMEM>>>(
        hidden, Wq, Wk, Wv, cosb, sinb, qw, kw, qh, ql, kh, kl, vh, vl);

    // tensor-core causal flash attention (bf16x3, unchanged)
    attn_bf16_kernel<<<dim3(S_ / 128, NH_, B_), 256, ATTN_SMEM>>>(
        qh, ql, kh, kl, vh, vl, gao);

    // output projection (fp16 two-product)
    gemm_nt<<<dim3(H_ / 128, TOK / 128), 512, GSMEM>>>(
        gao, Wo, out, TOK, H_, NH_ * D_);
}

// round 14
// speedup vs baseline: 2.6334x; 1.1329x over previous
#include <cuda_runtime.h>
#include <cuda_fp16.h>
#include <cstdint>

// ---------------------------------------------------------------------------
// Problem constants (B=2, S=2048, H=1024, NH=16, NKV=8, D=128)
// ---------------------------------------------------------------------------
constexpr int B_   = 2;
constexpr int S_   = 2048;
constexpr int H_   = 1024;
constexpr int NH_  = 16;
constexpr int NKV_ = 8;
constexpr int D_   = 128;
constexpr int TOK  = B_ * S_;            // 4096 tokens

// Scratch (device globals; no allocation allowed)
__device__ float g_ao[TOK * NH_ * D_];
// fp16 attention operands: Q split hi/lo, K and V single
__device__ __half g_qh [TOK * NH_  * D_], g_ql[TOK * NH_ * D_];
__device__ __half g_k16[TOK * NKV_ * D_];
__device__ __half g_v16[TOK * NKV_ * D_];

#define DEV_INLINE __device__ __forceinline__

// ---------------------------------------------------------------------------
// helpers
// ---------------------------------------------------------------------------
DEV_INLINE uint32_t cvt_f16x2(float f0, float f1) {
    __half2 h = __float22half2_rn(make_float2(f0, f1));
    return *reinterpret_cast<uint32_t*>(&h);
}
// Dekker split two fp32 into fp16 hi-pair + lo-pair (f0 -> low lane)
DEV_INLINE void split_pair_f16(float f0, float f1, uint32_t& hiw, uint32_t& low) {
    __half2 h = __float22half2_rn(make_float2(f0, f1));
    hiw = *reinterpret_cast<uint32_t*>(&h);
    const float r0 = f0 - __half2float(__low2half(h));
    const float r1 = f1 - __half2float(__high2half(h));
    __half2 l = __float22half2_rn(make_float2(r0, r1));
    low = *reinterpret_cast<uint32_t*>(&l);
}
DEV_INLINE void ldsm_x4(uint32_t* r, uint32_t addr) {
    asm volatile("ldmatrix.sync.aligned.m8n8.x4.shared.b16 {%0,%1,%2,%3}, [%4];"
                 : "=r"(r[0]), "=r"(r[1]), "=r"(r[2]), "=r"(r[3]) : "r"(addr));
}
DEV_INLINE void ldsm_x4_trans(uint32_t* r, uint32_t addr) {
    asm volatile("ldmatrix.sync.aligned.m8n8.x4.trans.shared.b16 {%0,%1,%2,%3}, [%4];"
                 : "=r"(r[0]), "=r"(r[1]), "=r"(r[2]), "=r"(r[3]) : "r"(addr));
}
DEV_INLINE void mma_f16(float* c, const uint32_t* a, const uint32_t* b) {
    asm volatile(
        "mma.sync.aligned.m16n8k16.row.col.f32.f16.f16.f32 "
        "{%0,%1,%2,%3}, {%4,%5,%6,%7}, {%8,%9}, {%0,%1,%2,%3};"
        : "+f"(c[0]), "+f"(c[1]), "+f"(c[2]), "+f"(c[3])
        : "r"(a[0]), "r"(a[1]), "r"(a[2]), "r"(a[3]), "r"(b[0]), "r"(b[1]));
}
DEV_INLINE uint32_t smem_u32(const void* p) {
    uint32_t a;
    asm("{ .reg .u64 t; cvta.to.shared.u64 t, %1; cvt.u32.u64 %0, t; }"
        : "=r"(a) : "l"(p));
    return a;
}
DEV_INLINE void cp16(uint32_t dst, const void* src) {
    asm volatile("cp.async.cg.shared.global [%0], [%1], 16;"
                 :: "r"(dst), "l"(src) : "memory");
}
DEV_INLINE void cp_commit() { asm volatile("cp.async.commit_group;" ::: "memory"); }
DEV_INLINE void cp_wait1()  { asm volatile("cp.async.wait_group 1;" ::: "memory"); }
DEV_INLINE void cp_wait0()  { asm volatile("cp.async.wait_group 0;" ::: "memory"); }

// ---------------------------------------------------------------------------
// fp16 two-product tensor-core NT GEMM mainloop (round-13 proven).
// C = (Ah + Al) * B16. 512 threads / 16 warps (4m x 4n, warp tile 32x32),
// CTA tile 128x128, BK=32, in-loop convert, double buffered.
// ---------------------------------------------------------------------------
constexpr int GMATB = 10240;           // 128 * 80 bytes per tile
constexpr int GBUFB = 3 * GMATB;       // 30720 per buffer: {Ah, Al, B}
constexpr int GSMEM = 2 * GBUFB;       // 61440
constexpr int QKV_SMEM = 128 * 132 * 4; // 67584 (epilogue stash) > GSMEM

DEV_INLINE void gemm_mainloop(const float* __restrict__ A, const float* __restrict__ Bm,
                              int K, int m0, int n0,
                              char* smem, uint32_t sb, float Cacc[2][4][4])
{
    const int tid  = threadIdx.x;
    const int lane = tid & 31;
    const int wid  = tid >> 5;          // 0..15
    const int wm   = wid & 3;
    const int wn   = wid >> 2;

    const int r = tid >> 2;             // 0..127
    const int q = tid & 3;              // quarter (8 f32)
    const float* Arow = A  + (size_t)(m0 + r) * K + q * 8;
    const float* Brow = Bm + (size_t)(n0 + r) * K + q * 8;

#pragma unroll
    for (int mi = 0; mi < 2; mi++)
#pragma unroll
        for (int nf = 0; nf < 4; nf++)
#pragma unroll
            for (int e = 0; e < 4; e++) Cacc[mi][nf][e] = 0.f;

    float4 ra[2], rb[2];
#pragma unroll
    for (int i = 0; i < 2; i++) {
        ra[i] = *reinterpret_cast<const float4*>(Arow + i * 4);
        rb[i] = *reinterpret_cast<const float4*>(Brow + i * 4);
    }

    const uint32_t lrow = (uint32_t)(lane & 15);
    const uint32_t lcol = (uint32_t)(lane >> 4) * 16;

    const int NC = K / 32;
    for (int c = 0; c < NC; c++) {
        char* bp = smem + (c & 1) * GBUFB;
        const uint32_t bufs = sb + (c & 1) * GBUFB;

        {   // convert + store: A split hi/lo, B single fp16
            const uint32_t off = (uint32_t)r * 80 + (uint32_t)q * 16;
            uint32_t h0, l0, h1, l1, h2, l2, h3, l3;
            split_pair_f16(ra[0].x, ra[0].y, h0, l0);
            split_pair_f16(ra[0].z, ra[0].w, h1, l1);
            split_pair_f16(ra[1].x, ra[1].y, h2, l2);
            split_pair_f16(ra[1].z, ra[1].w, h3, l3);
            *reinterpret_cast<uint4*>(bp + off)         = make_uint4(h0, h1, h2, h3);
            *reinterpret_cast<uint4*>(bp + GMATB + off) = make_uint4(l0, l1, l2, l3);
            const uint32_t b0 = cvt_f16x2(rb[0].x, rb[0].y);
            const uint32_t b1 = cvt_f16x2(rb[0].z, rb[0].w);
            const uint32_t b2 = cvt_f16x2(rb[1].x, rb[1].y);
            const uint32_t b3 = cvt_f16x2(rb[1].z, rb[1].w);
            *reinterpret_cast<uint4*>(bp + 2 * GMATB + off) = make_uint4(b0, b1, b2, b3);
        }
        __syncthreads();

        if (c + 1 < NC) {
            const int k0 = (c + 1) * 32;
#pragma unroll
            for (int i = 0; i < 2; i++) {
                ra[i] = *reinterpret_cast<const float4*>(Arow + k0 + i * 4);
                rb[i] = *reinterpret_cast<const float4*>(Brow + k0 + i * 4);
            }
        }

#pragma unroll
        for (int ks = 0; ks < 2; ks++) {
            uint32_t afrag[2][2][4];
            uint32_t bfr[4][2];
#pragma unroll
            for (int sel = 0; sel < 2; sel++)
#pragma unroll
                for (int mi = 0; mi < 2; mi++) {
                    const uint32_t addr = bufs + (uint32_t)sel * GMATB +
                        ((uint32_t)(wm * 32 + mi * 16) + lrow) * 80 +
                        (uint32_t)ks * 32 + lcol;
                    ldsm_x4(afrag[sel][mi], addr);
                }
#pragma unroll
            for (int ng = 0; ng < 2; ng++) {
                uint32_t t4[4];
                const uint32_t addr = bufs + 2 * GMATB +
                    ((uint32_t)(wn * 32 + ng * 16) + lrow) * 80 +
                    (uint32_t)ks * 32 + lcol;
                ldsm_x4(t4, addr);
                bfr[ng * 2][0]     = t4[0];
                bfr[ng * 2][1]     = t4[2];
                bfr[ng * 2 + 1][0] = t4[1];
                bfr[ng * 2 + 1][1] = t4[3];
            }
#pragma unroll
            for (int mi = 0; mi < 2; mi++)
#pragma unroll
                for (int nf = 0; nf < 4; nf++)
                    mma_f16(Cacc[mi][nf], afrag[0][mi], bfr[nf]);
#pragma unroll
            for (int mi = 0; mi < 2; mi++)
#pragma unroll
                for (int nf = 0; nf < 4; nf++)
                    mma_f16(Cacc[mi][nf], afrag[1][mi], bfr[nf]);
        }
        __syncthreads();
    }
}

// ---------------------------------------------------------------------------
// Merged QKV projection + FUSED RMSNorm/RoPE epilogue.
// Q -> fp16 hi/lo; K, V -> single fp16.
// ---------------------------------------------------------------------------
__global__ void __launch_bounds__(512, 1)
gemm_qkv_fused(const float* __restrict__ A,
               const float* __restrict__ Wq, const float* __restrict__ Wk,
               const float* __restrict__ Wv,
               const float* __restrict__ cosb, const float* __restrict__ sinb,
               const float* __restrict__ qw,   const float* __restrict__ kw,
               __half* __restrict__ qh, __half* __restrict__ ql,
               __half* __restrict__ k16, __half* __restrict__ v16)
{
    extern __shared__ char smem[];
    const uint32_t sb = smem_u32(smem);
    const int bx = blockIdx.x;
    const int m0 = blockIdx.y * 128;

    const float* Bm; int n0;
    if (bx < 16)      { Bm = Wq; n0 = bx * 128; }
    else if (bx < 24) { Bm = Wk; n0 = (bx - 16) * 128; }
    else              { Bm = Wv; n0 = (bx - 24) * 128; }

    float Cacc[2][4][4];
    gemm_mainloop(A, Bm, H_, m0, n0, smem, sb, Cacc);

    // ---- stash C tile to smem (post-final-sync; buffers dead) ----
    float* Cs = reinterpret_cast<float*>(smem);      // [128][132]
    {
        const int lane = threadIdx.x & 31;
        const int wid  = threadIdx.x >> 5;
        const int wm   = wid & 3;
        const int wn   = wid >> 2;
#pragma unroll
        for (int mi = 0; mi < 2; mi++) {
            const int row = wm * 32 + mi * 16 + (lane >> 2);
#pragma unroll
            for (int nf = 0; nf < 4; nf++) {
                const int col = wn * 32 + nf * 8 + (lane & 3) * 2;
                *reinterpret_cast<float2*>(&Cs[row * 132 + col]) =
                    make_float2(Cacc[mi][nf][0], Cacc[mi][nf][1]);
                *reinterpret_cast<float2*>(&Cs[(row + 8) * 132 + col]) =
                    make_float2(Cacc[mi][nf][2], Cacc[mi][nf][3]);
            }
        }
    }
    __syncthreads();

    const int lane = threadIdx.x & 31;
    const int wid  = threadIdx.x >> 5;
    const int l    = lane;

    if (bx >= 24) {                       // V: single fp16
        const int hv = bx - 24;
#pragma unroll
        for (int rr = 0; rr < 8; rr++) {
            const int row = wid * 8 + rr;
            const int token = m0 + row;
            const float4 x = *reinterpret_cast<const float4*>(&Cs[row * 132 + l * 4]);
            const uint32_t a0 = cvt_f16x2(x.x, x.y);
            const uint32_t a1 = cvt_f16x2(x.z, x.w);
            const size_t base = (size_t)token * (NKV_ * D_) + hv * D_ + l * 4;
            *reinterpret_cast<uint2*>(v16 + base) = make_uint2(a0, a1);
        }
        return;
    }

    const bool isq = (bx < 16);
    const float* w = isq ? qw : kw;
    const int hd  = isq ? bx : (bx - 16);
    const int hdn = isq ? (NH_ * D_) : (NKV_ * D_);
    const float4 wv = *reinterpret_cast<const float4*>(w + l * 4);
    const float sgn = (l < 16) ? -1.f : 1.f;

#pragma unroll
    for (int rr = 0; rr < 8; rr++) {
        const int row = wid * 8 + rr;
        const int token = m0 + row;
        const float4 x = *reinterpret_cast<const float4*>(&Cs[row * 132 + l * 4]);

        float ss = x.x * x.x + x.y * x.y + x.z * x.z + x.w * x.w;
#pragma unroll
        for (int off = 16; off >= 1; off >>= 1)
            ss += __shfl_xor_sync(0xffffffffu, ss, off);
        const float inv = rsqrtf(ss * (1.0f / 128.0f) + 1e-6f);

        const float4 cv = *reinterpret_cast<const float4*>(cosb + (size_t)token * D_ + l * 4);
        const float4 sv = *reinterpret_cast<const float4*>(sinb + (size_t)token * D_ + l * 4);

        const float z0 = x.x * wv.x, z1 = x.y * wv.y, z2 = x.z * wv.z, z3 = x.w * wv.w;
        const float p0 = __shfl_xor_sync(0xffffffffu, z0, 16);
        const float p1 = __shfl_xor_sync(0xffffffffu, z1, 16);
        const float p2 = __shfl_xor_sync(0xffffffffu, z2, 16);
        const float p3 = __shfl_xor_sync(0xffffffffu, z3, 16);

        const float y0 = (z0 * cv.x + sgn * p0 * sv.x) * inv;
        const float y1 = (z1 * cv.y + sgn * p1 * sv.y) * inv;
        const float y2 = (z2 * cv.z + sgn * p2 * sv.z) * inv;
        const float y3 = (z3 * cv.w + sgn * p3 * sv.w) * inv;

        const size_t base = (size_t)token * hdn + hd * D_ + l * 4;
        if (isq) {                        // Q: fp16 hi/lo split
            uint32_t h0, l0w, h1, l1w;
            split_pair_f16(y0, y1, h0, l0w);
            split_pair_f16(y2, y3, h1, l1w);
            *reinterpret_cast<uint2*>(qh + base) = make_uint2(h0, h1);
            *reinterpret_cast<uint2*>(ql + base) = make_uint2(l0w, l1w);
        } else {                          // K: single fp16
            const uint32_t a0 = cvt_f16x2(y0, y1);
            const uint32_t a1 = cvt_f16x2(y2, y3);
            *reinterpret_cast<uint2*>(k16 + base) = make_uint2(a0, a1);
        }
    }
}

// ---------------------------------------------------------------------------
// Generic GEMM (output projection), fp16 two-product
// ---------------------------------------------------------------------------
__global__ void __launch_bounds__(512, 1)
gemm_nt(const float* __restrict__ A, const float* __restrict__ Bm,
        float* __restrict__ C, int M, int N, int K)
{
    extern __shared__ char smem[];
    const uint32_t sb = smem_u32(smem);
    const int m0 = blockIdx.y * 128;
    const int n0 = blockIdx.x * 128;

    float Cacc[2][4][4];
    gemm_mainloop(A, Bm, K, m0, n0, smem, sb, Cacc);

    const int lane = threadIdx.x & 31;
    const int wid  = threadIdx.x >> 5;
    const int wm   = wid & 3;
    const int wn   = wid >> 2;
#pragma unroll
    for (int mi = 0; mi < 2; mi++) {
        const int row = m0 + wm * 32 + mi * 16 + (lane >> 2);
#pragma unroll
        for (int nf = 0; nf < 4; nf++) {
            const int col = n0 + wn * 32 + nf * 8 + (lane & 3) * 2;
            *reinterpret_cast<float2*>(C + (size_t)row * N + col) =
                make_float2(Cacc[mi][nf][0], Cacc[mi][nf][1]);
            *reinterpret_cast<float2*>(C + (size_t)(row + 8) * N + col) =
                make_float2(Cacc[mi][nf][2], Cacc[mi][nf][3]);
        }
    }
}

// ---------------------------------------------------------------------------
// Tensor-core flash attention (fp16 two-product, causal, GQA n_rep=2).
// BQ=128, BKV=64, D=128. 256 threads = 8 warps, warp w -> q rows w*16..+15.
// SMEM: Qhi,Qlo (128x272B each) + double-buffered {K16,V16} (64x272B each)
// ---------------------------------------------------------------------------
constexpr int AQ_BYTES  = 128 * 272;                 // 34816
constexpr int AKV_BYTES = 64 * 272;                  // 17408
constexpr int ABUF0     = 2 * AQ_BYTES;              // 69632
constexpr int ABUFSZ    = 2 * AKV_BYTES;             // 34816
constexpr int ATTN_SMEM = ABUF0 + 2 * ABUFSZ;        // 139264

__global__ void __launch_bounds__(256, 1)
attn_f16_kernel(const __half* __restrict__ qh, const __half* __restrict__ ql,
                const __half* __restrict__ k16, const __half* __restrict__ v16,
                float* __restrict__ ao)
{
    extern __shared__ char smem[];
    const uint32_t sb = smem_u32(smem);

    const int tid  = threadIdx.x;
    const int lane = tid & 31;
    const int w    = tid >> 5;
    const int qi   = gridDim.x - 1 - blockIdx.x;
    const int h    = blockIdx.y;
    const int b    = blockIdx.z;
    const int kvh  = h >> 1;

#pragma unroll
    for (int i = 0; i < 8; i++) {
        const int idx = tid + i * 256;
        const int row = idx >> 4, ch = idx & 15;
        const size_t g = ((size_t)(b * S_) + qi * 128 + row) * (NH_ * D_) + h * D_ + ch * 8;
        cp16(sb + row * 272 + ch * 16,            qh + g);
        cp16(sb + AQ_BYTES + row * 272 + ch * 16, ql + g);
    }
    {
        const uint32_t buf = sb + ABUF0;
#pragma unroll
        for (int i = 0; i < 4; i++) {
            const int idx = tid + i * 256;
            const int row = idx >> 4, ch = idx & 15;
            const size_t g = ((size_t)(b * S_) + row) * (NKV_ * D_) + kvh * D_ + ch * 8;
            const uint32_t so = buf + row * 272 + ch * 16;
            cp16(so,             k16 + g);
            cp16(so + AKV_BYTES, v16 + g);
        }
    }
    cp_commit();

    float oacc[16][4];
#pragma unroll
    for (int i = 0; i < 16; i++)
#pragma unroll
        for (int e = 0; e < 4; e++) oacc[i][e] = 0.f;
    float m_i[2] = {-1e30f, -1e30f};
    float l_i[2] = {0.f, 0.f};

    const uint32_t lrow16 = (uint32_t)(lane & 15);
    const uint32_t lhalf  = (uint32_t)(lane >> 4) * 16;
    const int jmax = 2 * qi + 1;

    for (int jb = 0; jb <= jmax; jb++) {
        if (jb < jmax) {
            const uint32_t buf = sb + ABUF0 + ((jb + 1) & 1) * ABUFSZ;
#pragma unroll
            for (int i = 0; i < 4; i++) {
                const int idx = tid + i * 256;
                const int row = idx >> 4, ch = idx & 15;
                const size_t g = ((size_t)(b * S_) + (jb + 1) * 64 + row) * (NKV_ * D_) +
                                 kvh * D_ + ch * 8;
                const uint32_t so = buf + row * 272 + ch * 16;
                cp16(so,             k16 + g);
                cp16(so + AKV_BYTES, v16 + g);
            }
            cp_commit();
            cp_wait1();
        } else {
            cp_wait0();
        }
        __syncthreads();

        const uint32_t kb = sb + ABUF0 + (jb & 1) * ABUFSZ;
        const bool skip = (jb * 64) > (qi * 128 + w * 16 + 15);

        if (!skip) {
            // ---- S = (Qh + Ql) K16 ----
            float sacc[8][4];
#pragma unroll
            for (int i = 0; i < 8; i++)
#pragma unroll
                for (int e = 0; e < 4; e++) sacc[i][e] = 0.f;

            const uint32_t qbase = sb + ((uint32_t)(w * 16) + lrow16) * 272 + lhalf;
#pragma unroll
            for (int ks = 0; ks < 8; ks++) {
                uint32_t ahi[4], alo[4];
                ldsm_x4(ahi, qbase + ks * 32);
                ldsm_x4(alo, qbase + AQ_BYTES + ks * 32);
#pragma unroll
                for (int ng = 0; ng < 4; ng++) {
                    uint32_t t[4];
                    const uint32_t ka = kb + ((uint32_t)(ng * 16) + lrow16) * 272 + ks * 32 + lhalf;
                    ldsm_x4(t, ka);
                    uint32_t bh0[2] = {t[0], t[2]}, bh1[2] = {t[1], t[3]};
                    mma_f16(sacc[ng * 2],     ahi, bh0);
                    mma_f16(sacc[ng * 2 + 1], ahi, bh1);
                    mma_f16(sacc[ng * 2],     alo, bh0);
                    mma_f16(sacc[ng * 2 + 1], alo, bh1);
                }
            }

            const float sc = 0.088388347648318447f;
            const bool domask = (jb * 64 + 63) > (qi * 128 + w * 16);
#pragma unroll
            for (int nf = 0; nf < 8; nf++)
#pragma unroll
                for (int e = 0; e < 4; e++) {
                    float s = sacc[nf][e] * sc;
                    if (domask) {
                        const int col = jb * 64 + nf * 8 + ((lane & 3) << 1) + (e & 1);
                        const int row = qi * 128 + w * 16 + (lane >> 2) + ((e >> 1) << 3);
                        if (col > row) s = -1e30f;
                    }
                    sacc[nf][e] = s;
                }

#pragma unroll
            for (int r2 = 0; r2 < 2; r2++) {
                float mx = -1e30f;
#pragma unroll
                for (int nf = 0; nf < 8; nf++)
                    mx = fmaxf(mx, fmaxf(sacc[nf][2 * r2], sacc[nf][2 * r2 + 1]));
                mx = fmaxf(mx, __shfl_xor_sync(0xffffffffu, mx, 1));
                mx = fmaxf(mx, __shfl_xor_sync(0xffffffffu, mx, 2));
                const float mn = fmaxf(m_i[r2], mx);
                const float alpha = __expf(m_i[r2] - mn);
                m_i[r2] = mn;
                float rs = 0.f;
#pragma unroll
                for (int nf = 0; nf < 8; nf++) {
                    float p0 = __expf(sacc[nf][2 * r2]     - mn);
                    float p1 = __expf(sacc[nf][2 * r2 + 1] - mn);
                    sacc[nf][2 * r2]     = p0;
                    sacc[nf][2 * r2 + 1] = p1;
                    rs += p0 + p1;
                }
                rs += __shfl_xor_sync(0xffffffffu, rs, 1);
                rs += __shfl_xor_sync(0xffffffffu, rs, 2);
                l_i[r2] = l_i[r2] * alpha + rs;
#pragma unroll
                for (int ndf = 0; ndf < 16; ndf++) {
                    oacc[ndf][2 * r2]     *= alpha;
                    oacc[ndf][2 * r2 + 1] *= alpha;
                }
            }

            // ---- O += (Ph + Pl) V16 ----
#pragma unroll
            for (int kk = 0; kk < 4; kk++) {
                uint32_t phi[4], plo[4];
                split_pair_f16(sacc[2 * kk][0],     sacc[2 * kk][1],     phi[0], plo[0]);
                split_pair_f16(sacc[2 * kk][2],     sacc[2 * kk][3],     phi[1], plo[1]);
                split_pair_f16(sacc[2 * kk + 1][0], sacc[2 * kk + 1][1], phi[2], plo[2]);
                split_pair_f16(sacc[2 * kk + 1][2], sacc[2 * kk + 1][3], phi[3], plo[3]);
#pragma unroll
                for (int ndg = 0; ndg < 8; ndg++) {
                    uint32_t t[4];
                    const uint32_t va = kb + AKV_BYTES +
                        ((uint32_t)(kk * 16) + lrow16) * 272 + ndg * 32 + lhalf;
                    ldsm_x4_trans(t, va);
                    uint32_t bh0[2] = {t[0], t[1]}, bh1[2] = {t[2], t[3]};
                    mma_f16(oacc[ndg * 2],     phi, bh0);
                    mma_f16(oacc[ndg * 2 + 1], phi, bh1);
                    mma_f16(oacc[ndg * 2],     plo, bh0);
                    mma_f16(oacc[ndg * 2 + 1], plo, bh1);
                }
            }
        }
        __syncthreads();
    }

    const float i0 = 1.0f / l_i[0];
    const float i1 = 1.0f / l_i[1];
    const int row0 = qi * 128 + w * 16 + (lane >> 2);
    const size_t base0 = ((size_t)(b * S_) + row0) * (NH_ * D_) + h * D_ + (lane & 3) * 2;
    const size_t base1 = base0 + (size_t)8 * (NH_ * D_);
#pragma unroll
    for (int ndf = 0; ndf < 16; ndf++) {
        *reinterpret_cast<float2*>(ao + base0 + ndf * 8) =
            make_float2(oacc[ndf][0] * i0, oacc[ndf][1] * i0);
        *reinterpret_cast<float2*>(ao + base1 + ndf * 8) =
            make_float2(oacc[ndf][2] * i1, oacc[ndf][3] * i1);
    }
}

// ---------------------------------------------------------------------------
// Launch
// ---------------------------------------------------------------------------
extern "C" void kernel_launch(void* const* d_in, const int* in_sizes, int n_in,
                              void* d_out, int out_size)
{
    const float* hidden = (const float*)d_in[0];
    const float* cosb   = (const float*)d_in[1];
    const float* sinb   = (const float*)d_in[2];
    const float* Wq     = (const float*)d_in[3];
    const float* Wk     = (const float*)d_in[4];
    const float* Wv     = (const float*)d_in[5];
    const float* Wo     = (const float*)d_in[6];
    const float* qw     = (const float*)d_in[7];
    const float* kw     = (const float*)d_in[8];
    float* out = (float*)d_out;

    float* gao;
    cudaGetSymbolAddress((void**)&gao, g_ao);
    __half *qh, *ql, *k16, *v16;
    cudaGetSymbolAddress((void**)&qh,  g_qh);
    cudaGetSymbolAddress((void**)&ql,  g_ql);
    cudaGetSymbolAddress((void**)&k16, g_k16);
    cudaGetSymbolAddress((void**)&v16, g_v16);

    cudaFuncSetAttribute((const void*)gemm_qkv_fused,
                         cudaFuncAttributeMaxDynamicSharedMemorySize, QKV_SMEM);
    cudaFuncSetAttribute((const void*)gemm_nt,
                         cudaFuncAttributeMaxDynamicSharedMemorySize, GSMEM);
    cudaFuncSetAttribute((const void*)attn_f16_kernel,
                         cudaFuncAttributeMaxDynamicSharedMemorySize, ATTN_SMEM);

    // merged QKV projection (fp16 two-product) + fused RMSNorm/RoPE epilogue
    gemm_qkv_fused<<<dim3(32, TOK / 128), 512, QKV_SMEM>>>(
        hidden, Wq, Wk, Wv, cosb, sinb, qw, kw, qh, ql, k16, v16);

    // tensor-core causal flash attention (fp16 two-product)
    attn_f16_kernel<<<dim3(S_ / 128, NH_, B_), 256, ATTN_SMEM>>>(
        qh, ql, k16, v16, gao);

    // output projection (fp16 two-product)
    gemm_nt<<<dim3(H_ / 128, TOK / 128), 512, GSMEM>>>(
        gao, Wo, out, TOK, H_, NH_ * D_);
}

// round 15
// speedup vs baseline: 2.8629x; 1.0872x over previous
#include <cuda_runtime.h>
#include <cuda_fp16.h>
#include <cstdint>

// ---------------------------------------------------------------------------
// Problem constants (B=2, S=2048, H=1024, NH=16, NKV=8, D=128)
// ---------------------------------------------------------------------------
constexpr int B_   = 2;
constexpr int S_   = 2048;
constexpr int H_   = 1024;
constexpr int NH_  = 16;
constexpr int NKV_ = 8;
constexpr int D_   = 128;
constexpr int TOK  = B_ * S_;            // 4096 tokens

// Scratch (device globals; no allocation allowed)
__device__ float g_ao[TOK * NH_ * D_];
// fp16 attention operands: Q split hi/lo, K and V single
__device__ __half g_qh [TOK * NH_  * D_], g_ql[TOK * NH_ * D_];
__device__ __half g_k16[TOK * NKV_ * D_];
__device__ __half g_v16[TOK * NKV_ * D_];

#define DEV_INLINE __device__ __forceinline__

// ---------------------------------------------------------------------------
// helpers
// ---------------------------------------------------------------------------
DEV_INLINE uint32_t cvt_f16x2(float f0, float f1) {
    __half2 h = __float22half2_rn(make_float2(f0, f1));
    return *reinterpret_cast<uint32_t*>(&h);
}
// Dekker split two fp32 into fp16 hi-pair + lo-pair (f0 -> low lane)
DEV_INLINE void split_pair_f16(float f0, float f1, uint32_t& hiw, uint32_t& low) {
    __half2 h = __float22half2_rn(make_float2(f0, f1));
    hiw = *reinterpret_cast<uint32_t*>(&h);
    const float r0 = f0 - __half2float(__low2half(h));
    const float r1 = f1 - __half2float(__high2half(h));
    __half2 l = __float22half2_rn(make_float2(r0, r1));
    low = *reinterpret_cast<uint32_t*>(&l);
}
DEV_INLINE void ldsm_x4(uint32_t* r, uint32_t addr) {
    asm volatile("ldmatrix.sync.aligned.m8n8.x4.shared.b16 {%0,%1,%2,%3}, [%4];"
                 : "=r"(r[0]), "=r"(r[1]), "=r"(r[2]), "=r"(r[3]) : "r"(addr));
}
DEV_INLINE void ldsm_x4_trans(uint32_t* r, uint32_t addr) {
    asm volatile("ldmatrix.sync.aligned.m8n8.x4.trans.shared.b16 {%0,%1,%2,%3}, [%4];"
                 : "=r"(r[0]), "=r"(r[1]), "=r"(r[2]), "=r"(r[3]) : "r"(addr));
}
DEV_INLINE void mma_f16(float* c, const uint32_t* a, const uint32_t* b) {
    asm volatile(
        "mma.sync.aligned.m16n8k16.row.col.f32.f16.f16.f32 "
        "{%0,%1,%2,%3}, {%4,%5,%6,%7}, {%8,%9}, {%0,%1,%2,%3};"
        : "+f"(c[0]), "+f"(c[1]), "+f"(c[2]), "+f"(c[3])
        : "r"(a[0]), "r"(a[1]), "r"(a[2]), "r"(a[3]), "r"(b[0]), "r"(b[1]));
}
DEV_INLINE uint32_t smem_u32(const void* p) {
    uint32_t a;
    asm("{ .reg .u64 t; cvta.to.shared.u64 t, %1; cvt.u32.u64 %0, t; }"
        : "=r"(a) : "l"(p));
    return a;
}
DEV_INLINE void cp16(uint32_t dst, const void* src) {
    asm volatile("cp.async.cg.shared.global [%0], [%1], 16;"
                 :: "r"(dst), "l"(src) : "memory");
}
DEV_INLINE void cp_commit() { asm volatile("cp.async.commit_group;" ::: "memory"); }
DEV_INLINE void cp_wait1()  { asm volatile("cp.async.wait_group 1;" ::: "memory"); }
DEV_INLINE void cp_wait0()  { asm volatile("cp.async.wait_group 0;" ::: "memory"); }

// ---------------------------------------------------------------------------
// fp16 SINGLE-product tensor-core NT GEMM mainloop.
// C = A16 * B16 (both quantized; ~3.9e-4 statistical rel err per GEMM).
// 512 threads / 16 warps (4m x 4n, warp tile 32x32), CTA tile 128x128, BK=32,
// in-loop convert, double buffered. Result in Cacc[2][4][4].
// ---------------------------------------------------------------------------
constexpr int GMATB = 10240;           // 128 * 80 bytes per tile
constexpr int GBUFB = 2 * GMATB;       // 20480 per buffer: {A, B}
constexpr int GSMEM = 2 * GBUFB;       // 40960
constexpr int QKV_SMEM = 128 * 132 * 4; // 67584 (epilogue stash) > GSMEM

DEV_INLINE void gemm_mainloop(const float* __restrict__ A, const float* __restrict__ Bm,
                              int K, int m0, int n0,
                              char* smem, uint32_t sb, float Cacc[2][4][4])
{
    const int tid  = threadIdx.x;
    const int lane = tid & 31;
    const int wid  = tid >> 5;          // 0..15
    const int wm   = wid & 3;
    const int wn   = wid >> 2;

    const int r = tid >> 2;             // 0..127
    const int q = tid & 3;              // quarter (8 f32)
    const float* Arow = A  + (size_t)(m0 + r) * K + q * 8;
    const float* Brow = Bm + (size_t)(n0 + r) * K + q * 8;

#pragma unroll
    for (int mi = 0; mi < 2; mi++)
#pragma unroll
        for (int nf = 0; nf < 4; nf++)
#pragma unroll
            for (int e = 0; e < 4; e++) Cacc[mi][nf][e] = 0.f;

    float4 ra[2], rb[2];
#pragma unroll
    for (int i = 0; i < 2; i++) {
        ra[i] = *reinterpret_cast<const float4*>(Arow + i * 4);
        rb[i] = *reinterpret_cast<const float4*>(Brow + i * 4);
    }

    const uint32_t lrow = (uint32_t)(lane & 15);
    const uint32_t lcol = (uint32_t)(lane >> 4) * 16;

    const int NC = K / 32;
    for (int c = 0; c < NC; c++) {
        char* bp = smem + (c & 1) * GBUFB;
        const uint32_t bufs = sb + (c & 1) * GBUFB;

        {   // convert + store: A and B single fp16
            const uint32_t off = (uint32_t)r * 80 + (uint32_t)q * 16;
            const uint32_t a0 = cvt_f16x2(ra[0].x, ra[0].y);
            const uint32_t a1 = cvt_f16x2(ra[0].z, ra[0].w);
            const uint32_t a2 = cvt_f16x2(ra[1].x, ra[1].y);
            const uint32_t a3 = cvt_f16x2(ra[1].z, ra[1].w);
            *reinterpret_cast<uint4*>(bp + off) = make_uint4(a0, a1, a2, a3);
            const uint32_t b0 = cvt_f16x2(rb[0].x, rb[0].y);
            const uint32_t b1 = cvt_f16x2(rb[0].z, rb[0].w);
            const uint32_t b2 = cvt_f16x2(rb[1].x, rb[1].y);
            const uint32_t b3 = cvt_f16x2(rb[1].z, rb[1].w);
            *reinterpret_cast<uint4*>(bp + GMATB + off) = make_uint4(b0, b1, b2, b3);
        }
        __syncthreads();

        if (c + 1 < NC) {
            const int k0 = (c + 1) * 32;
#pragma unroll
            for (int i = 0; i < 2; i++) {
                ra[i] = *reinterpret_cast<const float4*>(Arow + k0 + i * 4);
                rb[i] = *reinterpret_cast<const float4*>(Brow + k0 + i * 4);
            }
        }

#pragma unroll
        for (int ks = 0; ks < 2; ks++) {
            uint32_t afrag[2][4];       // [mi][4]
            uint32_t bfr[4][2];         // [nf][2]
#pragma unroll
            for (int mi = 0; mi < 2; mi++) {
                const uint32_t addr = bufs +
                    ((uint32_t)(wm * 32 + mi * 16) + lrow) * 80 +
                    (uint32_t)ks * 32 + lcol;
                ldsm_x4(afrag[mi], addr);
            }
#pragma unroll
            for (int ng = 0; ng < 2; ng++) {
                uint32_t t4[4];
                const uint32_t addr = bufs + GMATB +
                    ((uint32_t)(wn * 32 + ng * 16) + lrow) * 80 +
                    (uint32_t)ks * 32 + lcol;
                ldsm_x4(t4, addr);
                bfr[ng * 2][0]     = t4[0];
                bfr[ng * 2][1]     = t4[2];
                bfr[ng * 2 + 1][0] = t4[1];
                bfr[ng * 2 + 1][1] = t4[3];
            }
#pragma unroll
            for (int mi = 0; mi < 2; mi++)
#pragma unroll
                for (int nf = 0; nf < 4; nf++)
                    mma_f16(Cacc[mi][nf], afrag[mi], bfr[nf]);
        }
        __syncthreads();
    }
}

// ---------------------------------------------------------------------------
// Merged QKV projection + FUSED RMSNorm/RoPE epilogue.
// Q -> fp16 hi/lo; K, V -> single fp16.
// ---------------------------------------------------------------------------
__global__ void __launch_bounds__(512, 1)
gemm_qkv_fused(const float* __restrict__ A,
               const float* __restrict__ Wq, const float* __restrict__ Wk,
               const float* __restrict__ Wv,
               const float* __restrict__ cosb, const float* __restrict__ sinb,
               const float* __restrict__ qw,   const float* __restrict__ kw,
               __half* __restrict__ qh, __half* __restrict__ ql,
               __half* __restrict__ k16, __half* __restrict__ v16)
{
    extern __shared__ char smem[];
    const uint32_t sb = smem_u32(smem);
    const int bx = blockIdx.x;
    const int m0 = blockIdx.y * 128;

    const float* Bm; int n0;
    if (bx < 16)      { Bm = Wq; n0 = bx * 128; }
    else if (bx < 24) { Bm = Wk; n0 = (bx - 16) * 128; }
    else              { Bm = Wv; n0 = (bx - 24) * 128; }

    float Cacc[2][4][4];
    gemm_mainloop(A, Bm, H_, m0, n0, smem, sb, Cacc);

    // ---- stash C tile to smem (post-final-sync; buffers dead) ----
    float* Cs = reinterpret_cast<float*>(smem);      // [128][132]
    {
        const int lane = threadIdx.x & 31;
        const int wid  = threadIdx.x >> 5;
        const int wm   = wid & 3;
        const int wn   = wid >> 2;
#pragma unroll
        for (int mi = 0; mi < 2; mi++) {
            const int row = wm * 32 + mi * 16 + (lane >> 2);
#pragma unroll
            for (int nf = 0; nf < 4; nf++) {
                const int col = wn * 32 + nf * 8 + (lane & 3) * 2;
                *reinterpret_cast<float2*>(&Cs[row * 132 + col]) =
                    make_float2(Cacc[mi][nf][0], Cacc[mi][nf][1]);
                *reinterpret_cast<float2*>(&Cs[(row + 8) * 132 + col]) =
                    make_float2(Cacc[mi][nf][2], Cacc[mi][nf][3]);
            }
        }
    }
    __syncthreads();

    const int lane = threadIdx.x & 31;
    const int wid  = threadIdx.x >> 5;
    const int l    = lane;

    if (bx >= 24) {                       // V: single fp16
        const int hv = bx - 24;
#pragma unroll
        for (int rr = 0; rr < 8; rr++) {
            const int row = wid * 8 + rr;
            const int token = m0 + row;
            const float4 x = *reinterpret_cast<const float4*>(&Cs[row * 132 + l * 4]);
            const uint32_t a0 = cvt_f16x2(x.x, x.y);
            const uint32_t a1 = cvt_f16x2(x.z, x.w);
            const size_t base = (size_t)token * (NKV_ * D_) + hv * D_ + l * 4;
            *reinterpret_cast<uint2*>(v16 + base) = make_uint2(a0, a1);
        }
        return;
    }

    const bool isq = (bx < 16);
    const float* w = isq ? qw : kw;
    const int hd  = isq ? bx : (bx - 16);
    const int hdn = isq ? (NH_ * D_) : (NKV_ * D_);
    const float4 wv = *reinterpret_cast<const float4*>(w + l * 4);
    const float sgn = (l < 16) ? -1.f : 1.f;

#pragma unroll
    for (int rr = 0; rr < 8; rr++) {
        const int row = wid * 8 + rr;
        const int token = m0 + row;
        const float4 x = *reinterpret_cast<const float4*>(&Cs[row * 132 + l * 4]);

        float ss = x.x * x.x + x.y * x.y + x.z * x.z + x.w * x.w;
#pragma unroll
        for (int off = 16; off >= 1; off >>= 1)
            ss += __shfl_xor_sync(0xffffffffu, ss, off);
        const float inv = rsqrtf(ss * (1.0f / 128.0f) + 1e-6f);

        const float4 cv = *reinterpret_cast<const float4*>(cosb + (size_t)token * D_ + l * 4);
        const float4 sv = *reinterpret_cast<const float4*>(sinb + (size_t)token * D_ + l * 4);

        const float z0 = x.x * wv.x, z1 = x.y * wv.y, z2 = x.z * wv.z, z3 = x.w * wv.w;
        const float p0 = __shfl_xor_sync(0xffffffffu, z0, 16);
        const float p1 = __shfl_xor_sync(0xffffffffu, z1, 16);
        const float p2 = __shfl_xor_sync(0xffffffffu, z2, 16);
        const float p3 = __shfl_xor_sync(0xffffffffu, z3, 16);

        const float y0 = (z0 * cv.x + sgn * p0 * sv.x) * inv;
        const float y1 = (z1 * cv.y + sgn * p1 * sv.y) * inv;
        const float y2 = (z2 * cv.z + sgn * p2 * sv.z) * inv;
        const float y3 = (z3 * cv.w + sgn * p3 * sv.w) * inv;

        const size_t base = (size_t)token * hdn + hd * D_ + l * 4;
        if (isq) {                        // Q: fp16 hi/lo split
            uint32_t h0, l0w, h1, l1w;
            split_pair_f16(y0, y1, h0, l0w);
            split_pair_f16(y2, y3, h1, l1w);
            *reinterpret_cast<uint2*>(qh + base) = make_uint2(h0, h1);
            *reinterpret_cast<uint2*>(ql + base) = make_uint2(l0w, l1w);
        } else {                          // K: single fp16
            const uint32_t a0 = cvt_f16x2(y0, y1);
            const uint32_t a1 = cvt_f16x2(y2, y3);
            *reinterpret_cast<uint2*>(k16 + base) = make_uint2(a0, a1);
        }
    }
}

// ---------------------------------------------------------------------------
// Generic GEMM (output projection), fp16 single-product
// ---------------------------------------------------------------------------
__global__ void __launch_bounds__(512, 1)
gemm_nt(const float* __restrict__ A, const float* __restrict__ Bm,
        float* __restrict__ C, int M, int N, int K)
{
    extern __shared__ char smem[];
    const uint32_t sb = smem_u32(smem);
    const int m0 = blockIdx.y * 128;
    const int n0 = blockIdx.x * 128;

    float Cacc[2][4][4];
    gemm_mainloop(A, Bm, K, m0, n0, smem, sb, Cacc);

    const int lane = threadIdx.x & 31;
    const int wid  = threadIdx.x >> 5;
    const int wm   = wid & 3;
    const int wn   = wid >> 2;
#pragma unroll
    for (int mi = 0; mi < 2; mi++) {
        const int row = m0 + wm * 32 + mi * 16 + (lane >> 2);
#pragma unroll
        for (int nf = 0; nf < 4; nf++) {
            const int col = n0 + wn * 32 + nf * 8 + (lane & 3) * 2;
            *reinterpret_cast<float2*>(C + (size_t)row * N + col) =
                make_float2(Cacc[mi][nf][0], Cacc[mi][nf][1]);
            *reinterpret_cast<float2*>(C + (size_t)(row + 8) * N + col) =
                make_float2(Cacc[mi][nf][2], Cacc[mi][nf][3]);
        }
    }
}

// ---------------------------------------------------------------------------
// Tensor-core flash attention (fp16 two-product, causal, GQA n_rep=2).
// Unchanged from round 14 (passing, at tensor floor, holds error reserve).
// ---------------------------------------------------------------------------
constexpr int AQ_BYTES  = 128 * 272;                 // 34816
constexpr int AKV_BYTES = 64 * 272;                  // 17408
constexpr int ABUF0     = 2 * AQ_BYTES;              // 69632
constexpr int ABUFSZ    = 2 * AKV_BYTES;             // 34816
constexpr int ATTN_SMEM = ABUF0 + 2 * ABUFSZ;        // 139264

__global__ void __launch_bounds__(256, 1)
attn_f16_kernel(const __half* __restrict__ qh, const __half* __restrict__ ql,
                const __half* __restrict__ k16, const __half* __restrict__ v16,
                float* __restrict__ ao)
{
    extern __shared__ char smem[];
    const uint32_t sb = smem_u32(smem);

    const int tid  = threadIdx.x;
    const int lane = tid & 31;
    const int w    = tid >> 5;
    const int qi   = gridDim.x - 1 - blockIdx.x;
    const int h    = blockIdx.y;
    const int b    = blockIdx.z;
    const int kvh  = h >> 1;

#pragma unroll
    for (int i = 0; i < 8; i++) {
        const int idx = tid + i * 256;
        const int row = idx >> 4, ch = idx & 15;
        const size_t g = ((size_t)(b * S_) + qi * 128 + row) * (NH_ * D_) + h * D_ + ch * 8;
        cp16(sb + row * 272 + ch * 16,            qh + g);
        cp16(sb + AQ_BYTES + row * 272 + ch * 16, ql + g);
    }
    {
        const uint32_t buf = sb + ABUF0;
#pragma unroll
        for (int i = 0; i < 4; i++) {
            const int idx = tid + i * 256;
            const int row = idx >> 4, ch = idx & 15;
            const size_t g = ((size_t)(b * S_) + row) * (NKV_ * D_) + kvh * D_ + ch * 8;
            const uint32_t so = buf + row * 272 + ch * 16;
            cp16(so,             k16 + g);
            cp16(so + AKV_BYTES, v16 + g);
        }
    }
    cp_commit();

    float oacc[16][4];
#pragma unroll
    for (int i = 0; i < 16; i++)
#pragma unroll
        for (int e = 0; e < 4; e++) oacc[i][e] = 0.f;
    float m_i[2] = {-1e30f, -1e30f};
    float l_i[2] = {0.f, 0.f};

    const uint32_t lrow16 = (uint32_t)(lane & 15);
    const uint32_t lhalf  = (uint32_t)(lane >> 4) * 16;
    const int jmax = 2 * qi + 1;

    for (int jb = 0; jb <= jmax; jb++) {
        if (jb < jmax) {
            const uint32_t buf = sb + ABUF0 + ((jb + 1) & 1) * ABUFSZ;
#pragma unroll
            for (int i = 0; i < 4; i++) {
                const int idx = tid + i * 256;
                const int row = idx >> 4, ch = idx & 15;
                const size_t g = ((size_t)(b * S_) + (jb + 1) * 64 + row) * (NKV_ * D_) +
                                 kvh * D_ + ch * 8;
                const uint32_t so = buf + row * 272 + ch * 16;
                cp16(so,             k16 + g);
                cp16(so + AKV_BYTES, v16 + g);
            }
            cp_commit();
            cp_wait1();
        } else {
            cp_wait0();
        }
        __syncthreads();

        const uint32_t kb = sb + ABUF0 + (jb & 1) * ABUFSZ;
        const bool skip = (jb * 64) > (qi * 128 + w * 16 + 15);

        if (!skip) {
            float sacc[8][4];
#pragma unroll
            for (int i = 0; i < 8; i++)
#pragma unroll
                for (int e = 0; e < 4; e++) sacc[i][e] = 0.f;

            const uint32_t qbase = sb + ((uint32_t)(w * 16) + lrow16) * 272 + lhalf;
#pragma unroll
            for (int ks = 0; ks < 8; ks++) {
                uint32_t ahi[4], alo[4];
                ldsm_x4(ahi, qbase + ks * 32);
                ldsm_x4(alo, qbase + AQ_BYTES + ks * 32);
#pragma unroll
                for (int ng = 0; ng < 4; ng++) {
                    uint32_t t[4];
                    const uint32_t ka = kb + ((uint32_t)(ng * 16) + lrow16) * 272 + ks * 32 + lhalf;
                    ldsm_x4(t, ka);
                    uint32_t bh0[2] = {t[0], t[2]}, bh1[2] = {t[1], t[3]};
                    mma_f16(sacc[ng * 2],     ahi, bh0);
                    mma_f16(sacc[ng * 2 + 1], ahi, bh1);
                    mma_f16(sacc[ng * 2],     alo, bh0);
                    mma_f16(sacc[ng * 2 + 1], alo, bh1);
                }
            }

            const float sc = 0.088388347648318447f;
            const bool domask = (jb * 64 + 63) > (qi * 128 + w * 16);
#pragma unroll
            for (int nf = 0; nf < 8; nf++)
#pragma unroll
                for (int e = 0; e < 4; e++) {
                    float s = sacc[nf][e] * sc;
                    if (domask) {
                        const int col = jb * 64 + nf * 8 + ((lane & 3) << 1) + (e & 1);
                        const int row = qi * 128 + w * 16 + (lane >> 2) + ((e >> 1) << 3);
                        if (col > row) s = -1e30f;
                    }
                    sacc[nf][e] = s;
                }

#pragma unroll
            for (int r2 = 0; r2 < 2; r2++) {
                float mx = -1e30f;
#pragma unroll
                for (int nf = 0; nf < 8; nf++)
                    mx = fmaxf(mx, fmaxf(sacc[nf][2 * r2], sacc[nf][2 * r2 + 1]));
                mx = fmaxf(mx, __shfl_xor_sync(0xffffffffu, mx, 1));
                mx = fmaxf(mx, __shfl_xor_sync(0xffffffffu, mx, 2));
                const float mn = fmaxf(m_i[r2], mx);
                const float alpha = __expf(m_i[r2] - mn);
                m_i[r2] = mn;
                float rs = 0.f;
#pragma unroll
                for (int nf = 0; nf < 8; nf++) {
                    float p0 = __expf(sacc[nf][2 * r2]     - mn);
                    float p1 = __expf(sacc[nf][2 * r2 + 1] - mn);
                    sacc[nf][2 * r2]     = p0;
                    sacc[nf][2 * r2 + 1] = p1;
                    rs += p0 + p1;
                }
                rs += __shfl_xor_sync(0xffffffffu, rs, 1);
                rs += __shfl_xor_sync(0xffffffffu, rs, 2);
                l_i[r2] = l_i[r2] * alpha + rs;
#pragma unroll
                for (int ndf = 0; ndf < 16; ndf++) {
                    oacc[ndf][2 * r2]     *= alpha;
                    oacc[ndf][2 * r2 + 1] *= alpha;
                }
            }

#pragma unroll
            for (int kk = 0; kk < 4; kk++) {
                uint32_t phi[4], plo[4];
                split_pair_f16(sacc[2 * kk][0],     sacc[2 * kk][1],     phi[0], plo[0]);
                split_pair_f16(sacc[2 * kk][2],     sacc[2 * kk][3],     phi[1], plo[1]);
                split_pair_f16(sacc[2 * kk + 1][0], sacc[2 * kk + 1][1], phi[2], plo[2]);
                split_pair_f16(sacc[2 * kk + 1][2], sacc[2 * kk + 1][3], phi[3], plo[3]);
#pragma unroll
                for (int ndg = 0; ndg < 8; ndg++) {
                    uint32_t t[4];
                    const uint32_t va = kb + AKV_BYTES +
                        ((uint32_t)(kk * 16) + lrow16) * 272 + ndg * 32 + lhalf;
                    ldsm_x4_trans(t, va);
                    uint32_t bh0[2] = {t[0], t[1]}, bh1[2] = {t[2], t[3]};
                    mma_f16(oacc[ndg * 2],     phi, bh0);
                    mma_f16(oacc[ndg * 2 + 1], phi, bh1);
                    mma_f16(oacc[ndg * 2],     plo, bh0);
                    mma_f16(oacc[ndg * 2 + 1], plo, bh1);
                }
            }
        }
        __syncthreads();
    }

    const float i0 = 1.0f / l_i[0];
    const float i1 = 1.0f / l_i[1];
    const int row0 = qi * 128 + w * 16 + (lane >> 2);
    const size_t base0 = ((size_t)(b * S_) + row0) * (NH_ * D_) + h * D_ + (lane & 3) * 2;
    const size_t base1 = base0 + (size_t)8 * (NH_ * D_);
#pragma unroll
    for (int ndf = 0; ndf < 16; ndf++) {
        *reinterpret_cast<float2*>(ao + base0 + ndf * 8) =
            make_float2(oacc[ndf][0] * i0, oacc[ndf][1] * i0);
        *reinterpret_cast<float2*>(ao + base1 + ndf * 8) =
            make_float2(oacc[ndf][2] * i1, oacc[ndf][3] * i1);
    }
}

// ---------------------------------------------------------------------------
// Launch
// ---------------------------------------------------------------------------
extern "C" void kernel_launch(void* const* d_in, const int* in_sizes, int n_in,
                              void* d_out, int out_size)
{
    const float* hidden = (const float*)d_in[0];
    const float* cosb   = (const float*)d_in[1];
    const float* sinb   = (const float*)d_in[2];
    const float* Wq     = (const float*)d_in[3];
    const float* Wk     = (const float*)d_in[4];
    const float* Wv     = (const float*)d_in[5];
    const float* Wo     = (const float*)d_in[6];
    const float* qw     = (const float*)d_in[7];
    const float* kw     = (const float*)d_in[8];
    float* out = (float*)d_out;

    float* gao;
    cudaGetSymbolAddress((void**)&gao, g_ao);
    __half *qh, *ql, *k16, *v16;
    cudaGetSymbolAddress((void**)&qh,  g_qh);
    cudaGetSymbolAddress((void**)&ql,  g_ql);
    cudaGetSymbolAddress((void**)&k16, g_k16);
    cudaGetSymbolAddress((void**)&v16, g_v16);

    cudaFuncSetAttribute((const void*)gemm_qkv_fused,
                         cudaFuncAttributeMaxDynamicSharedMemorySize, QKV_SMEM);
    cudaFuncSetAttribute((const void*)gemm_nt,
                         cudaFuncAttributeMaxDynamicSharedMemorySize, GSMEM);
    cudaFuncSetAttribute((const void*)attn_f16_kernel,
                         cudaFuncAttributeMaxDynamicSharedMemorySize, ATTN_SMEM);

    // merged QKV projection (fp16 single-product) + fused RMSNorm/RoPE epilogue
    gemm_qkv_fused<<<dim3(32, TOK / 128), 512, QKV_SMEM>>>(
        hidden, Wq, Wk, Wv, cosb, sinb, qw, kw, qh, ql, k16, v16);

    // tensor-core causal flash attention (fp16 two-product)
    attn_f16_kernel<<<dim3(S_ / 128, NH_, B_), 256, ATTN_SMEM>>>(
        qh, ql, k16, v16, gao);

    // output projection (fp16 single-product)
    gemm_nt<<<dim3(H_ / 128, TOK / 128), 512, GSMEM>>>(
        gao, Wo, out, TOK, H_, NH_ * D_);
}

// round 16
// speedup vs baseline: 3.2098x; 1.1212x over previous
#include <cuda_runtime.h>
#include <cuda_fp16.h>
#include <cstdint>

// ---------------------------------------------------------------------------
// Problem constants (B=2, S=2048, H=1024, NH=16, NKV=8, D=128)
// ---------------------------------------------------------------------------
constexpr int B_   = 2;
constexpr int S_   = 2048;
constexpr int H_   = 1024;
constexpr int NH_  = 16;
constexpr int NKV_ = 8;
constexpr int D_   = 128;
constexpr int TOK  = B_ * S_;            // 4096 tokens

// Scratch (device globals; no allocation allowed)
// fp16 pre-converted GEMM operands
__device__ __half g_h16 [TOK * H_];
__device__ __half g_wq16[NH_  * D_ * H_];
__device__ __half g_wk16[NKV_ * D_ * H_];
__device__ __half g_wv16[NKV_ * D_ * H_];
__device__ __half g_wo16[H_ * NH_ * D_];
__device__ __half g_ao16[TOK * NH_ * D_];
// fp16 attention operands: Q split hi/lo, K and V single
__device__ __half g_qh [TOK * NH_  * D_], g_ql[TOK * NH_ * D_];
__device__ __half g_k16[TOK * NKV_ * D_];
__device__ __half g_v16[TOK * NKV_ * D_];

#define DEV_INLINE __device__ __forceinline__

// ---------------------------------------------------------------------------
// helpers
// ---------------------------------------------------------------------------
DEV_INLINE uint32_t cvt_f16x2(float f0, float f1) {
    __half2 h = __float22half2_rn(make_float2(f0, f1));
    return *reinterpret_cast<uint32_t*>(&h);
}
// Dekker split two fp32 into fp16 hi-pair + lo-pair (f0 -> low lane)
DEV_INLINE void split_pair_f16(float f0, float f1, uint32_t& hiw, uint32_t& low) {
    __half2 h = __float22half2_rn(make_float2(f0, f1));
    hiw = *reinterpret_cast<uint32_t*>(&h);
    const float r0 = f0 - __half2float(__low2half(h));
    const float r1 = f1 - __half2float(__high2half(h));
    __half2 l = __float22half2_rn(make_float2(r0, r1));
    low = *reinterpret_cast<uint32_t*>(&l);
}
DEV_INLINE void ldsm_x4(uint32_t* r, uint32_t addr) {
    asm volatile("ldmatrix.sync.aligned.m8n8.x4.shared.b16 {%0,%1,%2,%3}, [%4];"
                 : "=r"(r[0]), "=r"(r[1]), "=r"(r[2]), "=r"(r[3]) : "r"(addr));
}
DEV_INLINE void ldsm_x4_trans(uint32_t* r, uint32_t addr) {
    asm volatile("ldmatrix.sync.aligned.m8n8.x4.trans.shared.b16 {%0,%1,%2,%3}, [%4];"
                 : "=r"(r[0]), "=r"(r[1]), "=r"(r[2]), "=r"(r[3]) : "r"(addr));
}
DEV_INLINE void mma_f16(float* c, const uint32_t* a, const uint32_t* b) {
    asm volatile(
        "mma.sync.aligned.m16n8k16.row.col.f32.f16.f16.f32 "
        "{%0,%1,%2,%3}, {%4,%5,%6,%7}, {%8,%9}, {%0,%1,%2,%3};"
        : "+f"(c[0]), "+f"(c[1]), "+f"(c[2]), "+f"(c[3])
        : "r"(a[0]), "r"(a[1]), "r"(a[2]), "r"(a[3]), "r"(b[0]), "r"(b[1]));
}
DEV_INLINE uint32_t smem_u32(const void* p) {
    uint32_t a;
    asm("{ .reg .u64 t; cvta.to.shared.u64 t, %1; cvt.u32.u64 %0, t; }"
        : "=r"(a) : "l"(p));
    return a;
}
DEV_INLINE void cp16(uint32_t dst, const void* src) {
    asm volatile("cp.async.cg.shared.global [%0], [%1], 16;"
                 :: "r"(dst), "l"(src) : "memory");
}
DEV_INLINE void cp_commit() { asm volatile("cp.async.commit_group;" ::: "memory"); }
DEV_INLINE void cp_wait1()  { asm volatile("cp.async.wait_group 1;" ::: "memory"); }
DEV_INLINE void cp_wait0()  { asm volatile("cp.async.wait_group 0;" ::: "memory"); }

// ---------------------------------------------------------------------------
// fp32 -> fp16 converter (grid-stride, float4 -> 2x half2)
// ---------------------------------------------------------------------------
__global__ void cvt16_kernel(const float* __restrict__ x, __half* __restrict__ y, int n4)
{
    int i = blockIdx.x * blockDim.x + threadIdx.x;
    const int stride = gridDim.x * blockDim.x;
    for (; i < n4; i += stride) {
        const float4 v = reinterpret_cast<const float4*>(x)[i];
        reinterpret_cast<uint2*>(y)[i] =
            make_uint2(cvt_f16x2(v.x, v.y), cvt_f16x2(v.z, v.w));
    }
}

// ---------------------------------------------------------------------------
// fp16 single-product tensor-core NT GEMM mainloop, cp.async producer.
// C = A16 * B16, both operands pre-converted fp16 in global.
// 512 threads / 16 warps (4m x 4n, warp tile 32x32), CTA tile 128x128, BK=32.
// Per chunk per thread: 2 cp.async (16B each). Zero cvt/STS in loop.
// ---------------------------------------------------------------------------
constexpr int GMATB = 10240;           // 128 rows * 80B stride per tile
constexpr int GBUFB = 2 * GMATB;       // 20480 per buffer: {A, B}
constexpr int GSMEM = 2 * GBUFB;       // 40960
constexpr int QKV_SMEM = 128 * 132 * 4; // 67584 (epilogue stash) > GSMEM

DEV_INLINE void gemm_mainloop(const __half* __restrict__ A16, const __half* __restrict__ B16,
                              int K, int m0, int n0,
                              uint32_t sb, float Cacc[2][4][4])
{
    const int tid  = threadIdx.x;
    const int lane = tid & 31;
    const int wid  = tid >> 5;          // 0..15
    const int wm   = wid & 3;
    const int wn   = wid >> 2;

    // producer mapping: row r (0..127), 16B quarter q of the 64B chunk-row
    const int r = tid >> 2;
    const int q = tid & 3;
    const uint32_t soff = (uint32_t)r * 80 + (uint32_t)q * 16;
    const __half* Arow = A16 + (size_t)(m0 + r) * K + q * 8;
    const __half* Brow = B16 + (size_t)(n0 + r) * K + q * 8;

#pragma unroll
    for (int mi = 0; mi < 2; mi++)
#pragma unroll
        for (int nf = 0; nf < 4; nf++)
#pragma unroll
            for (int e = 0; e < 4; e++) Cacc[mi][nf][e] = 0.f;

    const uint32_t lrow = (uint32_t)(lane & 15);
    const uint32_t lcol = (uint32_t)(lane >> 4) * 16;
    const int NC = K / 32;

    // prologue: chunk 0
    cp16(sb + soff,         Arow);
    cp16(sb + GMATB + soff, Brow);
    cp_commit();

    for (int c = 0; c < NC; c++) {
        if (c + 1 < NC) {
            const uint32_t nb = sb + ((c + 1) & 1) * GBUFB;
            cp16(nb + soff,         Arow + (c + 1) * 32);
            cp16(nb + GMATB + soff, Brow + (c + 1) * 32);
            cp_commit();
            cp_wait1();
        } else {
            cp_wait0();
        }
        __syncthreads();

        const uint32_t bufs = sb + (c & 1) * GBUFB;
#pragma unroll
        for (int ks = 0; ks < 2; ks++) {
            uint32_t afrag[2][4];
            uint32_t bfr[4][2];
#pragma unroll
            for (int mi = 0; mi < 2; mi++) {
                const uint32_t addr = bufs +
                    ((uint32_t)(wm * 32 + mi * 16) + lrow) * 80 +
                    (uint32_t)ks * 32 + lcol;
                ldsm_x4(afrag[mi], addr);
            }
#pragma unroll
            for (int ng = 0; ng < 2; ng++) {
                uint32_t t4[4];
                const uint32_t addr = bufs + GMATB +
                    ((uint32_t)(wn * 32 + ng * 16) + lrow) * 80 +
                    (uint32_t)ks * 32 + lcol;
                ldsm_x4(t4, addr);
                bfr[ng * 2][0]     = t4[0];
                bfr[ng * 2][1]     = t4[2];
                bfr[ng * 2 + 1][0] = t4[1];
                bfr[ng * 2 + 1][1] = t4[3];
            }
#pragma unroll
            for (int mi = 0; mi < 2; mi++)
#pragma unroll
                for (int nf = 0; nf < 4; nf++)
                    mma_f16(Cacc[mi][nf], afrag[mi], bfr[nf]);
        }
        __syncthreads();   // compute done before buffer re-issue next iter
    }
}

// ---------------------------------------------------------------------------
// Merged QKV projection + FUSED RMSNorm/RoPE epilogue.
// Q -> fp16 hi/lo; K, V -> single fp16.
// ---------------------------------------------------------------------------
__global__ void __launch_bounds__(512, 1)
gemm_qkv_fused(const __half* __restrict__ A16,
               const __half* __restrict__ Wq16, const __half* __restrict__ Wk16,
               const __half* __restrict__ Wv16,
               const float* __restrict__ cosb, const float* __restrict__ sinb,
               const float* __restrict__ qw,   const float* __restrict__ kw,
               __half* __restrict__ qh, __half* __restrict__ ql,
               __half* __restrict__ k16, __half* __restrict__ v16)
{
    extern __shared__ char smem[];
    const uint32_t sb = smem_u32(smem);
    const int bx = blockIdx.x;
    const int m0 = blockIdx.y * 128;

    const __half* Bm; int n0;
    if (bx < 16)      { Bm = Wq16; n0 = bx * 128; }
    else if (bx < 24) { Bm = Wk16; n0 = (bx - 16) * 128; }
    else              { Bm = Wv16; n0 = (bx - 24) * 128; }

    float Cacc[2][4][4];
    gemm_mainloop(A16, Bm, H_, m0, n0, sb, Cacc);

    // ---- stash C tile to smem (post-final-sync; buffers dead) ----
    float* Cs = reinterpret_cast<float*>(smem);      // [128][132]
    {
        const int lane = threadIdx.x & 31;
        const int wid  = threadIdx.x >> 5;
        const int wm   = wid & 3;
        const int wn   = wid >> 2;
#pragma unroll
        for (int mi = 0; mi < 2; mi++) {
            const int row = wm * 32 + mi * 16 + (lane >> 2);
#pragma unroll
            for (int nf = 0; nf < 4; nf++) {
                const int col = wn * 32 + nf * 8 + (lane & 3) * 2;
                *reinterpret_cast<float2*>(&Cs[row * 132 + col]) =
                    make_float2(Cacc[mi][nf][0], Cacc[mi][nf][1]);
                *reinterpret_cast<float2*>(&Cs[(row + 8) * 132 + col]) =
                    make_float2(Cacc[mi][nf][2], Cacc[mi][nf][3]);
            }
        }
    }
    __syncthreads();

    const int lane = threadIdx.x & 31;
    const int wid  = threadIdx.x >> 5;
    const int l    = lane;

    if (bx >= 24) {                       // V: single fp16
        const int hv = bx - 24;
#pragma unroll
        for (int rr = 0; rr < 8; rr++) {
            const int row = wid * 8 + rr;
            const int token = m0 + row;
            const float4 x = *reinterpret_cast<const float4*>(&Cs[row * 132 + l * 4]);
            const uint32_t a0 = cvt_f16x2(x.x, x.y);
            const uint32_t a1 = cvt_f16x2(x.z, x.w);
            const size_t base = (size_t)token * (NKV_ * D_) + hv * D_ + l * 4;
            *reinterpret_cast<uint2*>(v16 + base) = make_uint2(a0, a1);
        }
        return;
    }

    const bool isq = (bx < 16);
    const float* w = isq ? qw : kw;
    const int hd  = isq ? bx : (bx - 16);
    const int hdn = isq ? (NH_ * D_) : (NKV_ * D_);
    const float4 wv = *reinterpret_cast<const float4*>(w + l * 4);
    const float sgn = (l < 16) ? -1.f : 1.f;

#pragma unroll
    for (int rr = 0; rr < 8; rr++) {
        const int row = wid * 8 + rr;
        const int token = m0 + row;
        const float4 x = *reinterpret_cast<const float4*>(&Cs[row * 132 + l * 4]);

        float ss = x.x * x.x + x.y * x.y + x.z * x.z + x.w * x.w;
#pragma unroll
        for (int off = 16; off >= 1; off >>= 1)
            ss += __shfl_xor_sync(0xffffffffu, ss, off);
        const float inv = rsqrtf(ss * (1.0f / 128.0f) + 1e-6f);

        const float4 cv = *reinterpret_cast<const float4*>(cosb + (size_t)token * D_ + l * 4);
        const float4 sv = *reinterpret_cast<const float4*>(sinb + (size_t)token * D_ + l * 4);

        const float z0 = x.x * wv.x, z1 = x.y * wv.y, z2 = x.z * wv.z, z3 = x.w * wv.w;
        const float p0 = __shfl_xor_sync(0xffffffffu, z0, 16);
        const float p1 = __shfl_xor_sync(0xffffffffu, z1, 16);
        const float p2 = __shfl_xor_sync(0xffffffffu, z2, 16);
        const float p3 = __shfl_xor_sync(0xffffffffu, z3, 16);

        const float y0 = (z0 * cv.x + sgn * p0 * sv.x) * inv;
        const float y1 = (z1 * cv.y + sgn * p1 * sv.y) * inv;
        const float y2 = (z2 * cv.z + sgn * p2 * sv.z) * inv;
        const float y3 = (z3 * cv.w + sgn * p3 * sv.w) * inv;

        const size_t base = (size_t)token * hdn + hd * D_ + l * 4;
        if (isq) {                        // Q: fp16 hi/lo split
            uint32_t h0, l0w, h1, l1w;
            split_pair_f16(y0, y1, h0, l0w);
            split_pair_f16(y2, y3, h1, l1w);
            *reinterpret_cast<uint2*>(qh + base) = make_uint2(h0, h1);
            *reinterpret_cast<uint2*>(ql + base) = make_uint2(l0w, l1w);
        } else {                          // K: single fp16
            const uint32_t a0 = cvt_f16x2(y0, y1);
            const uint32_t a1 = cvt_f16x2(y2, y3);
            *reinterpret_cast<uint2*>(k16 + base) = make_uint2(a0, a1);
        }
    }
}

// ---------------------------------------------------------------------------
// Output projection GEMM (fp16 single-product, fp16 operands, fp32 out)
// ---------------------------------------------------------------------------
__global__ void __launch_bounds__(512, 1)
gemm_nt(const __half* __restrict__ A16, const __half* __restrict__ B16,
        float* __restrict__ C, int M, int N, int K)
{
    extern __shared__ char smem[];
    const uint32_t sb = smem_u32(smem);
    const int m0 = blockIdx.y * 128;
    const int n0 = blockIdx.x * 128;

    float Cacc[2][4][4];
    gemm_mainloop(A16, B16, K, m0, n0, sb, Cacc);

    const int lane = threadIdx.x & 31;
    const int wid  = threadIdx.x >> 5;
    const int wm   = wid & 3;
    const int wn   = wid >> 2;
#pragma unroll
    for (int mi = 0; mi < 2; mi++) {
        const int row = m0 + wm * 32 + mi * 16 + (lane >> 2);
#pragma unroll
        for (int nf = 0; nf < 4; nf++) {
            const int col = n0 + wn * 32 + nf * 8 + (lane & 3) * 2;
            *reinterpret_cast<float2*>(C + (size_t)row * N + col) =
                make_float2(Cacc[mi][nf][0], Cacc[mi][nf][1]);
            *reinterpret_cast<float2*>(C + (size_t)(row + 8) * N + col) =
                make_float2(Cacc[mi][nf][2], Cacc[mi][nf][3]);
        }
    }
}

// ---------------------------------------------------------------------------
// Tensor-core flash attention (fp16 two-product, causal, GQA n_rep=2).
// Round-15 proven; epilogue now emits fp16 ao.
// ---------------------------------------------------------------------------
constexpr int AQ_BYTES  = 128 * 272;                 // 34816
constexpr int AKV_BYTES = 64 * 272;                  // 17408
constexpr int ABUF0     = 2 * AQ_BYTES;              // 69632
constexpr int ABUFSZ    = 2 * AKV_BYTES;             // 34816
constexpr int ATTN_SMEM = ABUF0 + 2 * ABUFSZ;        // 139264

__global__ void __launch_bounds__(256, 1)
attn_f16_kernel(const __half* __restrict__ qh, const __half* __restrict__ ql,
                const __half* __restrict__ k16, const __half* __restrict__ v16,
                __half* __restrict__ ao16)
{
    extern __shared__ char smem[];
    const uint32_t sb = smem_u32(smem);

    const int tid  = threadIdx.x;
    const int lane = tid & 31;
    const int w    = tid >> 5;
    const int qi   = gridDim.x - 1 - blockIdx.x;
    const int h    = blockIdx.y;
    const int b    = blockIdx.z;
    const int kvh  = h >> 1;

#pragma unroll
    for (int i = 0; i < 8; i++) {
        const int idx = tid + i * 256;
        const int row = idx >> 4, ch = idx & 15;
        const size_t g = ((size_t)(b * S_) + qi * 128 + row) * (NH_ * D_) + h * D_ + ch * 8;
        cp16(sb + row * 272 + ch * 16,            qh + g);
        cp16(sb + AQ_BYTES + row * 272 + ch * 16, ql + g);
    }
    {
        const uint32_t buf = sb + ABUF0;
#pragma unroll
        for (int i = 0; i < 4; i++) {
            const int idx = tid + i * 256;
            const int row = idx >> 4, ch = idx & 15;
            const size_t g = ((size_t)(b * S_) + row) * (NKV_ * D_) + kvh * D_ + ch * 8;
            const uint32_t so = buf + row * 272 + ch * 16;
            cp16(so,             k16 + g);
            cp16(so + AKV_BYTES, v16 + g);
        }
    }
    cp_commit();

    float oacc[16][4];
#pragma unroll
    for (int i = 0; i < 16; i++)
#pragma unroll
        for (int e = 0; e < 4; e++) oacc[i][e] = 0.f;
    float m_i[2] = {-1e30f, -1e30f};
    float l_i[2] = {0.f, 0.f};

    const uint32_t lrow16 = (uint32_t)(lane & 15);
    const uint32_t lhalf  = (uint32_t)(lane >> 4) * 16;
    const int jmax = 2 * qi + 1;

    for (int jb = 0; jb <= jmax; jb++) {
        if (jb < jmax) {
            const uint32_t buf = sb + ABUF0 + ((jb + 1) & 1) * ABUFSZ;
#pragma unroll
            for (int i = 0; i < 4; i++) {
                const int idx = tid + i * 256;
                const int row = idx >> 4, ch = idx & 15;
                const size_t g = ((size_t)(b * S_) + (jb + 1) * 64 + row) * (NKV_ * D_) +
                                 kvh * D_ + ch * 8;
                const uint32_t so = buf + row * 272 + ch * 16;
                cp16(so,             k16 + g);
                cp16(so + AKV_BYTES, v16 + g);
            }
            cp_commit();
            cp_wait1();
        } else {
            cp_wait0();
        }
        __syncthreads();

        const uint32_t kb = sb + ABUF0 + (jb & 1) * ABUFSZ;
        const bool skip = (jb * 64) > (qi * 128 + w * 16 + 15);

        if (!skip) {
            float sacc[8][4];
#pragma unroll
            for (int i = 0; i < 8; i++)
#pragma unroll
                for (int e = 0; e < 4; e++) sacc[i][e] = 0.f;

            const uint32_t qbase = sb + ((uint32_t)(w * 16) + lrow16) * 272 + lhalf;
#pragma unroll
            for (int ks = 0; ks < 8; ks++) {
                uint32_t ahi[4], alo[4];
                ldsm_x4(ahi, qbase + ks * 32);
                ldsm_x4(alo, qbase + AQ_BYTES + ks * 32);
#pragma unroll
                for (int ng = 0; ng < 4; ng++) {
                    uint32_t t[4];
                    const uint32_t ka = kb + ((uint32_t)(ng * 16) + lrow16) * 272 + ks * 32 + lhalf;
                    ldsm_x4(t, ka);
                    uint32_t bh0[2] = {t[0], t[2]}, bh1[2] = {t[1], t[3]};
                    mma_f16(sacc[ng * 2],     ahi, bh0);
                    mma_f16(sacc[ng * 2 + 1], ahi, bh1);
                    mma_f16(sacc[ng * 2],     alo, bh0);
                    mma_f16(sacc[ng * 2 + 1], alo, bh1);
                }
            }

            const float sc = 0.088388347648318447f;
            const bool domask = (jb * 64 + 63) > (qi * 128 + w * 16);
#pragma unroll
            for (int nf = 0; nf < 8; nf++)
#pragma unroll
                for (int e = 0; e < 4; e++) {
                    float s = sacc[nf][e] * sc;
                    if (domask) {
                        const int col = jb * 64 + nf * 8 + ((lane & 3) << 1) + (e & 1);
                        const int row = qi * 128 + w * 16 + (lane >> 2) + ((e >> 1) << 3);
                        if (col > row) s = -1e30f;
                    }
                    sacc[nf][e] = s;
                }

#pragma unroll
            for (int r2 = 0; r2 < 2; r2++) {
                float mx = -1e30f;
#pragma unroll
                for (int nf = 0; nf < 8; nf++)
                    mx = fmaxf(mx, fmaxf(sacc[nf][2 * r2], sacc[nf][2 * r2 + 1]));
                mx = fmaxf(mx, __shfl_xor_sync(0xffffffffu, mx, 1));
                mx = fmaxf(mx, __shfl_xor_sync(0xffffffffu, mx, 2));
                const float mn = fmaxf(m_i[r2], mx);
                const float alpha = __expf(m_i[r2] - mn);
                m_i[r2] = mn;
                float rs = 0.f;
#pragma unroll
                for (int nf = 0; nf < 8; nf++) {
                    float p0 = __expf(sacc[nf][2 * r2]     - mn);
                    float p1 = __expf(sacc[nf][2 * r2 + 1] - mn);
                    sacc[nf][2 * r2]     = p0;
                    sacc[nf][2 * r2 + 1] = p1;
                    rs += p0 + p1;
                }
                rs += __shfl_xor_sync(0xffffffffu, rs, 1);
                rs += __shfl_xor_sync(0xffffffffu, rs, 2);
                l_i[r2] = l_i[r2] * alpha + rs;
#pragma unroll
                for (int ndf = 0; ndf < 16; ndf++) {
                    oacc[ndf][2 * r2]     *= alpha;
                    oacc[ndf][2 * r2 + 1] *= alpha;
                }
            }

#pragma unroll
            for (int kk = 0; kk < 4; kk++) {
                uint32_t phi[4], plo[4];
                split_pair_f16(sacc[2 * kk][0],     sacc[2 * kk][1],     phi[0], plo[0]);
                split_pair_f16(sacc[2 * kk][2],     sacc[2 * kk][3],     phi[1], plo[1]);
                split_pair_f16(sacc[2 * kk + 1][0], sacc[2 * kk + 1][1], phi[2], plo[2]);
                split_pair_f16(sacc[2 * kk + 1][2], sacc[2 * kk + 1][3], phi[3], plo[3]);
#pragma unroll
                for (int ndg = 0; ndg < 8; ndg++) {
                    uint32_t t[4];
                    const uint32_t va = kb + AKV_BYTES +
                        ((uint32_t)(kk * 16) + lrow16) * 272 + ndg * 32 + lhalf;
                    ldsm_x4_trans(t, va);
                    uint32_t bh0[2] = {t[0], t[1]}, bh1[2] = {t[2], t[3]};
                    mma_f16(oacc[ndg * 2],     phi, bh0);
                    mma_f16(oacc[ndg * 2 + 1], phi, bh1);
                    mma_f16(oacc[ndg * 2],     plo, bh0);
                    mma_f16(oacc[ndg * 2 + 1], plo, bh1);
                }
            }
        }
        __syncthreads();
    }

    // epilogue: normalize, emit fp16 ao (same value Wo GEMM would quantize to)
    const float i0 = 1.0f / l_i[0];
    const float i1 = 1.0f / l_i[1];
    const int row0 = qi * 128 + w * 16 + (lane >> 2);
    const size_t base0 = ((size_t)(b * S_) + row0) * (NH_ * D_) + h * D_ + (lane & 3) * 2;
    const size_t base1 = base0 + (size_t)8 * (NH_ * D_);
#pragma unroll
    for (int ndf = 0; ndf < 16; ndf++) {
        *reinterpret_cast<uint32_t*>(ao16 + base0 + ndf * 8) =
            cvt_f16x2(oacc[ndf][0] * i0, oacc[ndf][1] * i0);
        *reinterpret_cast<uint32_t*>(ao16 + base1 + ndf * 8) =
            cvt_f16x2(oacc[ndf][2] * i1, oacc[ndf][3] * i1);
    }
}

// ---------------------------------------------------------------------------
// Launch
// ---------------------------------------------------------------------------
extern "C" void kernel_launch(void* const* d_in, const int* in_sizes, int n_in,
                              void* d_out, int out_size)
{
    const float* hidden = (const float*)d_in[0];
    const float* cosb   = (const float*)d_in[1];
    const float* sinb   = (const float*)d_in[2];
    const float* Wq     = (const float*)d_in[3];
    const float* Wk     = (const float*)d_in[4];
    const float* Wv     = (const float*)d_in[5];
    const float* Wo     = (const float*)d_in[6];
    const float* qw     = (const float*)d_in[7];
    const float* kw     = (const float*)d_in[8];
    float* out = (float*)d_out;

    __half *h16, *wq16, *wk16, *wv16, *wo16, *ao16;
    cudaGetSymbolAddress((void**)&h16,  g_h16);
    cudaGetSymbolAddress((void**)&wq16, g_wq16);
    cudaGetSymbolAddress((void**)&wk16, g_wk16);
    cudaGetSymbolAddress((void**)&wv16, g_wv16);
    cudaGetSymbolAddress((void**)&wo16, g_wo16);
    cudaGetSymbolAddress((void**)&ao16, g_ao16);
    __half *qh, *ql, *k16, *v16;
    cudaGetSymbolAddress((void**)&qh,  g_qh);
    cudaGetSymbolAddress((void**)&ql,  g_ql);
    cudaGetSymbolAddress((void**)&k16, g_k16);
    cudaGetSymbolAddress((void**)&v16, g_v16);

    cudaFuncSetAttribute((const void*)gemm_qkv_fused,
                         cudaFuncAttributeMaxDynamicSharedMemorySize, QKV_SMEM);
    cudaFuncSetAttribute((const void*)gemm_nt,
                         cudaFuncAttributeMaxDynamicSharedMemorySize, GSMEM);
    cudaFuncSetAttribute((const void*)attn_f16_kernel,
                         cudaFuncAttributeMaxDynamicSharedMemorySize, ATTN_SMEM);

    // pre-convert operands to fp16 (values identical to in-loop cvt)
    cvt16_kernel<<<1024, 256>>>(hidden, h16,  TOK * H_ / 4);
    cvt16_kernel<<<1024, 256>>>(Wq,     wq16, NH_ * D_ * H_ / 4);
    cvt16_kernel<<<512,  256>>>(Wk,     wk16, NKV_ * D_ * H_ / 4);
    cvt16_kernel<<<512,  256>>>(Wv,     wv16, NKV_ * D_ * H_ / 4);
    cvt16_kernel<<<1024, 256>>>(Wo,     wo16, H_ * NH_ * D_ / 4);

    // merged QKV projection (cp.async fp16) + fused RMSNorm/RoPE epilogue
    gemm_qkv_fused<<<dim3(32, TOK / 128), 512, QKV_SMEM>>>(
        h16, wq16, wk16, wv16, cosb, sinb, qw, kw, qh, ql, k16, v16);

    // tensor-core causal flash attention (fp16 two-product)
    attn_f16_kernel<<<dim3(S_ / 128, NH_, B_), 256, ATTN_SMEM>>>(
        qh, ql, k16, v16, ao16);

    // output projection (cp.async fp16 single-product)
    gemm_nt<<<dim3(H_ / 128, TOK / 128), 512, GSMEM>>>(
        ao16, wo16, out, TOK, H_, NH_ * D_);
}

// round 17
// speedup vs baseline: 4.0093x; 1.2491x over previous
#include <cuda_runtime.h>
#include <cuda_fp16.h>
#include <cstdint>

// ---------------------------------------------------------------------------
// Problem constants (B=2, S=2048, H=1024, NH=16, NKV=8, D=128)
// ---------------------------------------------------------------------------
constexpr int B_   = 2;
constexpr int S_   = 2048;
constexpr int H_   = 1024;
constexpr int NH_  = 16;
constexpr int NKV_ = 8;
constexpr int D_   = 128;
constexpr int TOK  = B_ * S_;            // 4096 tokens

// Scratch (device globals; no allocation allowed)
// fp16 pre-converted GEMM operands
__device__ __half g_h16 [TOK * H_];
__device__ __half g_wq16[NH_  * D_ * H_];
__device__ __half g_wk16[NKV_ * D_ * H_];
__device__ __half g_wv16[NKV_ * D_ * H_];
__device__ __half g_wo16[H_ * NH_ * D_];
__device__ __half g_ao16[TOK * NH_ * D_];
// fp16 attention operands (all single fp16)
__device__ __half g_q16[TOK * NH_  * D_];
__device__ __half g_k16[TOK * NKV_ * D_];
__device__ __half g_v16[TOK * NKV_ * D_];

#define DEV_INLINE __device__ __forceinline__

// ---------------------------------------------------------------------------
// helpers
// ---------------------------------------------------------------------------
DEV_INLINE uint32_t cvt_f16x2(float f0, float f1) {
    __half2 h = __float22half2_rn(make_float2(f0, f1));
    return *reinterpret_cast<uint32_t*>(&h);
}
DEV_INLINE void ldsm_x4(uint32_t* r, uint32_t addr) {
    asm volatile("ldmatrix.sync.aligned.m8n8.x4.shared.b16 {%0,%1,%2,%3}, [%4];"
                 : "=r"(r[0]), "=r"(r[1]), "=r"(r[2]), "=r"(r[3]) : "r"(addr));
}
DEV_INLINE void ldsm_x4_trans(uint32_t* r, uint32_t addr) {
    asm volatile("ldmatrix.sync.aligned.m8n8.x4.trans.shared.b16 {%0,%1,%2,%3}, [%4];"
                 : "=r"(r[0]), "=r"(r[1]), "=r"(r[2]), "=r"(r[3]) : "r"(addr));
}
DEV_INLINE void mma_f16(float* c, const uint32_t* a, const uint32_t* b) {
    asm volatile(
        "mma.sync.aligned.m16n8k16.row.col.f32.f16.f16.f32 "
        "{%0,%1,%2,%3}, {%4,%5,%6,%7}, {%8,%9}, {%0,%1,%2,%3};"
        : "+f"(c[0]), "+f"(c[1]), "+f"(c[2]), "+f"(c[3])
        : "r"(a[0]), "r"(a[1]), "r"(a[2]), "r"(a[3]), "r"(b[0]), "r"(b[1]));
}
DEV_INLINE uint32_t smem_u32(const void* p) {
    uint32_t a;
    asm("{ .reg .u64 t; cvta.to.shared.u64 t, %1; cvt.u32.u64 %0, t; }"
        : "=r"(a) : "l"(p));
    return a;
}
DEV_INLINE void cp16(uint32_t dst, const void* src) {
    asm volatile("cp.async.cg.shared.global [%0], [%1], 16;"
                 :: "r"(dst), "l"(src) : "memory");
}
DEV_INLINE void cp_commit() { asm volatile("cp.async.commit_group;" ::: "memory"); }
DEV_INLINE void cp_wait1()  { asm volatile("cp.async.wait_group 1;" ::: "memory"); }
DEV_INLINE void cp_wait0()  { asm volatile("cp.async.wait_group 0;" ::: "memory"); }

// ---------------------------------------------------------------------------
// fp32 -> fp16 converter (grid-stride, float4 -> 2x half2)
// ---------------------------------------------------------------------------
__global__ void cvt16_kernel(const float* __restrict__ x, __half* __restrict__ y, int n4)
{
    int i = blockIdx.x * blockDim.x + threadIdx.x;
    const int stride = gridDim.x * blockDim.x;
    for (; i < n4; i += stride) {
        const float4 v = reinterpret_cast<const float4*>(x)[i];
        reinterpret_cast<uint2*>(y)[i] =
            make_uint2(cvt_f16x2(v.x, v.y), cvt_f16x2(v.z, v.w));
    }
}

// ---------------------------------------------------------------------------
// fp16 single-product tensor-core NT GEMM mainloop, cp.async producer.
// (round-16 proven) 512 threads / 16 warps, CTA 128x128, BK=32.
// ---------------------------------------------------------------------------
constexpr int GMATB = 10240;           // 128 rows * 80B stride per tile
constexpr int GBUFB = 2 * GMATB;       // 20480 per buffer: {A, B}
constexpr int GSMEM = 2 * GBUFB;       // 40960
constexpr int QKV_SMEM = 128 * 132 * 4; // 67584 (epilogue stash) > GSMEM

DEV_INLINE void gemm_mainloop(const __half* __restrict__ A16, const __half* __restrict__ B16,
                              int K, int m0, int n0,
                              uint32_t sb, float Cacc[2][4][4])
{
    const int tid  = threadIdx.x;
    const int lane = tid & 31;
    const int wid  = tid >> 5;          // 0..15
    const int wm   = wid & 3;
    const int wn   = wid >> 2;

    const int r = tid >> 2;
    const int q = tid & 3;
    const uint32_t soff = (uint32_t)r * 80 + (uint32_t)q * 16;
    const __half* Arow = A16 + (size_t)(m0 + r) * K + q * 8;
    const __half* Brow = B16 + (size_t)(n0 + r) * K + q * 8;

#pragma unroll
    for (int mi = 0; mi < 2; mi++)
#pragma unroll
        for (int nf = 0; nf < 4; nf++)
#pragma unroll
            for (int e = 0; e < 4; e++) Cacc[mi][nf][e] = 0.f;

    const uint32_t lrow = (uint32_t)(lane & 15);
    const uint32_t lcol = (uint32_t)(lane >> 4) * 16;
    const int NC = K / 32;

    cp16(sb + soff,         Arow);
    cp16(sb + GMATB + soff, Brow);
    cp_commit();

    for (int c = 0; c < NC; c++) {
        if (c + 1 < NC) {
            const uint32_t nb = sb + ((c + 1) & 1) * GBUFB;
            cp16(nb + soff,         Arow + (c + 1) * 32);
            cp16(nb + GMATB + soff, Brow + (c + 1) * 32);
            cp_commit();
            cp_wait1();
        } else {
            cp_wait0();
        }
        __syncthreads();

        const uint32_t bufs = sb + (c & 1) * GBUFB;
#pragma unroll
        for (int ks = 0; ks < 2; ks++) {
            uint32_t afrag[2][4];
            uint32_t bfr[4][2];
#pragma unroll
            for (int mi = 0; mi < 2; mi++) {
                const uint32_t addr = bufs +
                    ((uint32_t)(wm * 32 + mi * 16) + lrow) * 80 +
                    (uint32_t)ks * 32 + lcol;
                ldsm_x4(afrag[mi], addr);
            }
#pragma unroll
            for (int ng = 0; ng < 2; ng++) {
                uint32_t t4[4];
                const uint32_t addr = bufs + GMATB +
                    ((uint32_t)(wn * 32 + ng * 16) + lrow) * 80 +
                    (uint32_t)ks * 32 + lcol;
                ldsm_x4(t4, addr);
                bfr[ng * 2][0]     = t4[0];
                bfr[ng * 2][1]     = t4[2];
                bfr[ng * 2 + 1][0] = t4[1];
                bfr[ng * 2 + 1][1] = t4[3];
            }
#pragma unroll
            for (int mi = 0; mi < 2; mi++)
#pragma unroll
                for (int nf = 0; nf < 4; nf++)
                    mma_f16(Cacc[mi][nf], afrag[mi], bfr[nf]);
        }
        __syncthreads();
    }
}

// ---------------------------------------------------------------------------
// Merged QKV projection + FUSED RMSNorm/RoPE epilogue. All outputs single fp16.
// ---------------------------------------------------------------------------
__global__ void __launch_bounds__(512, 1)
gemm_qkv_fused(const __half* __restrict__ A16,
               const __half* __restrict__ Wq16, const __half* __restrict__ Wk16,
               const __half* __restrict__ Wv16,
               const float* __restrict__ cosb, const float* __restrict__ sinb,
               const float* __restrict__ qw,   const float* __restrict__ kw,
               __half* __restrict__ q16, __half* __restrict__ k16,
               __half* __restrict__ v16)
{
    extern __shared__ char smem[];
    const uint32_t sb = smem_u32(smem);
    const int bx = blockIdx.x;
    const int m0 = blockIdx.y * 128;

    const __half* Bm; int n0;
    if (bx < 16)      { Bm = Wq16; n0 = bx * 128; }
    else if (bx < 24) { Bm = Wk16; n0 = (bx - 16) * 128; }
    else              { Bm = Wv16; n0 = (bx - 24) * 128; }

    float Cacc[2][4][4];
    gemm_mainloop(A16, Bm, H_, m0, n0, sb, Cacc);

    // ---- stash C tile to smem (post-final-sync; buffers dead) ----
    float* Cs = reinterpret_cast<float*>(smem);      // [128][132]
    {
        const int lane = threadIdx.x & 31;
        const int wid  = threadIdx.x >> 5;
        const int wm   = wid & 3;
        const int wn   = wid >> 2;
#pragma unroll
        for (int mi = 0; mi < 2; mi++) {
            const int row = wm * 32 + mi * 16 + (lane >> 2);
#pragma unroll
            for (int nf = 0; nf < 4; nf++) {
                const int col = wn * 32 + nf * 8 + (lane & 3) * 2;
                *reinterpret_cast<float2*>(&Cs[row * 132 + col]) =
                    make_float2(Cacc[mi][nf][0], Cacc[mi][nf][1]);
                *reinterpret_cast<float2*>(&Cs[(row + 8) * 132 + col]) =
                    make_float2(Cacc[mi][nf][2], Cacc[mi][nf][3]);
            }
        }
    }
    __syncthreads();

    const int lane = threadIdx.x & 31;
    const int wid  = threadIdx.x >> 5;
    const int l    = lane;

    if (bx >= 24) {                       // V: single fp16
        const int hv = bx - 24;
#pragma unroll
        for (int rr = 0; rr < 8; rr++) {
            const int row = wid * 8 + rr;
            const int token = m0 + row;
            const float4 x = *reinterpret_cast<const float4*>(&Cs[row * 132 + l * 4]);
            const uint32_t a0 = cvt_f16x2(x.x, x.y);
            const uint32_t a1 = cvt_f16x2(x.z, x.w);
            const size_t base = (size_t)token * (NKV_ * D_) + hv * D_ + l * 4;
            *reinterpret_cast<uint2*>(v16 + base) = make_uint2(a0, a1);
        }
        return;
    }

    const bool isq = (bx < 16);
    const float* w = isq ? qw : kw;
    __half* o16 = isq ? q16 : k16;
    const int hd  = isq ? bx : (bx - 16);
    const int hdn = isq ? (NH_ * D_) : (NKV_ * D_);
    const float4 wv = *reinterpret_cast<const float4*>(w + l * 4);
    const float sgn = (l < 16) ? -1.f : 1.f;

#pragma unroll
    for (int rr = 0; rr < 8; rr++) {
        const int row = wid * 8 + rr;
        const int token = m0 + row;
        const float4 x = *reinterpret_cast<const float4*>(&Cs[row * 132 + l * 4]);

        float ss = x.x * x.x + x.y * x.y + x.z * x.z + x.w * x.w;
#pragma unroll
        for (int off = 16; off >= 1; off >>= 1)
            ss += __shfl_xor_sync(0xffffffffu, ss, off);
        const float inv = rsqrtf(ss * (1.0f / 128.0f) + 1e-6f);

        const float4 cv = *reinterpret_cast<const float4*>(cosb + (size_t)token * D_ + l * 4);
        const float4 sv = *reinterpret_cast<const float4*>(sinb + (size_t)token * D_ + l * 4);

        const float z0 = x.x * wv.x, z1 = x.y * wv.y, z2 = x.z * wv.z, z3 = x.w * wv.w;
        const float p0 = __shfl_xor_sync(0xffffffffu, z0, 16);
        const float p1 = __shfl_xor_sync(0xffffffffu, z1, 16);
        const float p2 = __shfl_xor_sync(0xffffffffu, z2, 16);
        const float p3 = __shfl_xor_sync(0xffffffffu, z3, 16);

        const float y0 = (z0 * cv.x + sgn * p0 * sv.x) * inv;
        const float y1 = (z1 * cv.y + sgn * p1 * sv.y) * inv;
        const float y2 = (z2 * cv.z + sgn * p2 * sv.z) * inv;
        const float y3 = (z3 * cv.w + sgn * p3 * sv.w) * inv;

        const size_t base = (size_t)token * hdn + hd * D_ + l * 4;
        const uint32_t a0 = cvt_f16x2(y0, y1);
        const uint32_t a1 = cvt_f16x2(y2, y3);
        *reinterpret_cast<uint2*>(o16 + base) = make_uint2(a0, a1);
    }
}

// ---------------------------------------------------------------------------
// Output projection GEMM (fp16 single-product, fp16 operands, fp32 out)
// ---------------------------------------------------------------------------
__global__ void __launch_bounds__(512, 1)
gemm_nt(const __half* __restrict__ A16, const __half* __restrict__ B16,
        float* __restrict__ C, int M, int N, int K)
{
    extern __shared__ char smem[];
    const uint32_t sb = smem_u32(smem);
    const int m0 = blockIdx.y * 128;
    const int n0 = blockIdx.x * 128;

    float Cacc[2][4][4];
    gemm_mainloop(A16, B16, K, m0, n0, sb, Cacc);

    const int lane = threadIdx.x & 31;
    const int wid  = threadIdx.x >> 5;
    const int wm   = wid & 3;
    const int wn   = wid >> 2;
#pragma unroll
    for (int mi = 0; mi < 2; mi++) {
        const int row = m0 + wm * 32 + mi * 16 + (lane >> 2);
#pragma unroll
        for (int nf = 0; nf < 4; nf++) {
            const int col = n0 + wn * 32 + nf * 8 + (lane & 3) * 2;
            *reinterpret_cast<float2*>(C + (size_t)row * N + col) =
                make_float2(Cacc[mi][nf][0], Cacc[mi][nf][1]);
            *reinterpret_cast<float2*>(C + (size_t)(row + 8) * N + col) =
                make_float2(Cacc[mi][nf][2], Cacc[mi][nf][3]);
        }
    }
}

// ---------------------------------------------------------------------------
// Tensor-core flash attention (fp16 SINGLE-product, causal, GQA n_rep=2).
// BQ=128, BKV=64, D=128. 256 threads = 8 warps, warp w -> q rows w*16..+15.
// SMEM: Q16 (128x272B) + double-buffered {K16,V16} (64x272B each)
// ---------------------------------------------------------------------------
constexpr int AQ_BYTES  = 128 * 272;                 // 34816
constexpr int AKV_BYTES = 64 * 272;                  // 17408
constexpr int ABUF0     = AQ_BYTES;                  // 34816
constexpr int ABUFSZ    = 2 * AKV_BYTES;             // 34816
constexpr int ATTN_SMEM = ABUF0 + 2 * ABUFSZ;        // 104448

__global__ void __launch_bounds__(256, 1)
attn_f16_kernel(const __half* __restrict__ q16,
                const __half* __restrict__ k16, const __half* __restrict__ v16,
                __half* __restrict__ ao16)
{
    extern __shared__ char smem[];
    const uint32_t sb = smem_u32(smem);

    const int tid  = threadIdx.x;
    const int lane = tid & 31;
    const int w    = tid >> 5;
    const int qi   = gridDim.x - 1 - blockIdx.x;
    const int h    = blockIdx.y;
    const int b    = blockIdx.z;
    const int kvh  = h >> 1;

#pragma unroll
    for (int i = 0; i < 8; i++) {
        const int idx = tid + i * 256;
        const int row = idx >> 4, ch = idx & 15;
        const size_t g = ((size_t)(b * S_) + qi * 128 + row) * (NH_ * D_) + h * D_ + ch * 8;
        cp16(sb + row * 272 + ch * 16, q16 + g);
    }
    {
        const uint32_t buf = sb + ABUF0;
#pragma unroll
        for (int i = 0; i < 4; i++) {
            const int idx = tid + i * 256;
            const int row = idx >> 4, ch = idx & 15;
            const size_t g = ((size_t)(b * S_) + row) * (NKV_ * D_) + kvh * D_ + ch * 8;
            const uint32_t so = buf + row * 272 + ch * 16;
            cp16(so,             k16 + g);
            cp16(so + AKV_BYTES, v16 + g);
        }
    }
    cp_commit();

    float oacc[16][4];
#pragma unroll
    for (int i = 0; i < 16; i++)
#pragma unroll
        for (int e = 0; e < 4; e++) oacc[i][e] = 0.f;
    float m_i[2] = {-1e30f, -1e30f};
    float l_i[2] = {0.f, 0.f};

    const uint32_t lrow16 = (uint32_t)(lane & 15);
    const uint32_t lhalf  = (uint32_t)(lane >> 4) * 16;
    const int jmax = 2 * qi + 1;

    for (int jb = 0; jb <= jmax; jb++) {
        if (jb < jmax) {
            const uint32_t buf = sb + ABUF0 + ((jb + 1) & 1) * ABUFSZ;
#pragma unroll
            for (int i = 0; i < 4; i++) {
                const int idx = tid + i * 256;
                const int row = idx >> 4, ch = idx & 15;
                const size_t g = ((size_t)(b * S_) + (jb + 1) * 64 + row) * (NKV_ * D_) +
                                 kvh * D_ + ch * 8;
                const uint32_t so = buf + row * 272 + ch * 16;
                cp16(so,             k16 + g);
                cp16(so + AKV_BYTES, v16 + g);
            }
            cp_commit();
            cp_wait1();
        } else {
            cp_wait0();
        }
        __syncthreads();

        const uint32_t kb = sb + ABUF0 + (jb & 1) * ABUFSZ;
        const bool skip = (jb * 64) > (qi * 128 + w * 16 + 15);

        if (!skip) {
            // ---- S = Q16 K16 ----
            float sacc[8][4];
#pragma unroll
            for (int i = 0; i < 8; i++)
#pragma unroll
                for (int e = 0; e < 4; e++) sacc[i][e] = 0.f;

            const uint32_t qbase = sb + ((uint32_t)(w * 16) + lrow16) * 272 + lhalf;
#pragma unroll
            for (int ks = 0; ks < 8; ks++) {
                uint32_t aq[4];
                ldsm_x4(aq, qbase + ks * 32);
#pragma unroll
                for (int ng = 0; ng < 4; ng++) {
                    uint32_t t[4];
                    const uint32_t ka = kb + ((uint32_t)(ng * 16) + lrow16) * 272 + ks * 32 + lhalf;
                    ldsm_x4(t, ka);
                    uint32_t bh0[2] = {t[0], t[2]}, bh1[2] = {t[1], t[3]};
                    mma_f16(sacc[ng * 2],     aq, bh0);
                    mma_f16(sacc[ng * 2 + 1], aq, bh1);
                }
            }

            const float sc = 0.088388347648318447f;
            const bool domask = (jb * 64 + 63) > (qi * 128 + w * 16);
#pragma unroll
            for (int nf = 0; nf < 8; nf++)
#pragma unroll
                for (int e = 0; e < 4; e++) {
                    float s = sacc[nf][e] * sc;
                    if (domask) {
                        const int col = jb * 64 + nf * 8 + ((lane & 3) << 1) + (e & 1);
                        const int row = qi * 128 + w * 16 + (lane >> 2) + ((e >> 1) << 3);
                        if (col > row) s = -1e30f;
                    }
                    sacc[nf][e] = s;
                }

#pragma unroll
            for (int r2 = 0; r2 < 2; r2++) {
                float mx = -1e30f;
#pragma unroll
                for (int nf = 0; nf < 8; nf++)
                    mx = fmaxf(mx, fmaxf(sacc[nf][2 * r2], sacc[nf][2 * r2 + 1]));
                mx = fmaxf(mx, __shfl_xor_sync(0xffffffffu, mx, 1));
                mx = fmaxf(mx, __shfl_xor_sync(0xffffffffu, mx, 2));
                const float mn = fmaxf(m_i[r2], mx);
                const float alpha = __expf(m_i[r2] - mn);
                m_i[r2] = mn;
                float rs = 0.f;
#pragma unroll
                for (int nf = 0; nf < 8; nf++) {
                    float p0 = __expf(sacc[nf][2 * r2]     - mn);
                    float p1 = __expf(sacc[nf][2 * r2 + 1] - mn);
                    sacc[nf][2 * r2]     = p0;
                    sacc[nf][2 * r2 + 1] = p1;
                    rs += p0 + p1;
                }
                rs += __shfl_xor_sync(0xffffffffu, rs, 1);
                rs += __shfl_xor_sync(0xffffffffu, rs, 2);
                l_i[r2] = l_i[r2] * alpha + rs;
#pragma unroll
                for (int ndf = 0; ndf < 16; ndf++) {
                    oacc[ndf][2 * r2]     *= alpha;
                    oacc[ndf][2 * r2 + 1] *= alpha;
                }
            }

            // ---- O += P16 V16 ----
#pragma unroll
            for (int kk = 0; kk < 4; kk++) {
                uint32_t phi[4];
                phi[0] = cvt_f16x2(sacc[2 * kk][0],     sacc[2 * kk][1]);
                phi[1] = cvt_f16x2(sacc[2 * kk][2],     sacc[2 * kk][3]);
                phi[2] = cvt_f16x2(sacc[2 * kk + 1][0], sacc[2 * kk + 1][1]);
                phi[3] = cvt_f16x2(sacc[2 * kk + 1][2], sacc[2 * kk + 1][3]);
#pragma unroll
                for (int ndg = 0; ndg < 8; ndg++) {
                    uint32_t t[4];
                    const uint32_t va = kb + AKV_BYTES +
                        ((uint32_t)(kk * 16) + lrow16) * 272 + ndg * 32 + lhalf;
                    ldsm_x4_trans(t, va);
                    uint32_t bh0[2] = {t[0], t[1]}, bh1[2] = {t[2], t[3]};
                    mma_f16(oacc[ndg * 2],     phi, bh0);
                    mma_f16(oacc[ndg * 2 + 1], phi, bh1);
                }
            }
        }
        __syncthreads();
    }

    // epilogue: normalize, emit fp16 ao
    const float i0 = 1.0f / l_i[0];
    const float i1 = 1.0f / l_i[1];
    const int row0 = qi * 128 + w * 16 + (lane >> 2);
    const size_t base0 = ((size_t)(b * S_) + row0) * (NH_ * D_) + h * D_ + (lane & 3) * 2;
    const size_t base1 = base0 + (size_t)8 * (NH_ * D_);
#pragma unroll
    for (int ndf = 0; ndf < 16; ndf++) {
        *reinterpret_cast<uint32_t*>(ao16 + base0 + ndf * 8) =
            cvt_f16x2(oacc[ndf][0] * i0, oacc[ndf][1] * i0);
        *reinterpret_cast<uint32_t*>(ao16 + base1 + ndf * 8) =
            cvt_f16x2(oacc[ndf][2] * i1, oacc[ndf][3] * i1);
    }
}

// ---------------------------------------------------------------------------
// Launch
// ---------------------------------------------------------------------------
extern "C" void kernel_launch(void* const* d_in, const int* in_sizes, int n_in,
                              void* d_out, int out_size)
{
    const float* hidden = (const float*)d_in[0];
    const float* cosb   = (const float*)d_in[1];
    const float* sinb   = (const float*)d_in[2];
    const float* Wq     = (const float*)d_in[3];
    const float* Wk     = (const float*)d_in[4];
    const float* Wv     = (const float*)d_in[5];
    const float* Wo     = (const float*)d_in[6];
    const float* qw     = (const float*)d_in[7];
    const float* kw     = (const float*)d_in[8];
    float* out = (float*)d_out;

    __half *h16, *wq16, *wk16, *wv16, *wo16, *ao16;
    cudaGetSymbolAddress((void**)&h16,  g_h16);
    cudaGetSymbolAddress((void**)&wq16, g_wq16);
    cudaGetSymbolAddress((void**)&wk16, g_wk16);
    cudaGetSymbolAddress((void**)&wv16, g_wv16);
    cudaGetSymbolAddress((void**)&wo16, g_wo16);
    cudaGetSymbolAddress((void**)&ao16, g_ao16);
    __half *q16, *k16, *v16;
    cudaGetSymbolAddress((void**)&q16, g_q16);
    cudaGetSymbolAddress((void**)&k16, g_k16);
    cudaGetSymbolAddress((void**)&v16, g_v16);

    cudaFuncSetAttribute((const void*)gemm_qkv_fused,
                         cudaFuncAttributeMaxDynamicSharedMemorySize, QKV_SMEM);
    cudaFuncSetAttribute((const void*)gemm_nt,
                         cudaFuncAttributeMaxDynamicSharedMemorySize, GSMEM);
    cudaFuncSetAttribute((const void*)attn_f16_kernel,
                         cudaFuncAttributeMaxDynamicSharedMemorySize, ATTN_SMEM);

    // pre-convert operands to fp16
    cvt16_kernel<<<1024, 256>>>(hidden, h16,  TOK * H_ / 4);
    cvt16_kernel<<<1024, 256>>>(Wq,     wq16, NH_ * D_ * H_ / 4);
    cvt16_kernel<<<512,  256>>>(Wk,     wk16, NKV_ * D_ * H_ / 4);
    cvt16_kernel<<<512,  256>>>(Wv,     wv16, NKV_ * D_ * H_ / 4);
    cvt16_kernel<<<1024, 256>>>(Wo,     wo16, H_ * NH_ * D_ / 4);

    // merged QKV projection (cp.async fp16) + fused RMSNorm/RoPE epilogue
    gemm_qkv_fused<<<dim3(32, TOK / 128), 512, QKV_SMEM>>>(
        h16, wq16, wk16, wv16, cosb, sinb, qw, kw, q16, k16, v16);

    // tensor-core causal flash attention (fp16 single-product)
    attn_f16_kernel<<<dim3(S_ / 128, NH_, B_), 256, ATTN_SMEM>>>(
        q16, k16, v16, ao16);

    // output projection (cp.async fp16 single-product)
    gemm_nt<<<dim3(H_ / 128, TOK / 128), 512, GSMEM>>>(
        ao16, wo16, out, TOK, H_, NH_ * D_);
}